// round 5
// baseline (speedup 1.0000x reference)
#include <cuda_runtime.h>
#include <math.h>
#include <stddef.h>

#define NEGF (-1.0e9f)
#define CLIPV 4.135166556742356f

__device__ __forceinline__ unsigned skey(float s){
    unsigned u = __float_as_uint(s);
    return (u & 0x80000000u) ? ~u : (u | 0x80000000u);
}

struct __align__(256) Scratch {
    float h[35782656];
    float scores[2][209664];
    float deltas[2][838656];
    unsigned hist[2][65536];
    int tiebuf[2][4096];
    int tiecnt[2];
    int selcnt[2];
    unsigned long long sbuf[2][16384];
    float pb[2][4000];
    float ps[2][1000];
    float catb[2][19280];   // padded (4819*4=19276 used) -> keeps 16B alignment
    float cats[2][4820];    // padded (4819 used)
    float rois[2][4000];
    float roifeat[25088000];
    float h1[2048000];
    float h2[2048000];
    float clsl[182000];
    float boxl[728000];
    float dns[2][9000];
    float dnb[2][36000];
};
__device__ Scratch g;

__constant__ int cH[5]={208,104,52,26,13};
__constant__ int cW[5]={336,168,84,42,21};
__constant__ float cStrideF[5]={4.f,8.f,16.f,32.f,64.f};

// ---------------- SGEMM 128x128x8, 256 thr, 8x8 reg tiles ----------------
// MODE 0: dense A[M,K]. MODE 1: implicit 3x3 SAME conv, A=NHWC C=256, K=2304.
template<int MODE,bool VECB,bool RELU>
__global__ void gemm128(const float* __restrict__ A,const float* __restrict__ Bw,
                        const float* __restrict__ bias,float* __restrict__ C,
                        int M,int N,int K,int H,int W){
    __shared__ float As[8][128];
    __shared__ float Bs[8][132];
    int tid=threadIdx.x;
    int bm=blockIdx.y*128, bn=blockIdx.x*128;
    int tx=tid&15, ty=tid>>4;
    float acc[8][8];
#pragma unroll
    for(int i=0;i<8;i++)
#pragma unroll
        for(int j=0;j<8;j++) acc[i][j]=0.f;
    int ar=tid>>1, aco=(tid&1)*4;
    int brow=tid>>5, bcol=(tid&31)*4;
    int m=bm+ar;
    int ab=0,ay=0,ax=0;
    if(MODE==1){
        int HW=H*W; int mm=(m<M)?m:0;
        ab=mm/HW; int rem=mm-ab*HW; ay=rem/W; ax=rem-ay*W;
    }
    for(int k0=0;k0<K;k0+=8){
        float4 av=make_float4(0.f,0.f,0.f,0.f);
        if(m<M){
            if(MODE==0){
                av=*(const float4*)(A+(size_t)m*K+k0+aco);
            }else{
                int kz=k0+aco; int r=kz>>8, ci=kz&255;
                int ky=r/3, kx=r-ky*3;
                int yy=ay+ky-1, xx=ax+kx-1;
                if(yy>=0&&yy<H&&xx>=0&&xx<W)
                    av=*(const float4*)(A+(((size_t)ab*H+yy)*W+xx)*256+ci);
            }
        }
        As[aco+0][ar]=av.x; As[aco+1][ar]=av.y; As[aco+2][ar]=av.z; As[aco+3][ar]=av.w;
        {
            int kk=k0+brow; int n=bn+bcol;
            float4 bv=make_float4(0.f,0.f,0.f,0.f);
            if(VECB&&(n+3)<N){
                bv=*(const float4*)(Bw+(size_t)kk*N+n);
            }else{
                if(n+0<N) bv.x=Bw[(size_t)kk*N+n+0];
                if(n+1<N) bv.y=Bw[(size_t)kk*N+n+1];
                if(n+2<N) bv.z=Bw[(size_t)kk*N+n+2];
                if(n+3<N) bv.w=Bw[(size_t)kk*N+n+3];
            }
            *(float4*)&Bs[brow][bcol]=bv;
        }
        __syncthreads();
#pragma unroll
        for(int kk=0;kk<8;kk++){
            float af[8],bf[8];
            *(float4*)&af[0]=*(const float4*)&As[kk][ty*8];
            *(float4*)&af[4]=*(const float4*)&As[kk][ty*8+4];
            *(float4*)&bf[0]=*(const float4*)&Bs[kk][tx*8];
            *(float4*)&bf[4]=*(const float4*)&Bs[kk][tx*8+4];
#pragma unroll
            for(int i=0;i<8;i++)
#pragma unroll
                for(int j=0;j<8;j++) acc[i][j]+=af[i]*bf[j];
        }
        __syncthreads();
    }
#pragma unroll
    for(int i=0;i<8;i++){
        int mm=bm+ty*8+i;
        if(mm>=M) continue;
#pragma unroll
        for(int j=0;j<8;j++){
            int nn=bn+tx*8+j;
            if(nn>=N) continue;
            float v=acc[i][j]+bias[nn];
            if(RELU) v=fmaxf(v,0.f);
            C[(size_t)mm*N+nn]=v;
        }
    }
}

// ---------------- RPN head: 15 dots over 256 channels per pixel ----------
__global__ void rpn_head_kernel(const float* __restrict__ h,
    const float* __restrict__ sw,const float* __restrict__ sb,
    const float* __restrict__ bw,const float* __restrict__ bb,
    int HW,int Btot){
    __shared__ float wsm[256][16];
    __shared__ float bsm[16];
    int tid=threadIdx.x;
    for(int i=tid;i<256*16;i+=blockDim.x){
        int c=i>>4, j=i&15;
        float v=0.f;
        if(j<3) v=sw[c*3+j];
        else if(j<15) v=bw[c*12+(j-3)];
        wsm[c][j]=v;
    }
    if(tid<16) bsm[tid]=(tid<3)?sb[tid]:((tid<15)?bb[tid-3]:0.f);
    __syncthreads();
    int m=blockIdx.x*blockDim.x+tid;
    if(m>=Btot) return;
    int b=m/HW, pix=m-b*HW;
    const float* hr=h+(size_t)m*256;
    float acc[15];
#pragma unroll
    for(int j=0;j<15;j++) acc[j]=0.f;
    for(int c=0;c<256;c+=4){
        float4 v=*(const float4*)(hr+c);
#pragma unroll
        for(int j=0;j<15;j++)
            acc[j]+=v.x*wsm[c][j]+v.y*wsm[c+1][j]+v.z*wsm[c+2][j]+v.w*wsm[c+3][j];
    }
    for(int a=0;a<3;a++){
        float lg=acc[a]+bsm[a];
        g.scores[b][pix*3+a]=1.f/(1.f+expf(-lg));
        for(int d=0;d<4;d++)
            g.deltas[b][(size_t)(pix*3+a)*4+d]=acc[3+a*4+d]+bsm[3+a*4+d];
    }
}

// ------------- exact stable top-k: 16+16-bit radix select, 1 blk/batch ----
__global__ void select_topk(int Nl,int k){
    int b=blockIdx.x;
    const float* s=g.scores[b];
    unsigned* hist=g.hist[b];
    int tid=threadIdx.x;
    __shared__ unsigned csum[1024];
    __shared__ int s_t,s_above,s_u,s_above2;
    if(tid==0){ g.selcnt[b]=0; g.tiecnt[b]=0; }
    for(int i=tid;i<65536;i+=1024) __stcg(&hist[i],0u);
    __syncthreads();
    for(int i=tid;i<Nl;i+=1024) atomicAdd(&hist[skey(s[i])>>16],1u);
    __syncthreads();
    {
        unsigned own=0; int base=65535-tid*64;
        for(int q=0;q<64;q++) own+=__ldcg(&hist[base-q]);
        csum[tid]=own; __syncthreads();
        for(int off=1;off<1024;off<<=1){
            unsigned v=csum[tid]; unsigned add=(tid>=off)?csum[tid-off]:0u; __syncthreads();
            csum[tid]=v+add; __syncthreads();
        }
        unsigned excl=csum[tid]-own;
        if(excl<(unsigned)k&&csum[tid]>=(unsigned)k){
            unsigned cum=excl;
            for(int q=0;q<64;q++){
                unsigned c=__ldcg(&hist[base-q]);
                if(cum+c>=(unsigned)k){ s_t=base-q; s_above=(int)cum; break; }
                cum+=c;
            }
        }
        __syncthreads();
    }
    int t=s_t, above=s_above;
    for(int i=tid;i<65536;i+=1024) __stcg(&hist[i],0u);
    __syncthreads();
    for(int i=tid;i<Nl;i+=1024){
        unsigned key=skey(s[i]);
        if((int)(key>>16)==t) atomicAdd(&hist[key&0xFFFFu],1u);
    }
    __syncthreads();
    int need=k-above;
    {
        unsigned own=0; int base=65535-tid*64;
        for(int q=0;q<64;q++) own+=__ldcg(&hist[base-q]);
        csum[tid]=own; __syncthreads();
        for(int off=1;off<1024;off<<=1){
            unsigned v=csum[tid]; unsigned add=(tid>=off)?csum[tid-off]:0u; __syncthreads();
            csum[tid]=v+add; __syncthreads();
        }
        unsigned excl=csum[tid]-own;
        if(excl<(unsigned)need&&csum[tid]>=(unsigned)need){
            unsigned cum=excl;
            for(int q=0;q<64;q++){
                unsigned c=__ldcg(&hist[base-q]);
                if(cum+c>=(unsigned)need){ s_u=base-q; s_above2=(int)cum; break; }
                cum+=c;
            }
        }
        __syncthreads();
    }
    int u=s_u, above2=s_above2;
    unsigned T=(((unsigned)t)<<16)|(unsigned)u;
    for(int i=tid;i<Nl;i+=1024){
        unsigned key=skey(s[i]);
        if(key>T){
            int pos=atomicAdd(&g.selcnt[b],1);
            g.sbuf[b][pos]=(((unsigned long long)key)<<32)|(unsigned)(~(unsigned)i);
        }else if(key==T){
            int p=atomicAdd(&g.tiecnt[b],1);
            if(p<4096) g.tiebuf[b][p]=i;
        }
    }
    __syncthreads();
    int ct=g.tiecnt[b]; if(ct>4096) ct=4096;
    int mtake=need-above2;
    int pos0=above+above2;
    for(int ti=tid;ti<ct;ti+=1024){
        int myi=g.tiebuf[b][ti];
        int rank=0;
        for(int q=0;q<ct;q++) rank+=(g.tiebuf[b][q]<myi);
        if(rank<mtake)
            g.sbuf[b][pos0+rank]=(((unsigned long long)T)<<32)|(unsigned)(~(unsigned)myi);
    }
    __syncthreads();
    if(tid>=k&&tid<1024) g.sbuf[b][tid]=0ull;
}

// Descending bitonic sort of g.sbuf[blockIdx.x][0..n), n pow2.
__global__ void bitonic_desc(int n){
    unsigned long long* a=g.sbuf[blockIdx.x];
    for(int k=2;k<=n;k<<=1){
        for(int j=k>>1;j>0;j>>=1){
            for(int i=threadIdx.x;i<n;i+=blockDim.x){
                int l=i^j;
                if(l>i){
                    unsigned long long x=a[i],y=a[l];
                    bool sw=((i&k)==0)?(x<y):(x>y);
                    if(sw){ a[i]=y; a[l]=x; }
                }
            }
            __syncthreads();
        }
    }
}

// Decode sorted top-k RPN proposals (anchors in fp64 = numpy-exact).
__global__ void rpn_decode(const float* __restrict__ iminfo,int lvl,int W,int k){
    int b=blockIdx.x; int r=threadIdx.x;
    if(r>=k) return;
    unsigned long long key=g.sbuf[b][r];
    int i=(int)(~(unsigned)key);
    int a=i%3; int pix=i/3; int x=pix%W; int y=pix/W;
    double stride=(double)(1<<lvl);
    double size=8.0*stride;
    double rr=(a==0)?1.0:((a==1)?0.5:2.0);
    double sr=sqrt(rr);
    double hh=size/sr, ww=size*sr;
    double ycd=((double)y+0.5)*stride, xcd=((double)x+0.5)*stride;
    float ya1=(float)(ycd-hh*0.5), xa1=(float)(xcd-ww*0.5);
    float ya2=(float)(ycd+hh*0.5), xa2=(float)(xcd+ww*0.5);
    const float* d=&g.deltas[b][(size_t)i*4];
    float ha=ya2-ya1, wa=xa2-xa1;
    float yc=ya1+0.5f*ha, xc=xa1+0.5f*wa;
    float dy=d[0], dx=d[1];
    float dh=fminf(d[2],CLIPV), dw=fminf(d[3],CLIPV);
    float pcy=dy*ha+yc, pcx=dx*wa+xc;
    float ph=expf(dh)*ha, pw=expf(dw)*wa;
    float hI=iminfo[b*5+0], wI=iminfo[b*5+1];
    g.pb[b][r*4+0]=fminf(fmaxf(pcy-0.5f*ph,0.f),hI);
    g.pb[b][r*4+1]=fminf(fmaxf(pcx-0.5f*pw,0.f),wI);
    g.pb[b][r*4+2]=fminf(fmaxf(pcy+0.5f*ph,0.f),hI);
    g.pb[b][r*4+3]=fminf(fmaxf(pcx+0.5f*pw,0.f),wI);
    g.ps[b][r]=g.scores[b][i];
}

// -------- sequential NMS core (argmax-first-index + explicit s[j]=NEG) ----
__device__ void nms_run(float* y1,float* x1,float* y2,float* x2,float* s,
                        int n,int iters,float th,float* ob,float* os){
    __shared__ float rv[256];
    __shared__ int ri[256];
    __shared__ float cb[4];
    int tid=threadIdx.x;
    for(int it=0;it<iters;it++){
        float bv=-3.0e38f; int bi=1<<30;
        for(int i=tid;i<n;i+=256){
            float v=s[i];
            if(v>bv||(v==bv&&i<bi)){ bv=v; bi=i; }
        }
        rv[tid]=bv; ri[tid]=bi; __syncthreads();
        for(int o=128;o>0;o>>=1){
            if(tid<o){
                float v=rv[tid+o]; int j=ri[tid+o];
                if(v>rv[tid]||(v==rv[tid]&&j<ri[tid])){ rv[tid]=v; ri[tid]=j; }
            }
            __syncthreads();
        }
        int j=ri[0]; float js=rv[0];
        if(tid==0){ cb[0]=y1[j]; cb[1]=x1[j]; cb[2]=y2[j]; cb[3]=x2[j]; }
        __syncthreads();
        float a1=cb[0],a2=cb[1],a3=cb[2],a4=cb[3];
        float aA=(a3-a1)*(a4-a2);
        for(int i=tid;i<n;i+=256){
            float yy1=fmaxf(a1,y1[i]), xx1=fmaxf(a2,x1[i]);
            float yy2=fminf(a3,y2[i]), xx2=fminf(a4,x2[i]);
            float inter=fmaxf(yy2-yy1,0.f)*fmaxf(xx2-xx1,0.f);
            float bA=(y2[i]-y1[i])*(x2[i]-x1[i]);
            float iou=inter/(aA+bA-inter+1e-8f);
            if(iou>=th) s[i]=NEGF;
        }
        __syncthreads();
        if(tid==0){
            s[j]=NEGF;
            bool valid=js>NEGF*0.5f;
            os[it]=valid?js:NEGF;
            ob[it*4+0]=valid?a1:0.f;
            ob[it*4+1]=valid?a2:0.f;
            ob[it*4+2]=valid?a3:0.f;
            ob[it*4+3]=valid?a4:0.f;
        }
        __syncthreads();
    }
}

__global__ void nms_level(int k,int off){
    __shared__ float y1[1000],x1[1000],y2[1000],x2[1000],s[1000];
    int b=blockIdx.x; int tid=threadIdx.x;
    for(int i=tid;i<k;i+=256){
        y1[i]=g.pb[b][i*4+0]; x1[i]=g.pb[b][i*4+1];
        y2[i]=g.pb[b][i*4+2]; x2[i]=g.pb[b][i*4+3];
        s[i]=g.ps[b][i];
    }
    __syncthreads();
    nms_run(y1,x1,y2,x2,s,k,k,0.7f,&g.catb[b][off*4],&g.cats[b][off]);
}

__global__ void build_cat_keys(){
    int b=blockIdx.x;
    for(int i=threadIdx.x;i<8192;i+=blockDim.x){
        unsigned long long key=0ull;
        if(i<4819) key=(((unsigned long long)skey(g.cats[b][i]))<<32)|(unsigned)(~(unsigned)i);
        g.sbuf[b][i]=key;
    }
}

__global__ void gather_rois(){
    int b=blockIdx.x;
    for(int r=threadIdx.x;r<1000;r+=blockDim.x){
        int i=(int)(~(unsigned)g.sbuf[b][r]);
        for(int d=0;d<4;d++) g.rois[b][r*4+d]=g.catb[b][i*4+d];
    }
}

// ---------------- multilevel ROI align, 1 block per roi, thread=channel ---
__global__ void roialign(const float* f0,const float* f1,const float* f2,
                         const float* f3,const float* f4){
    int br=blockIdx.x; int b=br/1000;
    int c=threadIdx.x;
    const float* ro=&g.rois[b][(br%1000)*4];
    float y1=ro[0],x1=ro[1],y2=ro[2],x2=ro[3];
    float area=fmaxf((y2-y1)*(x2-x1),1e-6f);
    float lv=floorf(4.f+log2f(sqrtf(area)/224.f));
    lv=fminf(fmaxf(lv,2.f),6.f);
    int li=(int)lv-2;
    const float* fp=(li==0)?f0:(li==1)?f1:(li==2)?f2:(li==3)?f3:f4;
    int H=cH[li],W=cW[li];
    float Hf=(float)H,Wf=(float)W;
    float stride=cStrideF[li];
    const float* base=fp+(size_t)b*H*W*256;
    float* outp=&g.roifeat[(size_t)br*12544];
    for(int p=0;p<49;p++){
        int py=p/7,px=p%7;
        float uy=((float)py+0.5f)/7.f, ux=((float)px+0.5f)/7.f;
        float ys=(y1+(y2-y1)*uy)/stride-0.5f;
        float xs=(x1+(x2-x1)*ux)/stride-0.5f;
        ys=fminf(fmaxf(ys,0.f),Hf-1.f);
        xs=fminf(fmaxf(xs,0.f),Wf-1.f);
        float y0=floorf(ys),x0=floorf(xs);
        float wy=ys-y0,wx=xs-x0;
        int y0i=(int)y0,x0i=(int)x0;
        int y1i=min(y0i+1,H-1),x1i=min(x0i+1,W-1);
        const float* p00=base+((size_t)y0i*W+x0i)*256;
        const float* p01=base+((size_t)y0i*W+x1i)*256;
        const float* p10=base+((size_t)y1i*W+x0i)*256;
        const float* p11=base+((size_t)y1i*W+x1i)*256;
        float w00=(1.f-wy)*(1.f-wx), w01=(1.f-wy)*wx;
        float w10=wy*(1.f-wx), w11=wy*wx;
        outp[p*256+c]=p00[c]*w00+p01[c]*w01+p10[c]*w10+p11[c]*w11;
    }
}

__global__ void softmax91(){
    int i=blockIdx.x*blockDim.x+threadIdx.x;
    if(i>=2000) return;
    float* p=&g.clsl[(size_t)i*91];
    float mx=p[0];
    for(int c=1;c<91;c++) mx=fmaxf(mx,p[c]);
    float sm=0.f;
    float e[91];
    for(int c=0;c<91;c++){ e[c]=expf(p[c]-mx); sm+=e[c]; }
    for(int c=0;c<91;c++) p[c]=e[c]/sm;
}

__global__ void nms_det(const float* __restrict__ iminfo){
    __shared__ float y1[1000],x1[1000],y2[1000],x2[1000],s[1000];
    int blk=blockIdx.x; int b=blk/90; int c=blk%90+1;
    int tid=threadIdx.x;
    float hI=iminfo[b*5+0], wI=iminfo[b*5+1];
    for(int i=tid;i<1000;i+=256){
        const float* ro=&g.rois[b][i*4];
        float ya1=ro[0],xa1=ro[1],ya2=ro[2],xa2=ro[3];
        float ha=ya2-ya1, wa=xa2-xa1;
        float yc=ya1+0.5f*ha, xc=xa1+0.5f*wa;
        const float* d=&g.boxl[((size_t)(b*1000+i)*91+c)*4];
        float dy=d[0]/10.f, dx=d[1]/10.f;
        float dh=fminf(d[2]/5.f,CLIPV), dw=fminf(d[3]/5.f,CLIPV);
        float pcy=dy*ha+yc, pcx=dx*wa+xc;
        float ph=expf(dh)*ha, pw=expf(dw)*wa;
        y1[i]=fminf(fmaxf(pcy-0.5f*ph,0.f),hI);
        x1[i]=fminf(fmaxf(pcx-0.5f*pw,0.f),wI);
        y2[i]=fminf(fmaxf(pcy+0.5f*ph,0.f),hI);
        x2[i]=fminf(fmaxf(pcx+0.5f*pw,0.f),wI);
        float p=g.clsl[(size_t)(b*1000+i)*91+c];
        s[i]=(p>=0.05f)?p:NEGF;
    }
    __syncthreads();
    nms_run(y1,x1,y2,x2,s,1000,100,0.5f,&g.dnb[b][(c-1)*400],&g.dns[b][(c-1)*100]);
}

__global__ void build_det_keys(){
    int b=blockIdx.x;
    for(int i=threadIdx.x;i<16384;i+=blockDim.x){
        unsigned long long key=0ull;
        if(i<9000) key=(((unsigned long long)skey(g.dns[b][i]))<<32)|(unsigned)(~(unsigned)i);
        g.sbuf[b][i]=key;
    }
}

__global__ void write_out(float* out,int out_size){
    int tid=threadIdx.x;
    for(int i=tid;i<out_size;i+=256) out[i]=0.f;
    __syncthreads();
    __shared__ int cnt;
    for(int b=0;b<2;b++){
        if(tid==0) cnt=0;
        __syncthreads();
        if(tid<100){
            int r=tid;
            int idx=(int)(~(unsigned)g.sbuf[b][r]);
            float sc=g.dns[b][idx];
            bool valid=sc>0.f;
            if(valid) atomicAdd(&cnt,1);
            float cls=valid?(float)(idx/100+1):0.f;
            int ob=2+b*400+r*4;
            for(int d=0;d<4;d++){
                int o=ob+d;
                if(o<out_size) out[o]=valid?g.dnb[b][idx*4+d]:0.f;
            }
            int oc=2+800+b*100+r;
            if(oc<out_size) out[oc]=cls;
            int os=2+1000+b*100+r;
            if(os<out_size) out[os]=valid?sc:0.f;
        }
        __syncthreads();
        if(tid==0&&b<out_size) out[b]=(float)cnt;
        __syncthreads();
    }
}

extern "C" void kernel_launch(void* const* d_in,const int* in_sizes,int n_in,
                              void* d_out,int out_size){
    const float* feats[5];
    for(int i=0;i<5;i++) feats[i]=(const float*)d_in[i];
    const float* iminfo=(const float*)d_in[5];
    const float* cw =(const float*)d_in[6];
    const float* cbv=(const float*)d_in[7];
    const float* sw =(const float*)d_in[8];
    const float* sb =(const float*)d_in[9];
    const float* bw =(const float*)d_in[10];
    const float* bbv=(const float*)d_in[11];
    const float* fc1w=(const float*)d_in[12];
    const float* fc1b=(const float*)d_in[13];
    const float* fc2w=(const float*)d_in[14];
    const float* fc2b=(const float*)d_in[15];
    const float* clsw=(const float*)d_in[16];
    const float* clsb=(const float*)d_in[17];
    const float* boxw=(const float*)d_in[18];
    const float* boxb=(const float*)d_in[19];

    Scratch* gp=nullptr;
    cudaGetSymbolAddress((void**)&gp,g);

    int Hs[5]={208,104,52,26,13}, Ws[5]={336,168,84,42,21};
    int offs[5]={0,1000,2000,3000,4000};

    for(int i=0;i<5;i++){
        int H=Hs[i],W=Ws[i],M=2*H*W;
        dim3 gr(2,(M+127)/128);
        gemm128<1,true,true><<<gr,256>>>(feats[i],cw,cbv,gp->h,M,256,2304,H,W);
        rpn_head_kernel<<<(M+255)/256,256>>>(gp->h,sw,sb,bw,bbv,H*W,M);
        int Nl=H*W*3;
        int k=Nl<1000?Nl:1000;
        select_topk<<<2,1024>>>(Nl,k);
        bitonic_desc<<<2,1024>>>(1024);
        rpn_decode<<<2,1024>>>(iminfo,i+2,W,k);
        nms_level<<<2,256>>>(k,offs[i]);
    }
    build_cat_keys<<<2,256>>>();
    bitonic_desc<<<2,1024>>>(8192);
    gather_rois<<<2,256>>>();

    roialign<<<2000,256>>>(feats[0],feats[1],feats[2],feats[3],feats[4]);

    gemm128<0,true,true ><<<dim3(8,16),256>>>(gp->roifeat,fc1w,fc1b,gp->h1,2000,1024,12544,0,0);
    gemm128<0,true,true ><<<dim3(8,16),256>>>(gp->h1,fc2w,fc2b,gp->h2,2000,1024,1024,0,0);
    gemm128<0,false,false><<<dim3(1,16),256>>>(gp->h2,clsw,clsb,gp->clsl,2000,91,1024,0,0);
    gemm128<0,true,false><<<dim3(3,16),256>>>(gp->h2,boxw,boxb,gp->boxl,2000,364,1024,0,0);

    softmax91<<<8,256>>>();
    nms_det<<<180,256>>>(iminfo);
    build_det_keys<<<2,256>>>();
    bitonic_desc<<<2,1024>>>(16384);
    write_out<<<1,256>>>((float*)d_out,out_size);
}

// round 6
// speedup vs baseline: 1.2000x; 1.2000x over previous
#include <cuda_runtime.h>
#include <math.h>
#include <stddef.h>

#define NEGF (-1.0e9f)
#define CLIPV 4.135166556742356f

__device__ __forceinline__ unsigned skey(float s){
    unsigned u = __float_as_uint(s);
    return (u & 0x80000000u) ? ~u : (u | 0x80000000u);
}

struct __align__(256) Scratch {
    float h[35782656];
    float scores[2][209664];
    float deltas[2][838656];
    unsigned hist[2][65536];
    int tiebuf[2][4096];
    int tiecnt[2];
    int selcnt[2];
    unsigned long long sbuf[2][16384];
    float pb[2][4000];
    float ps[2][1000];
    float catb[2][19280];
    float cats[2][4820];
    float rois[2][4000];
    float roifeat[25088000];
    float h1[2048000];
    float h2[2048000];
    float clsl[182000];
    float boxl[728000];
    float dns[2][9000];
    float dnb[2][36000];
};
__device__ Scratch g;

__constant__ int cH[5]={208,104,52,26,13};
__constant__ int cW[5]={336,168,84,42,21};
__constant__ float cStrideF[5]={4.f,8.f,16.f,32.f,64.f};

// ------- SGEMM 128x128x8, 256 thr, 8x8 reg tiles, double-buffered smem ----
// MODE 0: dense A[M,K]. MODE 1: implicit 3x3 SAME conv, A=NHWC C=256, K=2304.
template<int MODE,bool VECB,bool RELU>
__global__ void gemm128(const float* __restrict__ A,const float* __restrict__ Bw,
                        const float* __restrict__ bias,float* __restrict__ C,
                        int M,int N,int K,int H,int W){
    __shared__ float As[2][8][128];
    __shared__ float Bs[2][8][132];
    int tid=threadIdx.x;
    int bm=blockIdx.y*128, bn=blockIdx.x*128;
    int tx=tid&15, ty=tid>>4;
    float acc[8][8];
#pragma unroll
    for(int i=0;i<8;i++)
#pragma unroll
        for(int j=0;j<8;j++) acc[i][j]=0.f;
    int ar=tid>>1, aco=(tid&1)*4;
    int brow=tid>>5, bcol=(tid&31)*4;
    int m=bm+ar;
    int ab=0,ay=0,ax=0;
    if(MODE==1){
        int HW=H*W; int mm=(m<M)?m:0;
        ab=mm/HW; int rem=mm-ab*HW; ay=rem/W; ax=rem-ay*W;
    }
    auto loadA=[&](int k0)->float4{
        float4 r=make_float4(0.f,0.f,0.f,0.f);
        if(m<M){
            if(MODE==0){
                r=*(const float4*)(A+(size_t)m*K+k0+aco);
            }else{
                int kz=k0+aco; int rr=kz>>8, ci=kz&255;
                int ky=rr/3, kx=rr-ky*3;
                int yy=ay+ky-1, xx=ax+kx-1;
                if(yy>=0&&yy<H&&xx>=0&&xx<W)
                    r=*(const float4*)(A+(((size_t)ab*H+yy)*W+xx)*256+ci);
            }
        }
        return r;
    };
    auto loadB=[&](int k0)->float4{
        int kk=k0+brow; int n=bn+bcol;
        float4 r=make_float4(0.f,0.f,0.f,0.f);
        if(VECB&&(n+3)<N){
            r=*(const float4*)(Bw+(size_t)kk*N+n);
        }else{
            if(n+0<N) r.x=Bw[(size_t)kk*N+n+0];
            if(n+1<N) r.y=Bw[(size_t)kk*N+n+1];
            if(n+2<N) r.z=Bw[(size_t)kk*N+n+2];
            if(n+3<N) r.w=Bw[(size_t)kk*N+n+3];
        }
        return r;
    };
    int T=K>>3;
    float4 av=loadA(0), bv=loadB(0);
    As[0][aco+0][ar]=av.x; As[0][aco+1][ar]=av.y; As[0][aco+2][ar]=av.z; As[0][aco+3][ar]=av.w;
    *(float4*)&Bs[0][brow][bcol]=bv;
    __syncthreads();
    for(int t=0;t<T;t++){
        int cur=t&1, nxt=cur^1;
        if(t+1<T){ av=loadA((t+1)*8); bv=loadB((t+1)*8); }
#pragma unroll
        for(int kk=0;kk<8;kk++){
            float af[8],bf[8];
            *(float4*)&af[0]=*(const float4*)&As[cur][kk][ty*8];
            *(float4*)&af[4]=*(const float4*)&As[cur][kk][ty*8+4];
            *(float4*)&bf[0]=*(const float4*)&Bs[cur][kk][tx*8];
            *(float4*)&bf[4]=*(const float4*)&Bs[cur][kk][tx*8+4];
#pragma unroll
            for(int i=0;i<8;i++)
#pragma unroll
                for(int j=0;j<8;j++) acc[i][j]+=af[i]*bf[j];
        }
        if(t+1<T){
            As[nxt][aco+0][ar]=av.x; As[nxt][aco+1][ar]=av.y;
            As[nxt][aco+2][ar]=av.z; As[nxt][aco+3][ar]=av.w;
            *(float4*)&Bs[nxt][brow][bcol]=bv;
        }
        __syncthreads();
    }
#pragma unroll
    for(int i=0;i<8;i++){
        int mm=bm+ty*8+i;
        if(mm>=M) continue;
#pragma unroll
        for(int j=0;j<8;j++){
            int nn=bn+tx*8+j;
            if(nn>=N) continue;
            float v=acc[i][j]+bias[nn];
            if(RELU) v=fmaxf(v,0.f);
            C[(size_t)mm*N+nn]=v;
        }
    }
}

// ---------------- RPN head: 15 dots over 256 channels per pixel ----------
__global__ void rpn_head_kernel(const float* __restrict__ h,
    const float* __restrict__ sw,const float* __restrict__ sb,
    const float* __restrict__ bw,const float* __restrict__ bb,
    int HW,int Btot){
    __shared__ float wsm[256][16];
    __shared__ float bsm[16];
    int tid=threadIdx.x;
    for(int i=tid;i<256*16;i+=blockDim.x){
        int c=i>>4, j=i&15;
        float v=0.f;
        if(j<3) v=sw[c*3+j];
        else if(j<15) v=bw[c*12+(j-3)];
        wsm[c][j]=v;
    }
    if(tid<16) bsm[tid]=(tid<3)?sb[tid]:((tid<15)?bb[tid-3]:0.f);
    __syncthreads();
    int m=blockIdx.x*blockDim.x+tid;
    if(m>=Btot) return;
    int b=m/HW, pix=m-b*HW;
    const float* hr=h+(size_t)m*256;
    float acc[15];
#pragma unroll
    for(int j=0;j<15;j++) acc[j]=0.f;
    for(int c=0;c<256;c+=4){
        float4 v=*(const float4*)(hr+c);
#pragma unroll
        for(int j=0;j<15;j++)
            acc[j]+=v.x*wsm[c][j]+v.y*wsm[c+1][j]+v.z*wsm[c+2][j]+v.w*wsm[c+3][j];
    }
    for(int a=0;a<3;a++){
        float lg=acc[a]+bsm[a];
        g.scores[b][pix*3+a]=1.f/(1.f+expf(-lg));
        for(int d=0;d<4;d++)
            g.deltas[b][(size_t)(pix*3+a)*4+d]=acc[3+a*4+d]+bsm[3+a*4+d];
    }
}

// ------------- exact stable top-k: 16+16-bit radix select, 1 blk/batch ----
__global__ void select_topk(int Nl,int k){
    int b=blockIdx.x;
    const float* s=g.scores[b];
    unsigned* hist=g.hist[b];
    int tid=threadIdx.x;
    __shared__ unsigned csum[1024];
    __shared__ int s_t,s_above,s_u,s_above2;
    if(tid==0){ g.selcnt[b]=0; g.tiecnt[b]=0; }
    for(int i=tid;i<65536;i+=1024) __stcg(&hist[i],0u);
    __syncthreads();
    for(int i=tid;i<Nl;i+=1024) atomicAdd(&hist[skey(s[i])>>16],1u);
    __syncthreads();
    {
        unsigned own=0; int base=65535-tid*64;
        for(int q=0;q<64;q++) own+=__ldcg(&hist[base-q]);
        csum[tid]=own; __syncthreads();
        for(int off=1;off<1024;off<<=1){
            unsigned v=csum[tid]; unsigned add=(tid>=off)?csum[tid-off]:0u; __syncthreads();
            csum[tid]=v+add; __syncthreads();
        }
        unsigned excl=csum[tid]-own;
        if(excl<(unsigned)k&&csum[tid]>=(unsigned)k){
            unsigned cum=excl;
            for(int q=0;q<64;q++){
                unsigned c=__ldcg(&hist[base-q]);
                if(cum+c>=(unsigned)k){ s_t=base-q; s_above=(int)cum; break; }
                cum+=c;
            }
        }
        __syncthreads();
    }
    int t=s_t, above=s_above;
    for(int i=tid;i<65536;i+=1024) __stcg(&hist[i],0u);
    __syncthreads();
    for(int i=tid;i<Nl;i+=1024){
        unsigned key=skey(s[i]);
        if((int)(key>>16)==t) atomicAdd(&hist[key&0xFFFFu],1u);
    }
    __syncthreads();
    int need=k-above;
    {
        unsigned own=0; int base=65535-tid*64;
        for(int q=0;q<64;q++) own+=__ldcg(&hist[base-q]);
        csum[tid]=own; __syncthreads();
        for(int off=1;off<1024;off<<=1){
            unsigned v=csum[tid]; unsigned add=(tid>=off)?csum[tid-off]:0u; __syncthreads();
            csum[tid]=v+add; __syncthreads();
        }
        unsigned excl=csum[tid]-own;
        if(excl<(unsigned)need&&csum[tid]>=(unsigned)need){
            unsigned cum=excl;
            for(int q=0;q<64;q++){
                unsigned c=__ldcg(&hist[base-q]);
                if(cum+c>=(unsigned)need){ s_u=base-q; s_above2=(int)cum; break; }
                cum+=c;
            }
        }
        __syncthreads();
    }
    int u=s_u, above2=s_above2;
    unsigned T=(((unsigned)t)<<16)|(unsigned)u;
    for(int i=tid;i<Nl;i+=1024){
        unsigned key=skey(s[i]);
        if(key>T){
            int pos=atomicAdd(&g.selcnt[b],1);
            g.sbuf[b][pos]=(((unsigned long long)key)<<32)|(unsigned)(~(unsigned)i);
        }else if(key==T){
            int p=atomicAdd(&g.tiecnt[b],1);
            if(p<4096) g.tiebuf[b][p]=i;
        }
    }
    __syncthreads();
    int ct=g.tiecnt[b]; if(ct>4096) ct=4096;
    int mtake=need-above2;
    int pos0=above+above2;
    for(int ti=tid;ti<ct;ti+=1024){
        int myi=g.tiebuf[b][ti];
        int rank=0;
        for(int q=0;q<ct;q++) rank+=(g.tiebuf[b][q]<myi);
        if(rank<mtake)
            g.sbuf[b][pos0+rank]=(((unsigned long long)T)<<32)|(unsigned)(~(unsigned)myi);
    }
    __syncthreads();
    if(tid>=k&&tid<1024) g.sbuf[b][tid]=0ull;
}

// Descending bitonic sort of g.sbuf[blockIdx.x][0..n), n pow2.
__global__ void bitonic_desc(int n){
    unsigned long long* a=g.sbuf[blockIdx.x];
    for(int k=2;k<=n;k<<=1){
        for(int j=k>>1;j>0;j>>=1){
            for(int i=threadIdx.x;i<n;i+=blockDim.x){
                int l=i^j;
                if(l>i){
                    unsigned long long x=a[i],y=a[l];
                    bool sw=((i&k)==0)?(x<y):(x>y);
                    if(sw){ a[i]=y; a[l]=x; }
                }
            }
            __syncthreads();
        }
    }
}

// Decode sorted top-k RPN proposals (anchors in fp64 = numpy-exact).
__global__ void rpn_decode(const float* __restrict__ iminfo,int lvl,int W,int k){
    int b=blockIdx.x; int r=threadIdx.x;
    if(r>=k) return;
    unsigned long long key=g.sbuf[b][r];
    int i=(int)(~(unsigned)key);
    int a=i%3; int pix=i/3; int x=pix%W; int y=pix/W;
    double stride=(double)(1<<lvl);
    double size=8.0*stride;
    double rr=(a==0)?1.0:((a==1)?0.5:2.0);
    double sr=sqrt(rr);
    double hh=size/sr, ww=size*sr;
    double ycd=((double)y+0.5)*stride, xcd=((double)x+0.5)*stride;
    float ya1=(float)(ycd-hh*0.5), xa1=(float)(xcd-ww*0.5);
    float ya2=(float)(ycd+hh*0.5), xa2=(float)(xcd+ww*0.5);
    const float* d=&g.deltas[b][(size_t)i*4];
    float ha=ya2-ya1, wa=xa2-xa1;
    float yc=ya1+0.5f*ha, xc=xa1+0.5f*wa;
    float dy=d[0], dx=d[1];
    float dh=fminf(d[2],CLIPV), dw=fminf(d[3],CLIPV);
    float pcy=dy*ha+yc, pcx=dx*wa+xc;
    float ph=expf(dh)*ha, pw=expf(dw)*wa;
    float hI=iminfo[b*5+0], wI=iminfo[b*5+1];
    g.pb[b][r*4+0]=fminf(fmaxf(pcy-0.5f*ph,0.f),hI);
    g.pb[b][r*4+1]=fminf(fmaxf(pcx-0.5f*pw,0.f),wI);
    g.pb[b][r*4+2]=fminf(fmaxf(pcy+0.5f*ph,0.f),hI);
    g.pb[b][r*4+3]=fminf(fmaxf(pcx+0.5f*pw,0.f),wI);
    g.ps[b][r]=g.scores[b][i];
}

// -------- sequential NMS core (argmax-first-index + explicit s[j]=NEG) ----
// Early exit: once the selected max is invalid, ALL remaining iterations of
// the reference loop produce identical invalid outputs (argmax over all-NEG
// scores only re-NEGs an entry). Exact, not approximate.
__device__ void nms_run(float* y1,float* x1,float* y2,float* x2,float* s,
                        int n,int iters,float th,float* ob,float* os){
    __shared__ float rv[256];
    __shared__ int ri[256];
    __shared__ float cb[4];
    int tid=threadIdx.x;
    for(int it=0;it<iters;it++){
        float bv=-3.0e38f; int bi=1<<30;
        for(int i=tid;i<n;i+=256){
            float v=s[i];
            if(v>bv||(v==bv&&i<bi)){ bv=v; bi=i; }
        }
        rv[tid]=bv; ri[tid]=bi; __syncthreads();
        for(int o=128;o>0;o>>=1){
            if(tid<o){
                float v=rv[tid+o]; int j=ri[tid+o];
                if(v>rv[tid]||(v==rv[tid]&&j<ri[tid])){ rv[tid]=v; ri[tid]=j; }
            }
            __syncthreads();
        }
        int j=ri[0]; float js=rv[0];
        if(js<=NEGF*0.5f){
            // fill remaining outputs with the invalid pattern and stop
            for(int r=it+tid;r<iters;r+=256){
                os[r]=NEGF;
                ob[r*4+0]=0.f; ob[r*4+1]=0.f; ob[r*4+2]=0.f; ob[r*4+3]=0.f;
            }
            __syncthreads();
            return;
        }
        if(tid==0){ cb[0]=y1[j]; cb[1]=x1[j]; cb[2]=y2[j]; cb[3]=x2[j]; }
        __syncthreads();
        float a1=cb[0],a2=cb[1],a3=cb[2],a4=cb[3];
        float aA=(a3-a1)*(a4-a2);
        for(int i=tid;i<n;i+=256){
            float yy1=fmaxf(a1,y1[i]), xx1=fmaxf(a2,x1[i]);
            float yy2=fminf(a3,y2[i]), xx2=fminf(a4,x2[i]);
            float inter=fmaxf(yy2-yy1,0.f)*fmaxf(xx2-xx1,0.f);
            float bA=(y2[i]-y1[i])*(x2[i]-x1[i]);
            float iou=inter/(aA+bA-inter+1e-8f);
            if(iou>=th) s[i]=NEGF;
        }
        __syncthreads();
        if(tid==0){
            s[j]=NEGF;
            os[it]=js;
            ob[it*4+0]=a1; ob[it*4+1]=a2; ob[it*4+2]=a3; ob[it*4+3]=a4;
        }
        __syncthreads();
    }
}

__global__ void nms_level(int k,int off){
    __shared__ float y1[1000],x1[1000],y2[1000],x2[1000],s[1000];
    int b=blockIdx.x; int tid=threadIdx.x;
    for(int i=tid;i<k;i+=256){
        y1[i]=g.pb[b][i*4+0]; x1[i]=g.pb[b][i*4+1];
        y2[i]=g.pb[b][i*4+2]; x2[i]=g.pb[b][i*4+3];
        s[i]=g.ps[b][i];
    }
    __syncthreads();
    nms_run(y1,x1,y2,x2,s,k,k,0.7f,&g.catb[b][off*4],&g.cats[b][off]);
}

__global__ void build_cat_keys(){
    int b=blockIdx.x;
    for(int i=threadIdx.x;i<8192;i+=blockDim.x){
        unsigned long long key=0ull;
        if(i<4819) key=(((unsigned long long)skey(g.cats[b][i]))<<32)|(unsigned)(~(unsigned)i);
        g.sbuf[b][i]=key;
    }
}

__global__ void gather_rois(){
    int b=blockIdx.x;
    for(int r=threadIdx.x;r<1000;r+=blockDim.x){
        int i=(int)(~(unsigned)g.sbuf[b][r]);
        for(int d=0;d<4;d++) g.rois[b][r*4+d]=g.catb[b][i*4+d];
    }
}

// ---------------- multilevel ROI align, 1 block per roi, thread=channel ---
__global__ void roialign(const float* f0,const float* f1,const float* f2,
                         const float* f3,const float* f4){
    int br=blockIdx.x; int b=br/1000;
    int c=threadIdx.x;
    const float* ro=&g.rois[b][(br%1000)*4];
    float y1=ro[0],x1=ro[1],y2=ro[2],x2=ro[3];
    float area=fmaxf((y2-y1)*(x2-x1),1e-6f);
    float lv=floorf(4.f+log2f(sqrtf(area)/224.f));
    lv=fminf(fmaxf(lv,2.f),6.f);
    int li=(int)lv-2;
    const float* fp=(li==0)?f0:(li==1)?f1:(li==2)?f2:(li==3)?f3:f4;
    int H=cH[li],W=cW[li];
    float Hf=(float)H,Wf=(float)W;
    float stride=cStrideF[li];
    const float* base=fp+(size_t)b*H*W*256;
    float* outp=&g.roifeat[(size_t)br*12544];
    for(int p=0;p<49;p++){
        int py=p/7,px=p%7;
        float uy=((float)py+0.5f)/7.f, ux=((float)px+0.5f)/7.f;
        float ys=(y1+(y2-y1)*uy)/stride-0.5f;
        float xs=(x1+(x2-x1)*ux)/stride-0.5f;
        ys=fminf(fmaxf(ys,0.f),Hf-1.f);
        xs=fminf(fmaxf(xs,0.f),Wf-1.f);
        float y0=floorf(ys),x0=floorf(xs);
        float wy=ys-y0,wx=xs-x0;
        int y0i=(int)y0,x0i=(int)x0;
        int y1i=min(y0i+1,H-1),x1i=min(x0i+1,W-1);
        const float* p00=base+((size_t)y0i*W+x0i)*256;
        const float* p01=base+((size_t)y0i*W+x1i)*256;
        const float* p10=base+((size_t)y1i*W+x0i)*256;
        const float* p11=base+((size_t)y1i*W+x1i)*256;
        float w00=(1.f-wy)*(1.f-wx), w01=(1.f-wy)*wx;
        float w10=wy*(1.f-wx), w11=wy*wx;
        outp[p*256+c]=p00[c]*w00+p01[c]*w01+p10[c]*w10+p11[c]*w11;
    }
}

__global__ void softmax91(){
    int i=blockIdx.x*blockDim.x+threadIdx.x;
    if(i>=2000) return;
    float* p=&g.clsl[(size_t)i*91];
    float mx=p[0];
    for(int c=1;c<91;c++) mx=fmaxf(mx,p[c]);
    float sm=0.f;
    float e[91];
    for(int c=0;c<91;c++){ e[c]=expf(p[c]-mx); sm+=e[c]; }
    for(int c=0;c<91;c++) p[c]=e[c]/sm;
}

__global__ void nms_det(const float* __restrict__ iminfo){
    __shared__ float y1[1000],x1[1000],y2[1000],x2[1000],s[1000];
    int blk=blockIdx.x; int b=blk/90; int c=blk%90+1;
    int tid=threadIdx.x;
    float hI=iminfo[b*5+0], wI=iminfo[b*5+1];
    for(int i=tid;i<1000;i+=256){
        const float* ro=&g.rois[b][i*4];
        float ya1=ro[0],xa1=ro[1],ya2=ro[2],xa2=ro[3];
        float ha=ya2-ya1, wa=xa2-xa1;
        float yc=ya1+0.5f*ha, xc=xa1+0.5f*wa;
        const float* d=&g.boxl[((size_t)(b*1000+i)*91+c)*4];
        float dy=d[0]/10.f, dx=d[1]/10.f;
        float dh=fminf(d[2]/5.f,CLIPV), dw=fminf(d[3]/5.f,CLIPV);
        float pcy=dy*ha+yc, pcx=dx*wa+xc;
        float ph=expf(dh)*ha, pw=expf(dw)*wa;
        y1[i]=fminf(fmaxf(pcy-0.5f*ph,0.f),hI);
        x1[i]=fminf(fmaxf(pcx-0.5f*pw,0.f),wI);
        y2[i]=fminf(fmaxf(pcy+0.5f*ph,0.f),hI);
        x2[i]=fminf(fmaxf(pcx+0.5f*pw,0.f),wI);
        float p=g.clsl[(size_t)(b*1000+i)*91+c];
        s[i]=(p>=0.05f)?p:NEGF;
    }
    __syncthreads();
    nms_run(y1,x1,y2,x2,s,1000,100,0.5f,&g.dnb[b][(c-1)*400],&g.dns[b][(c-1)*100]);
}

__global__ void build_det_keys(){
    int b=blockIdx.x;
    for(int i=threadIdx.x;i<16384;i+=blockDim.x){
        unsigned long long key=0ull;
        if(i<9000) key=(((unsigned long long)skey(g.dns[b][i]))<<32)|(unsigned)(~(unsigned)i);
        g.sbuf[b][i]=key;
    }
}

__global__ void write_out(float* out,int out_size){
    int tid=threadIdx.x;
    for(int i=tid;i<out_size;i+=256) out[i]=0.f;
    __syncthreads();
    __shared__ int cnt;
    for(int b=0;b<2;b++){
        if(tid==0) cnt=0;
        __syncthreads();
        if(tid<100){
            int r=tid;
            int idx=(int)(~(unsigned)g.sbuf[b][r]);
            float sc=g.dns[b][idx];
            bool valid=sc>0.f;
            if(valid) atomicAdd(&cnt,1);
            float cls=valid?(float)(idx/100+1):0.f;
            int ob=2+b*400+r*4;
            for(int d=0;d<4;d++){
                int o=ob+d;
                if(o<out_size) out[o]=valid?g.dnb[b][idx*4+d]:0.f;
            }
            int oc=2+800+b*100+r;
            if(oc<out_size) out[oc]=cls;
            int os=2+1000+b*100+r;
            if(os<out_size) out[os]=valid?sc:0.f;
        }
        __syncthreads();
        if(tid==0&&b<out_size) out[b]=(float)cnt;
        __syncthreads();
    }
}

extern "C" void kernel_launch(void* const* d_in,const int* in_sizes,int n_in,
                              void* d_out,int out_size){
    const float* feats[5];
    for(int i=0;i<5;i++) feats[i]=(const float*)d_in[i];
    const float* iminfo=(const float*)d_in[5];
    const float* cw =(const float*)d_in[6];
    const float* cbv=(const float*)d_in[7];
    const float* sw =(const float*)d_in[8];
    const float* sb =(const float*)d_in[9];
    const float* bw =(const float*)d_in[10];
    const float* bbv=(const float*)d_in[11];
    const float* fc1w=(const float*)d_in[12];
    const float* fc1b=(const float*)d_in[13];
    const float* fc2w=(const float*)d_in[14];
    const float* fc2b=(const float*)d_in[15];
    const float* clsw=(const float*)d_in[16];
    const float* clsb=(const float*)d_in[17];
    const float* boxw=(const float*)d_in[18];
    const float* boxb=(const float*)d_in[19];

    Scratch* gp=nullptr;
    cudaGetSymbolAddress((void**)&gp,g);

    int Hs[5]={208,104,52,26,13}, Ws[5]={336,168,84,42,21};
    int offs[5]={0,1000,2000,3000,4000};

    for(int i=0;i<5;i++){
        int H=Hs[i],W=Ws[i],M=2*H*W;
        dim3 gr(2,(M+127)/128);
        gemm128<1,true,true><<<gr,256>>>(feats[i],cw,cbv,gp->h,M,256,2304,H,W);
        rpn_head_kernel<<<(M+255)/256,256>>>(gp->h,sw,sb,bw,bbv,H*W,M);
        int Nl=H*W*3;
        int k=Nl<1000?Nl:1000;
        select_topk<<<2,1024>>>(Nl,k);
        bitonic_desc<<<2,1024>>>(1024);
        rpn_decode<<<2,1024>>>(iminfo,i+2,W,k);
        nms_level<<<2,256>>>(k,offs[i]);
    }
    build_cat_keys<<<2,256>>>();
    bitonic_desc<<<2,1024>>>(8192);
    gather_rois<<<2,256>>>();

    roialign<<<2000,256>>>(feats[0],feats[1],feats[2],feats[3],feats[4]);

    gemm128<0,true,true ><<<dim3(8,16),256>>>(gp->roifeat,fc1w,fc1b,gp->h1,2000,1024,12544,0,0);
    gemm128<0,true,true ><<<dim3(8,16),256>>>(gp->h1,fc2w,fc2b,gp->h2,2000,1024,1024,0,0);
    gemm128<0,false,false><<<dim3(1,16),256>>>(gp->h2,clsw,clsb,gp->clsl,2000,91,1024,0,0);
    gemm128<0,true,false><<<dim3(3,16),256>>>(gp->h2,boxw,boxb,gp->boxl,2000,364,1024,0,0);

    softmax91<<<8,256>>>();
    nms_det<<<180,256>>>(iminfo);
    build_det_keys<<<2,256>>>();
    bitonic_desc<<<2,1024>>>(16384);
    write_out<<<1,256>>>((float*)d_out,out_size);
}

// round 7
// speedup vs baseline: 1.9995x; 1.6663x over previous
#include <cuda_runtime.h>
#include <math.h>
#include <stddef.h>

#define NEGF (-1.0e9f)
#define CLIPV 4.135166556742356f

__device__ __forceinline__ unsigned skey(float s){
    unsigned u = __float_as_uint(s);
    return (u & 0x80000000u) ? ~u : (u | 0x80000000u);
}
__device__ __forceinline__ unsigned f2tf32(float x){
    unsigned r; asm("cvt.rna.tf32.f32 %0, %1;" : "=r"(r) : "f"(x)); return r;
}
__device__ __forceinline__ float tf32f(float x){ return __uint_as_float(f2tf32(x)); }

struct __align__(256) Scratch {
    float h[35782656];
    float scores[2][209664];
    float deltas[2][838656];
    unsigned hist[2][65536];
    int tiebuf[2][4096];
    int tiecnt[2];
    int selcnt[2];
    unsigned long long sbuf[2][16384];
    float pb[2][4000];
    float ps[2][1000];
    float catb[2][19280];
    float cats[2][4820];
    float rois[2][4000];
    float roifeat[25088000];
    float h1[2048000];
    float h2[2048000];
    float clsl[182000];
    float boxl[728000];
    float dns[2][9000];
    float dnb[2][36000];
};
__device__ Scratch g;

__constant__ int cH[5]={208,104,52,26,13};
__constant__ int cW[5]={336,168,84,42,21};
__constant__ float cStrideF[5]={4.f,8.f,16.f,32.f,64.f};

// ================= TF32 tensor-core GEMM 128x128x32 =======================
// MODE 0: dense A[M,K]. MODE 1: implicit 3x3 SAME conv, A=NHWC C=256, K=2304.
// Requires K%32==0, N%128==0. 256 threads, 8 warps (4 in M x 2 in N).
#define TFPAD 36
#define TFSTG (128*TFPAD)
template<int MODE,bool RELU>
__global__ void gemm_tf32(const float* __restrict__ A,const float* __restrict__ Bw,
                          const float* __restrict__ bias,float* __restrict__ C,
                          int M,int N,int K,int H,int W){
    extern __shared__ float sm[];
    float* Asm=sm;              // [2][128][TFPAD]
    float* Bsm=sm+2*TFSTG;      // [2][128][TFPAD]  (stored [n][k])
    int tid=threadIdx.x;
    int bm=blockIdx.y*128, bn=blockIdx.x*128;
    int wid=tid>>5, lane=tid&31;
    int wm=wid&3, wn=wid>>2;
    int lr=lane>>2, lc=lane&3;

    float acc[2][8][4];
#pragma unroll
    for(int i=0;i<2;i++)
#pragma unroll
        for(int j=0;j<8;j++)
#pragma unroll
            for(int q=0;q<4;q++) acc[i][j][q]=0.f;

    // A loader: row = tid>>1, k-half = (tid&1)*16
    int arow=tid>>1, ahalf=tid&1;
    int m=bm+arow;
    int ab=0,ay=0,ax=0;
    if(MODE==1){
        int HW=H*W; int mm=(m<M)?m:0;
        ab=mm/HW; int rem=mm-ab*HW; ay=rem/W; ax=rem-ay*W;
    }
    // B loader: k = tid>>3, n0 = (tid&7)*16
    int bk=tid>>3, bn0=(tid&7)*16;

    float4 av[4], bvv[4];
    auto loadG=[&](int k0){
#pragma unroll
        for(int c=0;c<4;c++) av[c]=make_float4(0.f,0.f,0.f,0.f);
        if(m<M){
            if(MODE==0){
                const float* p=A+(size_t)m*K+k0+ahalf*16;
#pragma unroll
                for(int c=0;c<4;c++) av[c]=*(const float4*)(p+c*4);
            }else{
                int r=k0>>8;
                int ky=r/3, kx=r-ky*3;
                int yy=ay+ky-1, xx=ax+kx-1;
                if(yy>=0&&yy<H&&xx>=0&&xx<W){
                    const float* p=A+(((size_t)ab*H+yy)*W+xx)*256+(k0&255)+ahalf*16;
#pragma unroll
                    for(int c=0;c<4;c++) av[c]=*(const float4*)(p+c*4);
                }
            }
        }
        const float* q=Bw+(size_t)(k0+bk)*N+bn+bn0;
#pragma unroll
        for(int c=0;c<4;c++) bvv[c]=*(const float4*)(q+c*4);
    };
    auto storeS=[&](int stg){
        float* Ad=Asm+stg*TFSTG+arow*TFPAD+ahalf*16;
#pragma unroll
        for(int c=0;c<4;c++){
            float4 v=av[c];
            v.x=tf32f(v.x); v.y=tf32f(v.y); v.z=tf32f(v.z); v.w=tf32f(v.w);
            *(float4*)(Ad+c*4)=v;
        }
        float* Bd=Bsm+stg*TFSTG+bk;   // Bsm[n][k]: + n*TFPAD
#pragma unroll
        for(int c=0;c<4;c++){
            Bd[(bn0+c*4+0)*TFPAD]=tf32f(bvv[c].x);
            Bd[(bn0+c*4+1)*TFPAD]=tf32f(bvv[c].y);
            Bd[(bn0+c*4+2)*TFPAD]=tf32f(bvv[c].z);
            Bd[(bn0+c*4+3)*TFPAD]=tf32f(bvv[c].w);
        }
    };

    int T=K>>5;
    loadG(0); storeS(0);
    __syncthreads();
    for(int t=0;t<T;t++){
        int cur=t&1, nxt=cur^1;
        if(t+1<T) loadG((t+1)*32);
        const float* Ac=Asm+cur*TFSTG;
        const float* Bc=Bsm+cur*TFSTG;
#pragma unroll
        for(int ks=0;ks<4;ks++){
            int kb=ks*8;
            unsigned af[2][4];
#pragma unroll
            for(int mt=0;mt<2;mt++){
                int r0=wm*32+mt*16+lr;
                af[mt][0]=__float_as_uint(Ac[r0*TFPAD+kb+lc]);
                af[mt][1]=__float_as_uint(Ac[(r0+8)*TFPAD+kb+lc]);
                af[mt][2]=__float_as_uint(Ac[r0*TFPAD+kb+lc+4]);
                af[mt][3]=__float_as_uint(Ac[(r0+8)*TFPAD+kb+lc+4]);
            }
#pragma unroll
            for(int nt=0;nt<8;nt++){
                int cb=wn*64+nt*8+lr;
                unsigned b0=__float_as_uint(Bc[cb*TFPAD+kb+lc]);
                unsigned b1=__float_as_uint(Bc[cb*TFPAD+kb+lc+4]);
#pragma unroll
                for(int mt=0;mt<2;mt++){
                    asm volatile(
                      "mma.sync.aligned.m16n8k8.row.col.f32.tf32.tf32.f32 "
                      "{%0,%1,%2,%3}, {%4,%5,%6,%7}, {%8,%9}, {%0,%1,%2,%3};\n"
                      : "+f"(acc[mt][nt][0]),"+f"(acc[mt][nt][1]),
                        "+f"(acc[mt][nt][2]),"+f"(acc[mt][nt][3])
                      : "r"(af[mt][0]),"r"(af[mt][1]),"r"(af[mt][2]),"r"(af[mt][3]),
                        "r"(b0),"r"(b1));
                }
            }
        }
        if(t+1<T) storeS(nxt);
        __syncthreads();
    }
    // epilogue
#pragma unroll
    for(int mt=0;mt<2;mt++){
#pragma unroll
        for(int nt=0;nt<8;nt++){
            int r0=bm+wm*32+mt*16+lr;
            int c0=bn+wn*64+nt*8+lc*2;
            float b0=bias[c0], b1=bias[c0+1];
            float v0=acc[mt][nt][0]+b0, v1=acc[mt][nt][1]+b1;
            float v2=acc[mt][nt][2]+b0, v3=acc[mt][nt][3]+b1;
            if(RELU){ v0=fmaxf(v0,0.f); v1=fmaxf(v1,0.f); v2=fmaxf(v2,0.f); v3=fmaxf(v3,0.f); }
            if(r0<M){ C[(size_t)r0*N+c0]=v0; C[(size_t)r0*N+c0+1]=v1; }
            if(r0+8<M){ C[(size_t)(r0+8)*N+c0]=v2; C[(size_t)(r0+8)*N+c0+1]=v3; }
        }
    }
}

// ---------------- fp32 SGEMM (small heads), double-buffered ---------------
template<int MODE,bool VECB,bool RELU>
__global__ void gemm128(const float* __restrict__ A,const float* __restrict__ Bw,
                        const float* __restrict__ bias,float* __restrict__ C,
                        int M,int N,int K,int H,int W){
    __shared__ float As[2][8][128];
    __shared__ float Bs[2][8][132];
    int tid=threadIdx.x;
    int bm=blockIdx.y*128, bn=blockIdx.x*128;
    int tx=tid&15, ty=tid>>4;
    float acc[8][8];
#pragma unroll
    for(int i=0;i<8;i++)
#pragma unroll
        for(int j=0;j<8;j++) acc[i][j]=0.f;
    int ar=tid>>1, aco=(tid&1)*4;
    int brow=tid>>5, bcol=(tid&31)*4;
    int m=bm+ar;
    auto loadA=[&](int k0)->float4{
        float4 r=make_float4(0.f,0.f,0.f,0.f);
        if(m<M) r=*(const float4*)(A+(size_t)m*K+k0+aco);
        return r;
    };
    auto loadB=[&](int k0)->float4{
        int kk=k0+brow; int n=bn+bcol;
        float4 r=make_float4(0.f,0.f,0.f,0.f);
        if(VECB&&(n+3)<N){
            r=*(const float4*)(Bw+(size_t)kk*N+n);
        }else{
            if(n+0<N) r.x=Bw[(size_t)kk*N+n+0];
            if(n+1<N) r.y=Bw[(size_t)kk*N+n+1];
            if(n+2<N) r.z=Bw[(size_t)kk*N+n+2];
            if(n+3<N) r.w=Bw[(size_t)kk*N+n+3];
        }
        return r;
    };
    int T=K>>3;
    float4 av=loadA(0), bv=loadB(0);
    As[0][aco+0][ar]=av.x; As[0][aco+1][ar]=av.y; As[0][aco+2][ar]=av.z; As[0][aco+3][ar]=av.w;
    *(float4*)&Bs[0][brow][bcol]=bv;
    __syncthreads();
    for(int t=0;t<T;t++){
        int cur=t&1, nxt=cur^1;
        if(t+1<T){ av=loadA((t+1)*8); bv=loadB((t+1)*8); }
#pragma unroll
        for(int kk=0;kk<8;kk++){
            float af[8],bf[8];
            *(float4*)&af[0]=*(const float4*)&As[cur][kk][ty*8];
            *(float4*)&af[4]=*(const float4*)&As[cur][kk][ty*8+4];
            *(float4*)&bf[0]=*(const float4*)&Bs[cur][kk][tx*8];
            *(float4*)&bf[4]=*(const float4*)&Bs[cur][kk][tx*8+4];
#pragma unroll
            for(int i=0;i<8;i++)
#pragma unroll
                for(int j=0;j<8;j++) acc[i][j]+=af[i]*bf[j];
        }
        if(t+1<T){
            As[nxt][aco+0][ar]=av.x; As[nxt][aco+1][ar]=av.y;
            As[nxt][aco+2][ar]=av.z; As[nxt][aco+3][ar]=av.w;
            *(float4*)&Bs[nxt][brow][bcol]=bv;
        }
        __syncthreads();
    }
#pragma unroll
    for(int i=0;i<8;i++){
        int mm=bm+ty*8+i;
        if(mm>=M) continue;
#pragma unroll
        for(int j=0;j<8;j++){
            int nn=bn+tx*8+j;
            if(nn>=N) continue;
            float v=acc[i][j]+bias[nn];
            if(RELU) v=fmaxf(v,0.f);
            C[(size_t)mm*N+nn]=v;
        }
    }
}

// ---------------- RPN head ----------------
__global__ void rpn_head_kernel(const float* __restrict__ h,
    const float* __restrict__ sw,const float* __restrict__ sb,
    const float* __restrict__ bw,const float* __restrict__ bb,
    int HW,int Btot){
    __shared__ float wsm[256][16];
    __shared__ float bsm[16];
    int tid=threadIdx.x;
    for(int i=tid;i<256*16;i+=blockDim.x){
        int c=i>>4, j=i&15;
        float v=0.f;
        if(j<3) v=sw[c*3+j];
        else if(j<15) v=bw[c*12+(j-3)];
        wsm[c][j]=v;
    }
    if(tid<16) bsm[tid]=(tid<3)?sb[tid]:((tid<15)?bb[tid-3]:0.f);
    __syncthreads();
    int m=blockIdx.x*blockDim.x+tid;
    if(m>=Btot) return;
    int b=m/HW, pix=m-b*HW;
    const float* hr=h+(size_t)m*256;
    float acc[15];
#pragma unroll
    for(int j=0;j<15;j++) acc[j]=0.f;
    for(int c=0;c<256;c+=4){
        float4 v=*(const float4*)(hr+c);
#pragma unroll
        for(int j=0;j<15;j++)
            acc[j]+=v.x*wsm[c][j]+v.y*wsm[c+1][j]+v.z*wsm[c+2][j]+v.w*wsm[c+3][j];
    }
    for(int a=0;a<3;a++){
        float lg=acc[a]+bsm[a];
        g.scores[b][pix*3+a]=1.f/(1.f+expf(-lg));
        for(int d=0;d<4;d++)
            g.deltas[b][(size_t)(pix*3+a)*4+d]=acc[3+a*4+d]+bsm[3+a*4+d];
    }
}

// ------------- exact stable top-k ----------
__global__ void select_topk(int Nl,int k){
    int b=blockIdx.x;
    const float* s=g.scores[b];
    unsigned* hist=g.hist[b];
    int tid=threadIdx.x;
    __shared__ unsigned csum[1024];
    __shared__ int s_t,s_above,s_u,s_above2;
    if(tid==0){ g.selcnt[b]=0; g.tiecnt[b]=0; }
    for(int i=tid;i<65536;i+=1024) __stcg(&hist[i],0u);
    __syncthreads();
    for(int i=tid;i<Nl;i+=1024) atomicAdd(&hist[skey(s[i])>>16],1u);
    __syncthreads();
    {
        unsigned own=0; int base=65535-tid*64;
        for(int q=0;q<64;q++) own+=__ldcg(&hist[base-q]);
        csum[tid]=own; __syncthreads();
        for(int off=1;off<1024;off<<=1){
            unsigned v=csum[tid]; unsigned add=(tid>=off)?csum[tid-off]:0u; __syncthreads();
            csum[tid]=v+add; __syncthreads();
        }
        unsigned excl=csum[tid]-own;
        if(excl<(unsigned)k&&csum[tid]>=(unsigned)k){
            unsigned cum=excl;
            for(int q=0;q<64;q++){
                unsigned c=__ldcg(&hist[base-q]);
                if(cum+c>=(unsigned)k){ s_t=base-q; s_above=(int)cum; break; }
                cum+=c;
            }
        }
        __syncthreads();
    }
    int t=s_t, above=s_above;
    for(int i=tid;i<65536;i+=1024) __stcg(&hist[i],0u);
    __syncthreads();
    for(int i=tid;i<Nl;i+=1024){
        unsigned key=skey(s[i]);
        if((int)(key>>16)==t) atomicAdd(&hist[key&0xFFFFu],1u);
    }
    __syncthreads();
    int need=k-above;
    {
        unsigned own=0; int base=65535-tid*64;
        for(int q=0;q<64;q++) own+=__ldcg(&hist[base-q]);
        csum[tid]=own; __syncthreads();
        for(int off=1;off<1024;off<<=1){
            unsigned v=csum[tid]; unsigned add=(tid>=off)?csum[tid-off]:0u; __syncthreads();
            csum[tid]=v+add; __syncthreads();
        }
        unsigned excl=csum[tid]-own;
        if(excl<(unsigned)need&&csum[tid]>=(unsigned)need){
            unsigned cum=excl;
            for(int q=0;q<64;q++){
                unsigned c=__ldcg(&hist[base-q]);
                if(cum+c>=(unsigned)need){ s_u=base-q; s_above2=(int)cum; break; }
                cum+=c;
            }
        }
        __syncthreads();
    }
    int u=s_u, above2=s_above2;
    unsigned T=(((unsigned)t)<<16)|(unsigned)u;
    for(int i=tid;i<Nl;i+=1024){
        unsigned key=skey(s[i]);
        if(key>T){
            int pos=atomicAdd(&g.selcnt[b],1);
            g.sbuf[b][pos]=(((unsigned long long)key)<<32)|(unsigned)(~(unsigned)i);
        }else if(key==T){
            int p=atomicAdd(&g.tiecnt[b],1);
            if(p<4096) g.tiebuf[b][p]=i;
        }
    }
    __syncthreads();
    int ct=g.tiecnt[b]; if(ct>4096) ct=4096;
    int mtake=need-above2;
    int pos0=above+above2;
    for(int ti=tid;ti<ct;ti+=1024){
        int myi=g.tiebuf[b][ti];
        int rank=0;
        for(int q=0;q<ct;q++) rank+=(g.tiebuf[b][q]<myi);
        if(rank<mtake)
            g.sbuf[b][pos0+rank]=(((unsigned long long)T)<<32)|(unsigned)(~(unsigned)myi);
    }
    __syncthreads();
    if(tid>=k&&tid<1024) g.sbuf[b][tid]=0ull;
}

__global__ void bitonic_desc(int n){
    unsigned long long* a=g.sbuf[blockIdx.x];
    for(int k=2;k<=n;k<<=1){
        for(int j=k>>1;j>0;j>>=1){
            for(int i=threadIdx.x;i<n;i+=blockDim.x){
                int l=i^j;
                if(l>i){
                    unsigned long long x=a[i],y=a[l];
                    bool sw=((i&k)==0)?(x<y):(x>y);
                    if(sw){ a[i]=y; a[l]=x; }
                }
            }
            __syncthreads();
        }
    }
}

__global__ void rpn_decode(const float* __restrict__ iminfo,int lvl,int W,int k){
    int b=blockIdx.x; int r=threadIdx.x;
    if(r>=k) return;
    unsigned long long key=g.sbuf[b][r];
    int i=(int)(~(unsigned)key);
    int a=i%3; int pix=i/3; int x=pix%W; int y=pix/W;
    double stride=(double)(1<<lvl);
    double size=8.0*stride;
    double rr=(a==0)?1.0:((a==1)?0.5:2.0);
    double sr=sqrt(rr);
    double hh=size/sr, ww=size*sr;
    double ycd=((double)y+0.5)*stride, xcd=((double)x+0.5)*stride;
    float ya1=(float)(ycd-hh*0.5), xa1=(float)(xcd-ww*0.5);
    float ya2=(float)(ycd+hh*0.5), xa2=(float)(xcd+ww*0.5);
    const float* d=&g.deltas[b][(size_t)i*4];
    float ha=ya2-ya1, wa=xa2-xa1;
    float yc=ya1+0.5f*ha, xc=xa1+0.5f*wa;
    float dy=d[0], dx=d[1];
    float dh=fminf(d[2],CLIPV), dw=fminf(d[3],CLIPV);
    float pcy=dy*ha+yc, pcx=dx*wa+xc;
    float ph=expf(dh)*ha, pw=expf(dw)*wa;
    float hI=iminfo[b*5+0], wI=iminfo[b*5+1];
    g.pb[b][r*4+0]=fminf(fmaxf(pcy-0.5f*ph,0.f),hI);
    g.pb[b][r*4+1]=fminf(fmaxf(pcx-0.5f*pw,0.f),wI);
    g.pb[b][r*4+2]=fminf(fmaxf(pcy+0.5f*ph,0.f),hI);
    g.pb[b][r*4+3]=fminf(fmaxf(pcx+0.5f*pw,0.f),wI);
    g.ps[b][r]=g.scores[b][i];
}

// -------- RPN NMS: inputs sorted desc -> argmax == forward pointer scan ---
__global__ void nms_level_sorted(int k,int off){
    __shared__ float y1[1000],x1[1000],y2[1000],x2[1000],s[1000];
    __shared__ int sp,sj;
    int b=blockIdx.x; int tid=threadIdx.x;
    float* ob=&g.catb[b][off*4];
    float* os=&g.cats[b][off];
    for(int i=tid;i<k;i+=256){
        y1[i]=g.pb[b][i*4+0]; x1[i]=g.pb[b][i*4+1];
        y2[i]=g.pb[b][i*4+2]; x2[i]=g.pb[b][i*4+3];
        s[i]=g.ps[b][i];
    }
    if(tid==0) sp=0;
    __syncthreads();
    for(int it=0;it<k;it++){
        if(tid==0){
            int p=sp;
            while(p<k && s[p]<=NEGF*0.5f) p++;
            sj=(p<k)?p:-1; sp=p;
        }
        __syncthreads();
        int j=sj;
        if(j<0){
            for(int r=it+tid;r<k;r+=256){
                os[r]=NEGF;
                ob[r*4+0]=0.f; ob[r*4+1]=0.f; ob[r*4+2]=0.f; ob[r*4+3]=0.f;
            }
            return;
        }
        float a1=y1[j],a2=x1[j],a3=y2[j],a4=x2[j];
        float js=s[j];
        __syncthreads();
        float aA=(a3-a1)*(a4-a2);
        for(int i=tid;i<k;i+=256){
            float yy1=fmaxf(a1,y1[i]), xx1=fmaxf(a2,x1[i]);
            float yy2=fminf(a3,y2[i]), xx2=fminf(a4,x2[i]);
            float inter=fmaxf(yy2-yy1,0.f)*fmaxf(xx2-xx1,0.f);
            float bA=(y2[i]-y1[i])*(x2[i]-x1[i]);
            float iou=inter/(aA+bA-inter+1e-8f);
            if(iou>=0.7f) s[i]=NEGF;
        }
        __syncthreads();
        if(tid==0){
            s[j]=NEGF;
            os[it]=js;
            ob[it*4+0]=a1; ob[it*4+1]=a2; ob[it*4+2]=a3; ob[it*4+3]=a4;
        }
        __syncthreads();
    }
}

// -------- general sequential NMS (det path), early-exit exact -------------
__device__ void nms_run(float* y1,float* x1,float* y2,float* x2,float* s,
                        int n,int iters,float th,float* ob,float* os){
    __shared__ float rv[256];
    __shared__ int ri[256];
    __shared__ float cb[4];
    int tid=threadIdx.x;
    for(int it=0;it<iters;it++){
        float bv=-3.0e38f; int bi=1<<30;
        for(int i=tid;i<n;i+=256){
            float v=s[i];
            if(v>bv||(v==bv&&i<bi)){ bv=v; bi=i; }
        }
        rv[tid]=bv; ri[tid]=bi; __syncthreads();
        for(int o=128;o>0;o>>=1){
            if(tid<o){
                float v=rv[tid+o]; int j=ri[tid+o];
                if(v>rv[tid]||(v==rv[tid]&&j<ri[tid])){ rv[tid]=v; ri[tid]=j; }
            }
            __syncthreads();
        }
        int j=ri[0]; float js=rv[0];
        if(js<=NEGF*0.5f){
            for(int r=it+tid;r<iters;r+=256){
                os[r]=NEGF;
                ob[r*4+0]=0.f; ob[r*4+1]=0.f; ob[r*4+2]=0.f; ob[r*4+3]=0.f;
            }
            __syncthreads();
            return;
        }
        if(tid==0){ cb[0]=y1[j]; cb[1]=x1[j]; cb[2]=y2[j]; cb[3]=x2[j]; }
        __syncthreads();
        float a1=cb[0],a2=cb[1],a3=cb[2],a4=cb[3];
        float aA=(a3-a1)*(a4-a2);
        for(int i=tid;i<n;i+=256){
            float yy1=fmaxf(a1,y1[i]), xx1=fmaxf(a2,x1[i]);
            float yy2=fminf(a3,y2[i]), xx2=fminf(a4,x2[i]);
            float inter=fmaxf(yy2-yy1,0.f)*fmaxf(xx2-xx1,0.f);
            float bA=(y2[i]-y1[i])*(x2[i]-x1[i]);
            float iou=inter/(aA+bA-inter+1e-8f);
            if(iou>=th) s[i]=NEGF;
        }
        __syncthreads();
        if(tid==0){
            s[j]=NEGF;
            os[it]=js;
            ob[it*4+0]=a1; ob[it*4+1]=a2; ob[it*4+2]=a3; ob[it*4+3]=a4;
        }
        __syncthreads();
    }
}

__global__ void build_cat_keys(){
    int b=blockIdx.x;
    for(int i=threadIdx.x;i<8192;i+=blockDim.x){
        unsigned long long key=0ull;
        if(i<4819) key=(((unsigned long long)skey(g.cats[b][i]))<<32)|(unsigned)(~(unsigned)i);
        g.sbuf[b][i]=key;
    }
}

__global__ void gather_rois(){
    int b=blockIdx.x;
    for(int r=threadIdx.x;r<1000;r+=blockDim.x){
        int i=(int)(~(unsigned)g.sbuf[b][r]);
        for(int d=0;d<4;d++) g.rois[b][r*4+d]=g.catb[b][i*4+d];
    }
}

__global__ void roialign(const float* f0,const float* f1,const float* f2,
                         const float* f3,const float* f4){
    int br=blockIdx.x; int b=br/1000;
    int c=threadIdx.x;
    const float* ro=&g.rois[b][(br%1000)*4];
    float y1=ro[0],x1=ro[1],y2=ro[2],x2=ro[3];
    float area=fmaxf((y2-y1)*(x2-x1),1e-6f);
    float lv=floorf(4.f+log2f(sqrtf(area)/224.f));
    lv=fminf(fmaxf(lv,2.f),6.f);
    int li=(int)lv-2;
    const float* fp=(li==0)?f0:(li==1)?f1:(li==2)?f2:(li==3)?f3:f4;
    int H=cH[li],W=cW[li];
    float Hf=(float)H,Wf=(float)W;
    float stride=cStrideF[li];
    const float* base=fp+(size_t)b*H*W*256;
    float* outp=&g.roifeat[(size_t)br*12544];
    for(int p=0;p<49;p++){
        int py=p/7,px=p%7;
        float uy=((float)py+0.5f)/7.f, ux=((float)px+0.5f)/7.f;
        float ys=(y1+(y2-y1)*uy)/stride-0.5f;
        float xs=(x1+(x2-x1)*ux)/stride-0.5f;
        ys=fminf(fmaxf(ys,0.f),Hf-1.f);
        xs=fminf(fmaxf(xs,0.f),Wf-1.f);
        float y0=floorf(ys),x0=floorf(xs);
        float wy=ys-y0,wx=xs-x0;
        int y0i=(int)y0,x0i=(int)x0;
        int y1i=min(y0i+1,H-1),x1i=min(x0i+1,W-1);
        const float* p00=base+((size_t)y0i*W+x0i)*256;
        const float* p01=base+((size_t)y0i*W+x1i)*256;
        const float* p10=base+((size_t)y1i*W+x0i)*256;
        const float* p11=base+((size_t)y1i*W+x1i)*256;
        float w00=(1.f-wy)*(1.f-wx), w01=(1.f-wy)*wx;
        float w10=wy*(1.f-wx), w11=wy*wx;
        outp[p*256+c]=p00[c]*w00+p01[c]*w01+p10[c]*w10+p11[c]*w11;
    }
}

__global__ void softmax91(){
    int i=blockIdx.x*blockDim.x+threadIdx.x;
    if(i>=2000) return;
    float* p=&g.clsl[(size_t)i*91];
    float mx=p[0];
    for(int c=1;c<91;c++) mx=fmaxf(mx,p[c]);
    float sm=0.f;
    float e[91];
    for(int c=0;c<91;c++){ e[c]=expf(p[c]-mx); sm+=e[c]; }
    for(int c=0;c<91;c++) p[c]=e[c]/sm;
}

__global__ void nms_det(const float* __restrict__ iminfo){
    __shared__ float y1[1000],x1[1000],y2[1000],x2[1000],s[1000];
    int blk=blockIdx.x; int b=blk/90; int c=blk%90+1;
    int tid=threadIdx.x;
    float hI=iminfo[b*5+0], wI=iminfo[b*5+1];
    for(int i=tid;i<1000;i+=256){
        const float* ro=&g.rois[b][i*4];
        float ya1=ro[0],xa1=ro[1],ya2=ro[2],xa2=ro[3];
        float ha=ya2-ya1, wa=xa2-xa1;
        float yc=ya1+0.5f*ha, xc=xa1+0.5f*wa;
        const float* d=&g.boxl[((size_t)(b*1000+i)*91+c)*4];
        float dy=d[0]/10.f, dx=d[1]/10.f;
        float dh=fminf(d[2]/5.f,CLIPV), dw=fminf(d[3]/5.f,CLIPV);
        float pcy=dy*ha+yc, pcx=dx*wa+xc;
        float ph=expf(dh)*ha, pw=expf(dw)*wa;
        y1[i]=fminf(fmaxf(pcy-0.5f*ph,0.f),hI);
        x1[i]=fminf(fmaxf(pcx-0.5f*pw,0.f),wI);
        y2[i]=fminf(fmaxf(pcy+0.5f*ph,0.f),hI);
        x2[i]=fminf(fmaxf(pcx+0.5f*pw,0.f),wI);
        float p=g.clsl[(size_t)(b*1000+i)*91+c];
        s[i]=(p>=0.05f)?p:NEGF;
    }
    __syncthreads();
    nms_run(y1,x1,y2,x2,s,1000,100,0.5f,&g.dnb[b][(c-1)*400],&g.dns[b][(c-1)*100]);
}

__global__ void build_det_keys(){
    int b=blockIdx.x;
    for(int i=threadIdx.x;i<16384;i+=blockDim.x){
        unsigned long long key=0ull;
        if(i<9000) key=(((unsigned long long)skey(g.dns[b][i]))<<32)|(unsigned)(~(unsigned)i);
        g.sbuf[b][i]=key;
    }
}

__global__ void write_out(float* out,int out_size){
    int tid=threadIdx.x;
    for(int i=tid;i<out_size;i+=256) out[i]=0.f;
    __syncthreads();
    __shared__ int cnt;
    for(int b=0;b<2;b++){
        if(tid==0) cnt=0;
        __syncthreads();
        if(tid<100){
            int r=tid;
            int idx=(int)(~(unsigned)g.sbuf[b][r]);
            float sc=g.dns[b][idx];
            bool valid=sc>0.f;
            if(valid) atomicAdd(&cnt,1);
            float cls=valid?(float)(idx/100+1):0.f;
            int ob=2+b*400+r*4;
            for(int d=0;d<4;d++){
                int o=ob+d;
                if(o<out_size) out[o]=valid?g.dnb[b][idx*4+d]:0.f;
            }
            int oc=2+800+b*100+r;
            if(oc<out_size) out[oc]=cls;
            int os=2+1000+b*100+r;
            if(os<out_size) out[os]=valid?sc:0.f;
        }
        __syncthreads();
        if(tid==0&&b<out_size) out[b]=(float)cnt;
        __syncthreads();
    }
}

extern "C" void kernel_launch(void* const* d_in,const int* in_sizes,int n_in,
                              void* d_out,int out_size){
    const float* feats[5];
    for(int i=0;i<5;i++) feats[i]=(const float*)d_in[i];
    const float* iminfo=(const float*)d_in[5];
    const float* cw =(const float*)d_in[6];
    const float* cbv=(const float*)d_in[7];
    const float* sw =(const float*)d_in[8];
    const float* sb =(const float*)d_in[9];
    const float* bw =(const float*)d_in[10];
    const float* bbv=(const float*)d_in[11];
    const float* fc1w=(const float*)d_in[12];
    const float* fc1b=(const float*)d_in[13];
    const float* fc2w=(const float*)d_in[14];
    const float* fc2b=(const float*)d_in[15];
    const float* clsw=(const float*)d_in[16];
    const float* clsb=(const float*)d_in[17];
    const float* boxw=(const float*)d_in[18];
    const float* boxb=(const float*)d_in[19];

    Scratch* gp=nullptr;
    cudaGetSymbolAddress((void**)&gp,g);

    const int TFSMEM=4*128*36*4;   // 73728 bytes
    static int attr_done=0;
    if(!attr_done){
        cudaFuncSetAttribute(gemm_tf32<1,true>,cudaFuncAttributeMaxDynamicSharedMemorySize,TFSMEM);
        cudaFuncSetAttribute(gemm_tf32<0,true>,cudaFuncAttributeMaxDynamicSharedMemorySize,TFSMEM);
        attr_done=1;
    }

    int Hs[5]={208,104,52,26,13}, Ws[5]={336,168,84,42,21};
    int offs[5]={0,1000,2000,3000,4000};

    for(int i=0;i<5;i++){
        int H=Hs[i],W=Ws[i],M=2*H*W;
        dim3 gr(2,(M+127)/128);
        gemm_tf32<1,true><<<gr,256,TFSMEM>>>(feats[i],cw,cbv,gp->h,M,256,2304,H,W);
        rpn_head_kernel<<<(M+255)/256,256>>>(gp->h,sw,sb,bw,bbv,H*W,M);
        int Nl=H*W*3;
        int k=Nl<1000?Nl:1000;
        select_topk<<<2,1024>>>(Nl,k);
        bitonic_desc<<<2,1024>>>(1024);
        rpn_decode<<<2,1024>>>(iminfo,i+2,W,k);
        nms_level_sorted<<<2,256>>>(k,offs[i]);
    }
    build_cat_keys<<<2,256>>>();
    bitonic_desc<<<2,1024>>>(8192);
    gather_rois<<<2,256>>>();

    roialign<<<2000,256>>>(feats[0],feats[1],feats[2],feats[3],feats[4]);

    gemm_tf32<0,true><<<dim3(8,16),256,TFSMEM>>>(gp->roifeat,fc1w,fc1b,gp->h1,2000,1024,12544,0,0);
    gemm_tf32<0,true><<<dim3(8,16),256,TFSMEM>>>(gp->h1,fc2w,fc2b,gp->h2,2000,1024,1024,0,0);
    gemm128<0,false,false><<<dim3(1,16),256>>>(gp->h2,clsw,clsb,gp->clsl,2000,91,1024,0,0);
    gemm128<0,true,false><<<dim3(3,16),256>>>(gp->h2,boxw,boxb,gp->boxl,2000,364,1024,0,0);

    softmax91<<<8,256>>>();
    nms_det<<<180,256>>>(iminfo);
    build_det_keys<<<2,256>>>();
    bitonic_desc<<<2,1024>>>(16384);
    write_out<<<1,256>>>((float*)d_out,out_size);
}

// round 9
// speedup vs baseline: 3.6210x; 1.8110x over previous
#include <cuda_runtime.h>
#include <math.h>
#include <stddef.h>

#define NEGF (-1.0e9f)
#define CLIPV 4.135166556742356f

__device__ __forceinline__ unsigned skey(float s){
    unsigned u = __float_as_uint(s);
    return (u & 0x80000000u) ? ~u : (u | 0x80000000u);
}
__device__ __forceinline__ unsigned f2tf32(float x){
    unsigned r; asm("cvt.rna.tf32.f32 %0, %1;" : "=r"(r) : "f"(x)); return r;
}
__device__ __forceinline__ float tf32f(float x){ return __uint_as_float(f2tf32(x)); }

struct __align__(256) Scratch {
    float h[47663616];               // per-level conv outputs (row offsets cHOff)
    float scores[2][279280];         // per-level at cSOff
    float deltas[2][1117120];        // per-level at cSOff*4
    unsigned histL[10][65536];
    int tiebufL[10][4096];
    int tiecntL[10];
    int selcntL[10];
    unsigned long long sbufL[10][1024];
    unsigned long long sbuf[2][16384];
    float pbL[10][4000];
    float psL[10][1000];
    float catb[2][19280];
    float cats[2][4820];
    float rois[2][4000];
    float roifeat[25088000];
    float h1[2048000];
    float h2[2048000];
    float clsl[182000];
    float boxl[728000];
    float dns[2][9000];
    float dnb[2][36000];
};
__device__ Scratch g;

__constant__ int cH[5]={208,104,52,26,13};
__constant__ int cW[5]={336,168,84,42,21};
__constant__ float cStrideF[5]={4.f,8.f,16.f,32.f,64.f};
__constant__ int cNl5[5]={209664,52416,13104,3276,819};
__constant__ int cK5[5]={1000,1000,1000,1000,819};
__constant__ int cSOff[5]={0,209664,262080,275184,278460};
__constant__ int cHOff[5]={0,139776,174720,183456,185640};  // row offsets
__constant__ int cOffCat[5]={0,1000,2000,3000,4000};

// ================= TF32 tensor-core GEMM 128x128x32 =======================
#define TFPAD 36
#define TFSTG (128*TFPAD)
template<int MODE,bool RELU>
__global__ void gemm_tf32(const float* __restrict__ A,const float* __restrict__ Bw,
                          const float* __restrict__ bias,float* __restrict__ C,
                          int M,int N,int K,int H,int W){
    extern __shared__ float sm[];
    float* Asm=sm;
    float* Bsm=sm+2*TFSTG;
    int tid=threadIdx.x;
    int bm=blockIdx.y*128, bn=blockIdx.x*128;
    int wid=tid>>5, lane=tid&31;
    int wm=wid&3, wn=wid>>2;
    int lr=lane>>2, lc=lane&3;

    float acc[2][8][4];
#pragma unroll
    for(int i=0;i<2;i++)
#pragma unroll
        for(int j=0;j<8;j++)
#pragma unroll
            for(int q=0;q<4;q++) acc[i][j][q]=0.f;

    int arow=tid>>1, ahalf=tid&1;
    int m=bm+arow;
    int ab=0,ay=0,ax=0;
    if(MODE==1){
        int HW=H*W; int mm=(m<M)?m:0;
        ab=mm/HW; int rem=mm-ab*HW; ay=rem/W; ax=rem-ay*W;
    }
    int bk=tid>>3, bn0=(tid&7)*16;

    float4 av[4], bvv[4];
    auto loadG=[&](int k0){
#pragma unroll
        for(int c=0;c<4;c++) av[c]=make_float4(0.f,0.f,0.f,0.f);
        if(m<M){
            if(MODE==0){
                const float* p=A+(size_t)m*K+k0+ahalf*16;
#pragma unroll
                for(int c=0;c<4;c++) av[c]=*(const float4*)(p+c*4);
            }else{
                int r=k0>>8;
                int ky=r/3, kx=r-ky*3;
                int yy=ay+ky-1, xx=ax+kx-1;
                if(yy>=0&&yy<H&&xx>=0&&xx<W){
                    const float* p=A+(((size_t)ab*H+yy)*W+xx)*256+(k0&255)+ahalf*16;
#pragma unroll
                    for(int c=0;c<4;c++) av[c]=*(const float4*)(p+c*4);
                }
            }
        }
        const float* q=Bw+(size_t)(k0+bk)*N+bn+bn0;
#pragma unroll
        for(int c=0;c<4;c++) bvv[c]=*(const float4*)(q+c*4);
    };
    auto storeS=[&](int stg){
        float* Ad=Asm+stg*TFSTG+arow*TFPAD+ahalf*16;
#pragma unroll
        for(int c=0;c<4;c++){
            float4 v=av[c];
            v.x=tf32f(v.x); v.y=tf32f(v.y); v.z=tf32f(v.z); v.w=tf32f(v.w);
            *(float4*)(Ad+c*4)=v;
        }
        float* Bd=Bsm+stg*TFSTG+bk;
#pragma unroll
        for(int c=0;c<4;c++){
            Bd[(bn0+c*4+0)*TFPAD]=tf32f(bvv[c].x);
            Bd[(bn0+c*4+1)*TFPAD]=tf32f(bvv[c].y);
            Bd[(bn0+c*4+2)*TFPAD]=tf32f(bvv[c].z);
            Bd[(bn0+c*4+3)*TFPAD]=tf32f(bvv[c].w);
        }
    };

    int T=K>>5;
    loadG(0); storeS(0);
    __syncthreads();
    for(int t=0;t<T;t++){
        int cur=t&1, nxt=cur^1;
        if(t+1<T) loadG((t+1)*32);
        const float* Ac=Asm+cur*TFSTG;
        const float* Bc=Bsm+cur*TFSTG;
#pragma unroll
        for(int ks=0;ks<4;ks++){
            int kb=ks*8;
            unsigned af[2][4];
#pragma unroll
            for(int mt=0;mt<2;mt++){
                int r0=wm*32+mt*16+lr;
                af[mt][0]=__float_as_uint(Ac[r0*TFPAD+kb+lc]);
                af[mt][1]=__float_as_uint(Ac[(r0+8)*TFPAD+kb+lc]);
                af[mt][2]=__float_as_uint(Ac[r0*TFPAD+kb+lc+4]);
                af[mt][3]=__float_as_uint(Ac[(r0+8)*TFPAD+kb+lc+4]);
            }
#pragma unroll
            for(int nt=0;nt<8;nt++){
                int cb=wn*64+nt*8+lr;
                unsigned b0=__float_as_uint(Bc[cb*TFPAD+kb+lc]);
                unsigned b1=__float_as_uint(Bc[cb*TFPAD+kb+lc+4]);
#pragma unroll
                for(int mt=0;mt<2;mt++){
                    asm volatile(
                      "mma.sync.aligned.m16n8k8.row.col.f32.tf32.tf32.f32 "
                      "{%0,%1,%2,%3}, {%4,%5,%6,%7}, {%8,%9}, {%0,%1,%2,%3};\n"
                      : "+f"(acc[mt][nt][0]),"+f"(acc[mt][nt][1]),
                        "+f"(acc[mt][nt][2]),"+f"(acc[mt][nt][3])
                      : "r"(af[mt][0]),"r"(af[mt][1]),"r"(af[mt][2]),"r"(af[mt][3]),
                        "r"(b0),"r"(b1));
                }
            }
        }
        if(t+1<T) storeS(nxt);
        __syncthreads();
    }
#pragma unroll
    for(int mt=0;mt<2;mt++){
#pragma unroll
        for(int nt=0;nt<8;nt++){
            int r0=bm+wm*32+mt*16+lr;
            int c0=bn+wn*64+nt*8+lc*2;
            float b0=bias[c0], b1=bias[c0+1];
            float v0=acc[mt][nt][0]+b0, v1=acc[mt][nt][1]+b1;
            float v2=acc[mt][nt][2]+b0, v3=acc[mt][nt][3]+b1;
            if(RELU){ v0=fmaxf(v0,0.f); v1=fmaxf(v1,0.f); v2=fmaxf(v2,0.f); v3=fmaxf(v3,0.f); }
            if(r0<M){ C[(size_t)r0*N+c0]=v0; C[(size_t)r0*N+c0+1]=v1; }
            if(r0+8<M){ C[(size_t)(r0+8)*N+c0]=v2; C[(size_t)(r0+8)*N+c0+1]=v3; }
        }
    }
}

// ---------------- fp32 SGEMM (small heads), double-buffered ---------------
template<int MODE,bool VECB,bool RELU>
__global__ void gemm128(const float* __restrict__ A,const float* __restrict__ Bw,
                        const float* __restrict__ bias,float* __restrict__ C,
                        int M,int N,int K,int H,int W){
    __shared__ float As[2][8][128];
    __shared__ float Bs[2][8][132];
    int tid=threadIdx.x;
    int bm=blockIdx.y*128, bn=blockIdx.x*128;
    int tx=tid&15, ty=tid>>4;
    float acc[8][8];
#pragma unroll
    for(int i=0;i<8;i++)
#pragma unroll
        for(int j=0;j<8;j++) acc[i][j]=0.f;
    int ar=tid>>1, aco=(tid&1)*4;
    int brow=tid>>5, bcol=(tid&31)*4;
    int m=bm+ar;
    auto loadA=[&](int k0)->float4{
        float4 r=make_float4(0.f,0.f,0.f,0.f);
        if(m<M) r=*(const float4*)(A+(size_t)m*K+k0+aco);
        return r;
    };
    auto loadB=[&](int k0)->float4{
        int kk=k0+brow; int n=bn+bcol;
        float4 r=make_float4(0.f,0.f,0.f,0.f);
        if(VECB&&(n+3)<N){
            r=*(const float4*)(Bw+(size_t)kk*N+n);
        }else{
            if(n+0<N) r.x=Bw[(size_t)kk*N+n+0];
            if(n+1<N) r.y=Bw[(size_t)kk*N+n+1];
            if(n+2<N) r.z=Bw[(size_t)kk*N+n+2];
            if(n+3<N) r.w=Bw[(size_t)kk*N+n+3];
        }
        return r;
    };
    int T=K>>3;
    float4 av=loadA(0), bv=loadB(0);
    As[0][aco+0][ar]=av.x; As[0][aco+1][ar]=av.y; As[0][aco+2][ar]=av.z; As[0][aco+3][ar]=av.w;
    *(float4*)&Bs[0][brow][bcol]=bv;
    __syncthreads();
    for(int t=0;t<T;t++){
        int cur=t&1, nxt=cur^1;
        if(t+1<T){ av=loadA((t+1)*8); bv=loadB((t+1)*8); }
#pragma unroll
        for(int kk=0;kk<8;kk++){
            float af[8],bf[8];
            *(float4*)&af[0]=*(const float4*)&As[cur][kk][ty*8];
            *(float4*)&af[4]=*(const float4*)&As[cur][kk][ty*8+4];
            *(float4*)&bf[0]=*(const float4*)&Bs[cur][kk][tx*8];
            *(float4*)&bf[4]=*(const float4*)&Bs[cur][kk][tx*8+4];
#pragma unroll
            for(int i=0;i<8;i++)
#pragma unroll
                for(int j=0;j<8;j++) acc[i][j]+=af[i]*bf[j];
        }
        if(t+1<T){
            As[nxt][aco+0][ar]=av.x; As[nxt][aco+1][ar]=av.y;
            As[nxt][aco+2][ar]=av.z; As[nxt][aco+3][ar]=av.w;
            *(float4*)&Bs[nxt][brow][bcol]=bv;
        }
        __syncthreads();
    }
#pragma unroll
    for(int i=0;i<8;i++){
        int mm=bm+ty*8+i;
        if(mm>=M) continue;
#pragma unroll
        for(int j=0;j<8;j++){
            int nn=bn+tx*8+j;
            if(nn>=N) continue;
            float v=acc[i][j]+bias[nn];
            if(RELU) v=fmaxf(v,0.f);
            C[(size_t)mm*N+nn]=v;
        }
    }
}

// tiny init node so the ncu capture slot (-s 5) lands on conv-l2
__global__ void init_kernel(){
    int i=threadIdx.x;
    if(i<10){ g.tiecntL[i]=0; g.selcntL[i]=0; }
}

// ---------------- fused RPN head over all levels --------------------------
__global__ void rpn_head_all(const float* __restrict__ sw,const float* __restrict__ sb,
    const float* __restrict__ bw,const float* __restrict__ bb){
    __shared__ float wsm[256][16];
    __shared__ float bsm[16];
    int tid=threadIdx.x;
    int lvl=blockIdx.y;
    int H=cH[lvl],W=cW[lvl];
    int HW=H*W, Btot=2*HW;
    for(int i=tid;i<256*16;i+=blockDim.x){
        int c=i>>4, j=i&15;
        float v=0.f;
        if(j<3) v=sw[c*3+j];
        else if(j<15) v=bw[c*12+(j-3)];
        wsm[c][j]=v;
    }
    if(tid<16) bsm[tid]=(tid<3)?sb[tid]:((tid<15)?bb[tid-3]:0.f);
    __syncthreads();
    int m=blockIdx.x*blockDim.x+tid;
    if(m>=Btot) return;
    int b=m/HW, pix=m-b*HW;
    const float* hr=g.h+((size_t)cHOff[lvl]+m)*256;
    int soff=cSOff[lvl];
    float acc[15];
#pragma unroll
    for(int j=0;j<15;j++) acc[j]=0.f;
    for(int c=0;c<256;c+=4){
        float4 v=*(const float4*)(hr+c);
#pragma unroll
        for(int j=0;j<15;j++)
            acc[j]+=v.x*wsm[c][j]+v.y*wsm[c+1][j]+v.z*wsm[c+2][j]+v.w*wsm[c+3][j];
    }
    for(int a=0;a<3;a++){
        float lg=acc[a]+bsm[a];
        g.scores[b][soff+pix*3+a]=1.f/(1.f+expf(-lg));
        for(int d=0;d<4;d++)
            g.deltas[b][(size_t)(soff+pix*3+a)*4+d]=acc[3+a*4+d]+bsm[3+a*4+d];
    }
}

// ------------- fused exact stable top-k: grid = 10 instances --------------
__global__ void select_topk_all(){
    int inst=blockIdx.x;
    int lvl=inst>>1, b=inst&1;
    int Nl=cNl5[lvl], k=cK5[lvl];
    const float* s=&g.scores[b][cSOff[lvl]];
    unsigned* hist=g.histL[inst];
    int* tiebuf=g.tiebufL[inst];
    unsigned long long* sbuf=g.sbufL[inst];
    int tid=threadIdx.x;
    __shared__ unsigned csum[1024];
    __shared__ int s_t,s_above,s_u,s_above2;
    if(tid==0){ g.selcntL[inst]=0; g.tiecntL[inst]=0; }
    for(int i=tid;i<65536;i+=1024) __stcg(&hist[i],0u);
    __syncthreads();
    for(int i=tid;i<Nl;i+=1024) atomicAdd(&hist[skey(s[i])>>16],1u);
    __syncthreads();
    {
        unsigned own=0; int base=65535-tid*64;
        for(int q=0;q<64;q++) own+=__ldcg(&hist[base-q]);
        csum[tid]=own; __syncthreads();
        for(int off=1;off<1024;off<<=1){
            unsigned v=csum[tid]; unsigned add=(tid>=off)?csum[tid-off]:0u; __syncthreads();
            csum[tid]=v+add; __syncthreads();
        }
        unsigned excl=csum[tid]-own;
        if(excl<(unsigned)k&&csum[tid]>=(unsigned)k){
            unsigned cum=excl;
            for(int q=0;q<64;q++){
                unsigned c=__ldcg(&hist[base-q]);
                if(cum+c>=(unsigned)k){ s_t=base-q; s_above=(int)cum; break; }
                cum+=c;
            }
        }
        __syncthreads();
    }
    int t=s_t, above=s_above;
    for(int i=tid;i<65536;i+=1024) __stcg(&hist[i],0u);
    __syncthreads();
    for(int i=tid;i<Nl;i+=1024){
        unsigned key=skey(s[i]);
        if((int)(key>>16)==t) atomicAdd(&hist[key&0xFFFFu],1u);
    }
    __syncthreads();
    int need=k-above;
    {
        unsigned own=0; int base=65535-tid*64;
        for(int q=0;q<64;q++) own+=__ldcg(&hist[base-q]);
        csum[tid]=own; __syncthreads();
        for(int off=1;off<1024;off<<=1){
            unsigned v=csum[tid]; unsigned add=(tid>=off)?csum[tid-off]:0u; __syncthreads();
            csum[tid]=v+add; __syncthreads();
        }
        unsigned excl=csum[tid]-own;
        if(excl<(unsigned)need&&csum[tid]>=(unsigned)need){
            unsigned cum=excl;
            for(int q=0;q<64;q++){
                unsigned c=__ldcg(&hist[base-q]);
                if(cum+c>=(unsigned)need){ s_u=base-q; s_above2=(int)cum; break; }
                cum+=c;
            }
        }
        __syncthreads();
    }
    int u=s_u, above2=s_above2;
    unsigned T=(((unsigned)t)<<16)|(unsigned)u;
    for(int i=tid;i<Nl;i+=1024){
        unsigned key=skey(s[i]);
        if(key>T){
            int pos=atomicAdd(&g.selcntL[inst],1);
            sbuf[pos]=(((unsigned long long)key)<<32)|(unsigned)(~(unsigned)i);
        }else if(key==T){
            int p=atomicAdd(&g.tiecntL[inst],1);
            if(p<4096) tiebuf[p]=i;
        }
    }
    __syncthreads();
    int ct=g.tiecntL[inst]; if(ct>4096) ct=4096;
    int mtake=need-above2;
    int pos0=above+above2;
    for(int ti=tid;ti<ct;ti+=1024){
        int myi=tiebuf[ti];
        int rank=0;
        for(int q=0;q<ct;q++) rank+=(tiebuf[q]<myi);
        if(rank<mtake)
            sbuf[pos0+rank]=(((unsigned long long)T)<<32)|(unsigned)(~(unsigned)myi);
    }
    __syncthreads();
    if(tid>=k&&tid<1024) sbuf[tid]=0ull;
}

// fused bitonic over the 10 level-instances (n=1024 each)
__global__ void bitonic_lvl(){
    unsigned long long* a=g.sbufL[blockIdx.x];
    const int n=1024;
    for(int k=2;k<=n;k<<=1){
        for(int j=k>>1;j>0;j>>=1){
            for(int i=threadIdx.x;i<n;i+=blockDim.x){
                int l=i^j;
                if(l>i){
                    unsigned long long x=a[i],y=a[l];
                    bool sw=((i&k)==0)?(x<y):(x>y);
                    if(sw){ a[i]=y; a[l]=x; }
                }
            }
            __syncthreads();
        }
    }
}

__global__ void bitonic_desc(int n){
    unsigned long long* a=g.sbuf[blockIdx.x];
    for(int k=2;k<=n;k<<=1){
        for(int j=k>>1;j>0;j>>=1){
            for(int i=threadIdx.x;i<n;i+=blockDim.x){
                int l=i^j;
                if(l>i){
                    unsigned long long x=a[i],y=a[l];
                    bool sw=((i&k)==0)?(x<y):(x>y);
                    if(sw){ a[i]=y; a[l]=x; }
                }
            }
            __syncthreads();
        }
    }
}

// fused decode (grid 10, 1024 thr)
__global__ void rpn_decode_all(const float* __restrict__ iminfo){
    int inst=blockIdx.x;
    int lvl=inst>>1, b=inst&1;
    int k=cK5[lvl], W=cW[lvl];
    int r=threadIdx.x;
    if(r>=k) return;
    unsigned long long key=g.sbufL[inst][r];
    int i=(int)(~(unsigned)key);
    int a=i%3; int pix=i/3; int x=pix%W; int y=pix/W;
    double stride=(double)(1<<(lvl+2));
    double size=8.0*stride;
    double rr=(a==0)?1.0:((a==1)?0.5:2.0);
    double sr=sqrt(rr);
    double hh=size/sr, ww=size*sr;
    double ycd=((double)y+0.5)*stride, xcd=((double)x+0.5)*stride;
    float ya1=(float)(ycd-hh*0.5), xa1=(float)(xcd-ww*0.5);
    float ya2=(float)(ycd+hh*0.5), xa2=(float)(xcd+ww*0.5);
    const float* d=&g.deltas[b][(size_t)(cSOff[lvl]+i)*4];
    float ha=ya2-ya1, wa=xa2-xa1;
    float yc=ya1+0.5f*ha, xc=xa1+0.5f*wa;
    float dy=d[0], dx=d[1];
    float dh=fminf(d[2],CLIPV), dw=fminf(d[3],CLIPV);
    float pcy=dy*ha+yc, pcx=dx*wa+xc;
    float ph=expf(dh)*ha, pw=expf(dw)*wa;
    float hI=iminfo[b*5+0], wI=iminfo[b*5+1];
    g.pbL[inst][r*4+0]=fminf(fmaxf(pcy-0.5f*ph,0.f),hI);
    g.pbL[inst][r*4+1]=fminf(fmaxf(pcx-0.5f*pw,0.f),wI);
    g.pbL[inst][r*4+2]=fminf(fmaxf(pcy+0.5f*ph,0.f),hI);
    g.pbL[inst][r*4+3]=fminf(fmaxf(pcx+0.5f*pw,0.f),wI);
    g.psL[inst][r]=g.scores[b][cSOff[lvl]+i];
}

// fused sorted NMS (grid 10, 256 thr)
__global__ void nms_level_all(){
    __shared__ float y1[1000],x1[1000],y2[1000],x2[1000],s[1000];
    __shared__ int sp,sj;
    int inst=blockIdx.x;
    int lvl=inst>>1, b=inst&1;
    int k=cK5[lvl], off=cOffCat[lvl];
    int tid=threadIdx.x;
    float* ob=&g.catb[b][off*4];
    float* os=&g.cats[b][off];
    for(int i=tid;i<k;i+=256){
        y1[i]=g.pbL[inst][i*4+0]; x1[i]=g.pbL[inst][i*4+1];
        y2[i]=g.pbL[inst][i*4+2]; x2[i]=g.pbL[inst][i*4+3];
        s[i]=g.psL[inst][i];
    }
    if(tid==0) sp=0;
    __syncthreads();
    for(int it=0;it<k;it++){
        if(tid==0){
            int p=sp;
            while(p<k && s[p]<=NEGF*0.5f) p++;
            sj=(p<k)?p:-1; sp=p;
        }
        __syncthreads();
        int j=sj;
        if(j<0){
            for(int r=it+tid;r<k;r+=256){
                os[r]=NEGF;
                ob[r*4+0]=0.f; ob[r*4+1]=0.f; ob[r*4+2]=0.f; ob[r*4+3]=0.f;
            }
            return;
        }
        float a1=y1[j],a2=x1[j],a3=y2[j],a4=x2[j];
        float js=s[j];
        __syncthreads();
        float aA=(a3-a1)*(a4-a2);
        for(int i=tid;i<k;i+=256){
            float yy1=fmaxf(a1,y1[i]), xx1=fmaxf(a2,x1[i]);
            float yy2=fminf(a3,y2[i]), xx2=fminf(a4,x2[i]);
            float inter=fmaxf(yy2-yy1,0.f)*fmaxf(xx2-xx1,0.f);
            float bA=(y2[i]-y1[i])*(x2[i]-x1[i]);
            float iou=inter/(aA+bA-inter+1e-8f);
            if(iou>=0.7f) s[i]=NEGF;
        }
        __syncthreads();
        if(tid==0){
            s[j]=NEGF;
            os[it]=js;
            ob[it*4+0]=a1; ob[it*4+1]=a2; ob[it*4+2]=a3; ob[it*4+3]=a4;
        }
        __syncthreads();
    }
}

// -------- general sequential NMS (det path), early-exit exact -------------
__device__ void nms_run(float* y1,float* x1,float* y2,float* x2,float* s,
                        int n,int iters,float th,float* ob,float* os){
    __shared__ float rv[256];
    __shared__ int ri[256];
    __shared__ float cb[4];
    int tid=threadIdx.x;
    for(int it=0;it<iters;it++){
        float bv=-3.0e38f; int bi=1<<30;
        for(int i=tid;i<n;i+=256){
            float v=s[i];
            if(v>bv||(v==bv&&i<bi)){ bv=v; bi=i; }
        }
        rv[tid]=bv; ri[tid]=bi; __syncthreads();
        for(int o=128;o>0;o>>=1){
            if(tid<o){
                float v=rv[tid+o]; int j=ri[tid+o];
                if(v>rv[tid]||(v==rv[tid]&&j<ri[tid])){ rv[tid]=v; ri[tid]=j; }
            }
            __syncthreads();
        }
        int j=ri[0]; float js=rv[0];
        if(js<=NEGF*0.5f){
            for(int r=it+tid;r<iters;r+=256){
                os[r]=NEGF;
                ob[r*4+0]=0.f; ob[r*4+1]=0.f; ob[r*4+2]=0.f; ob[r*4+3]=0.f;
            }
            __syncthreads();
            return;
        }
        if(tid==0){ cb[0]=y1[j]; cb[1]=x1[j]; cb[2]=y2[j]; cb[3]=x2[j]; }
        __syncthreads();
        float a1=cb[0],a2=cb[1],a3=cb[2],a4=cb[3];
        float aA=(a3-a1)*(a4-a2);
        for(int i=tid;i<n;i+=256){
            float yy1=fmaxf(a1,y1[i]), xx1=fmaxf(a2,x1[i]);
            float yy2=fminf(a3,y2[i]), xx2=fminf(a4,x2[i]);
            float inter=fmaxf(yy2-yy1,0.f)*fmaxf(xx2-xx1,0.f);
            float bA=(y2[i]-y1[i])*(x2[i]-x1[i]);
            float iou=inter/(aA+bA-inter+1e-8f);
            if(iou>=th) s[i]=NEGF;
        }
        __syncthreads();
        if(tid==0){
            s[j]=NEGF;
            os[it]=js;
            ob[it*4+0]=a1; ob[it*4+1]=a2; ob[it*4+2]=a3; ob[it*4+3]=a4;
        }
        __syncthreads();
    }
}

__global__ void build_cat_keys(){
    int b=blockIdx.x;
    for(int i=threadIdx.x;i<8192;i+=blockDim.x){
        unsigned long long key=0ull;
        if(i<4819) key=(((unsigned long long)skey(g.cats[b][i]))<<32)|(unsigned)(~(unsigned)i);
        g.sbuf[b][i]=key;
    }
}

__global__ void gather_rois(){
    int b=blockIdx.x;
    for(int r=threadIdx.x;r<1000;r+=blockDim.x){
        int i=(int)(~(unsigned)g.sbuf[b][r]);
        for(int d=0;d<4;d++) g.rois[b][r*4+d]=g.catb[b][i*4+d];
    }
}

__global__ void roialign(const float* f0,const float* f1,const float* f2,
                         const float* f3,const float* f4){
    int br=blockIdx.x; int b=br/1000;
    int c=threadIdx.x;
    const float* ro=&g.rois[b][(br%1000)*4];
    float y1=ro[0],x1=ro[1],y2=ro[2],x2=ro[3];
    float area=fmaxf((y2-y1)*(x2-x1),1e-6f);
    float lv=floorf(4.f+log2f(sqrtf(area)/224.f));
    lv=fminf(fmaxf(lv,2.f),6.f);
    int li=(int)lv-2;
    const float* fp=(li==0)?f0:(li==1)?f1:(li==2)?f2:(li==3)?f3:f4;
    int H=cH[li],W=cW[li];
    float Hf=(float)H,Wf=(float)W;
    float stride=cStrideF[li];
    const float* base=fp+(size_t)b*H*W*256;
    float* outp=&g.roifeat[(size_t)br*12544];
    for(int p=0;p<49;p++){
        int py=p/7,px=p%7;
        float uy=((float)py+0.5f)/7.f, ux=((float)px+0.5f)/7.f;
        float ys=(y1+(y2-y1)*uy)/stride-0.5f;
        float xs=(x1+(x2-x1)*ux)/stride-0.5f;
        ys=fminf(fmaxf(ys,0.f),Hf-1.f);
        xs=fminf(fmaxf(xs,0.f),Wf-1.f);
        float y0=floorf(ys),x0=floorf(xs);
        float wy=ys-y0,wx=xs-x0;
        int y0i=(int)y0,x0i=(int)x0;
        int y1i=min(y0i+1,H-1),x1i=min(x0i+1,W-1);
        const float* p00=base+((size_t)y0i*W+x0i)*256;
        const float* p01=base+((size_t)y0i*W+x1i)*256;
        const float* p10=base+((size_t)y1i*W+x0i)*256;
        const float* p11=base+((size_t)y1i*W+x1i)*256;
        float w00=(1.f-wy)*(1.f-wx), w01=(1.f-wy)*wx;
        float w10=wy*(1.f-wx), w11=wy*wx;
        outp[p*256+c]=p00[c]*w00+p01[c]*w01+p10[c]*w10+p11[c]*w11;
    }
}

__global__ void softmax91(){
    int i=blockIdx.x*blockDim.x+threadIdx.x;
    if(i>=2000) return;
    float* p=&g.clsl[(size_t)i*91];
    float mx=p[0];
    for(int c=1;c<91;c++) mx=fmaxf(mx,p[c]);
    float sm=0.f;
    float e[91];
    for(int c=0;c<91;c++){ e[c]=expf(p[c]-mx); sm+=e[c]; }
    for(int c=0;c<91;c++) p[c]=e[c]/sm;
}

__global__ void nms_det(const float* __restrict__ iminfo){
    __shared__ float y1[1000],x1[1000],y2[1000],x2[1000],s[1000];
    int blk=blockIdx.x; int b=blk/90; int c=blk%90+1;
    int tid=threadIdx.x;
    float hI=iminfo[b*5+0], wI=iminfo[b*5+1];
    for(int i=tid;i<1000;i+=256){
        const float* ro=&g.rois[b][i*4];
        float ya1=ro[0],xa1=ro[1],ya2=ro[2],xa2=ro[3];
        float ha=ya2-ya1, wa=xa2-xa1;
        float yc=ya1+0.5f*ha, xc=xa1+0.5f*wa;
        const float* d=&g.boxl[((size_t)(b*1000+i)*91+c)*4];
        float dy=d[0]/10.f, dx=d[1]/10.f;
        float dh=fminf(d[2]/5.f,CLIPV), dw=fminf(d[3]/5.f,CLIPV);
        float pcy=dy*ha+yc, pcx=dx*wa+xc;
        float ph=expf(dh)*ha, pw=expf(dw)*wa;
        y1[i]=fminf(fmaxf(pcy-0.5f*ph,0.f),hI);
        x1[i]=fminf(fmaxf(pcx-0.5f*pw,0.f),wI);
        y2[i]=fminf(fmaxf(pcy+0.5f*ph,0.f),hI);
        x2[i]=fminf(fmaxf(pcx+0.5f*pw,0.f),wI);
        float p=g.clsl[(size_t)(b*1000+i)*91+c];
        s[i]=(p>=0.05f)?p:NEGF;
    }
    __syncthreads();
    nms_run(y1,x1,y2,x2,s,1000,100,0.5f,&g.dnb[b][(c-1)*400],&g.dns[b][(c-1)*100]);
}

__global__ void build_det_keys(){
    int b=blockIdx.x;
    for(int i=threadIdx.x;i<16384;i+=blockDim.x){
        unsigned long long key=0ull;
        if(i<9000) key=(((unsigned long long)skey(g.dns[b][i]))<<32)|(unsigned)(~(unsigned)i);
        g.sbuf[b][i]=key;
    }
}

__global__ void write_out(float* out,int out_size){
    int tid=threadIdx.x;
    for(int i=tid;i<out_size;i+=256) out[i]=0.f;
    __syncthreads();
    __shared__ int cnt;
    for(int b=0;b<2;b++){
        if(tid==0) cnt=0;
        __syncthreads();
        if(tid<100){
            int r=tid;
            int idx=(int)(~(unsigned)g.sbuf[b][r]);
            float sc=g.dns[b][idx];
            bool valid=sc>0.f;
            if(valid) atomicAdd(&cnt,1);
            float cls=valid?(float)(idx/100+1):0.f;
            int ob=2+b*400+r*4;
            for(int d=0;d<4;d++){
                int o=ob+d;
                if(o<out_size) out[o]=valid?g.dnb[b][idx*4+d]:0.f;
            }
            int oc=2+800+b*100+r;
            if(oc<out_size) out[oc]=cls;
            int os=2+1000+b*100+r;
            if(os<out_size) out[os]=valid?sc:0.f;
        }
        __syncthreads();
        if(tid==0&&b<out_size) out[b]=(float)cnt;
        __syncthreads();
    }
}

extern "C" void kernel_launch(void* const* d_in,const int* in_sizes,int n_in,
                              void* d_out,int out_size){
    const float* feats[5];
    for(int i=0;i<5;i++) feats[i]=(const float*)d_in[i];
    const float* iminfo=(const float*)d_in[5];
    const float* cw =(const float*)d_in[6];
    const float* cbv=(const float*)d_in[7];
    const float* sw =(const float*)d_in[8];
    const float* sb =(const float*)d_in[9];
    const float* bw =(const float*)d_in[10];
    const float* bbv=(const float*)d_in[11];
    const float* fc1w=(const float*)d_in[12];
    const float* fc1b=(const float*)d_in[13];
    const float* fc2w=(const float*)d_in[14];
    const float* fc2b=(const float*)d_in[15];
    const float* clsw=(const float*)d_in[16];
    const float* clsb=(const float*)d_in[17];
    const float* boxw=(const float*)d_in[18];
    const float* boxb=(const float*)d_in[19];

    Scratch* gp=nullptr;
    cudaGetSymbolAddress((void**)&gp,g);

    const int TFSMEM=4*128*36*4;
    static int attr_done=0;
    if(!attr_done){
        cudaFuncSetAttribute(gemm_tf32<1,true>,cudaFuncAttributeMaxDynamicSharedMemorySize,TFSMEM);
        cudaFuncSetAttribute(gemm_tf32<0,true>,cudaFuncAttributeMaxDynamicSharedMemorySize,TFSMEM);
        attr_done=1;
    }

    int Hs[5]={208,104,52,26,13}, Ws[5]={336,168,84,42,21};
    int hOff[5]={0,139776,174720,183456,185640};

    init_kernel<<<1,32>>>();                               // idx 0
    for(int i=4;i>=0;i--){                                  // idx 1..5 (l2 = idx 5)
        int H=Hs[i],W=Ws[i],M=2*H*W;
        dim3 gr(2,(M+127)/128);
        gemm_tf32<1,true><<<gr,256,TFSMEM>>>(feats[i],cw,cbv,gp->h+(size_t)hOff[i]*256,M,256,2304,H,W);
    }
    rpn_head_all<<<dim3(546,5),256>>>(sw,sb,bw,bbv);
    select_topk_all<<<10,1024>>>();
    bitonic_lvl<<<10,1024>>>();
    rpn_decode_all<<<10,1024>>>(iminfo);
    nms_level_all<<<10,256>>>();

    build_cat_keys<<<2,256>>>();
    bitonic_desc<<<2,1024>>>(8192);
    gather_rois<<<2,256>>>();

    roialign<<<2000,256>>>(feats[0],feats[1],feats[2],feats[3],feats[4]);

    gemm_tf32<0,true><<<dim3(8,16),256,TFSMEM>>>(gp->roifeat,fc1w,fc1b,gp->h1,2000,1024,12544,0,0);
    gemm_tf32<0,true><<<dim3(8,16),256,TFSMEM>>>(gp->h1,fc2w,fc2b,gp->h2,2000,1024,1024,0,0);
    gemm128<0,false,false><<<dim3(1,16),256>>>(gp->h2,clsw,clsb,gp->clsl,2000,91,1024,0,0);
    gemm128<0,true,false><<<dim3(3,16),256>>>(gp->h2,boxw,boxb,gp->boxl,2000,364,1024,0,0);

    softmax91<<<8,256>>>();
    nms_det<<<180,256>>>(iminfo);
    build_det_keys<<<2,256>>>();
    bitonic_desc<<<2,1024>>>(16384);
    write_out<<<1,256>>>((float*)d_out,out_size);
}

// round 10
// speedup vs baseline: 4.8861x; 1.3494x over previous
#include <cuda_runtime.h>
#include <cuda_bf16.h>
#include <math.h>
#include <stddef.h>

#define NEGF (-1.0e9f)
#define CLIPV 4.135166556742356f

__device__ __forceinline__ unsigned skey(float s){
    unsigned u = __float_as_uint(s);
    return (u & 0x80000000u) ? ~u : (u | 0x80000000u);
}
__device__ __forceinline__ unsigned packbf(float e,float o){
    __nv_bfloat162 h=__floats2bfloat162_rn(e,o);   // x=e (lo), y=o (hi)
    return *(unsigned*)&h;
}

struct __align__(256) Scratch {
    float h[47663616];
    float scores[2][279280];
    float deltas[2][1117120];
    unsigned histL[10][65536];
    int tiebufL[10][4096];
    int tiecntL[10];
    int selcntL[10];
    unsigned long long sbufL[10][1024];
    unsigned long long sbuf[2][16384];
    float pbL[10][4000];
    float psL[10][1000];
    float catb[2][19280];
    float cats[2][4820];
    float rois[2][4000];
    float roifeat[25088000];
    float h1[2048000];
    float h2[2048000];
    float clsl[182000];
    float boxl[728000];
    float dns[2][9000];
    float dnb[2][36000];
};
__device__ Scratch g;

__constant__ int cH[5]={208,104,52,26,13};
__constant__ int cW[5]={336,168,84,42,21};
__constant__ float cStrideF[5]={4.f,8.f,16.f,32.f,64.f};
__constant__ int cNl5[5]={209664,52416,13104,3276,819};
__constant__ int cK5[5]={1000,1000,1000,1000,819};
__constant__ int cSOff[5]={0,209664,262080,275184,278460};
__constant__ int cHOff[5]={0,139776,174720,183456,185640};
__constant__ int cOffCat[5]={0,1000,2000,3000,4000};

// ============ BF16 tensor-core GEMM 128x128x32 (m16n8k16, fp32 acc) =======
// MODE 0: dense A[M,K]. MODE 1: implicit 3x3 SAME conv, A=NHWC C=256, K=2304.
// K%32==0, N%128==0. 256 threads = 8 warps (4 M x 2 N), warp tile 32x64.
// smem words per row: 16 (=32 bf16) + pad 4 -> conflict-free frag loads.
#define BPADW 20
template<int MODE,bool RELU>
__global__ void __launch_bounds__(256,2)
gemm_bf16(const float* __restrict__ A,const float* __restrict__ Bw,
          const float* __restrict__ bias,float* __restrict__ C,
          int M,int N,int K,int H,int W){
    __shared__ unsigned Ah[2][128*BPADW];
    __shared__ unsigned Bh[2][128*BPADW];
    int tid=threadIdx.x;
    int bm=blockIdx.y*128, bn=blockIdx.x*128;
    int wid=tid>>5, lane=tid&31;
    int wm=wid&3, wn=wid>>2;
    int lr=lane>>2, lc=lane&3;

    float acc[2][8][4];
#pragma unroll
    for(int i=0;i<2;i++)
#pragma unroll
        for(int j=0;j<8;j++)
#pragma unroll
            for(int q=0;q<4;q++) acc[i][j][q]=0.f;

    // A loader: row=tid>>1 (0..127), k-half=(tid&1)*16
    int arow=tid>>1, ahalf=tid&1;
    int m=bm+arow;
    int ab=0,ay=0,ax=0;
    if(MODE==1){
        int HW=H*W; int mm=(m<M)?m:0;
        ab=mm/HW; int rem=mm-ab*HW; ay=rem/W; ax=rem-ay*W;
    }
    // B loader: col=tid>>1 (0..127), k-half=(tid&1)*16 (strided-coalesced)
    int bcol=tid>>1, bhalf=tid&1;

    unsigned aU[8], bU[8];
    auto loadG=[&](int k0){
        float4 t[4];
#pragma unroll
        for(int c=0;c<4;c++) t[c]=make_float4(0.f,0.f,0.f,0.f);
        if(m<M){
            if(MODE==0){
                const float* p=A+(size_t)m*K+k0+ahalf*16;
#pragma unroll
                for(int c=0;c<4;c++) t[c]=*(const float4*)(p+c*4);
            }else{
                int r=k0>>8;
                int ky=r/3, kx=r-ky*3;
                int yy=ay+ky-1, xx=ax+kx-1;
                if(yy>=0&&yy<H&&xx>=0&&xx<W){
                    const float* p=A+(((size_t)ab*H+yy)*W+xx)*256+(k0&255)+ahalf*16;
#pragma unroll
                    for(int c=0;c<4;c++) t[c]=*(const float4*)(p+c*4);
                }
            }
        }
#pragma unroll
        for(int c=0;c<4;c++){
            aU[2*c+0]=packbf(t[c].x,t[c].y);
            aU[2*c+1]=packbf(t[c].z,t[c].w);
        }
        const float* q=Bw+(size_t)(k0+bhalf*16)*N+bn+bcol;
        float f[16];
#pragma unroll
        for(int kk=0;kk<16;kk++) f[kk]=q[(size_t)kk*N];
#pragma unroll
        for(int c=0;c<8;c++) bU[c]=packbf(f[2*c],f[2*c+1]);
    };
    auto storeS=[&](int stg){
        unsigned* Ad=&Ah[stg][arow*BPADW+ahalf*8];
        *(uint4*)Ad      =make_uint4(aU[0],aU[1],aU[2],aU[3]);
        *(uint4*)(Ad+4)  =make_uint4(aU[4],aU[5],aU[6],aU[7]);
        unsigned* Bd=&Bh[stg][bcol*BPADW+bhalf*8];
        *(uint4*)Bd      =make_uint4(bU[0],bU[1],bU[2],bU[3]);
        *(uint4*)(Bd+4)  =make_uint4(bU[4],bU[5],bU[6],bU[7]);
    };

    int T=K>>5;
    loadG(0); storeS(0);
    __syncthreads();
    for(int t=0;t<T;t++){
        int cur=t&1, nxt=cur^1;
        if(t+1<T) loadG((t+1)*32);
        const unsigned* Ac=Ah[cur];
        const unsigned* Bc=Bh[cur];
#pragma unroll
        for(int ks=0;ks<2;ks++){
            int kb=ks*8;
            unsigned af[2][4];
#pragma unroll
            for(int mt=0;mt<2;mt++){
                int r0=wm*32+mt*16+lr;
                af[mt][0]=Ac[r0*BPADW+kb+lc];
                af[mt][1]=Ac[(r0+8)*BPADW+kb+lc];
                af[mt][2]=Ac[r0*BPADW+kb+lc+4];
                af[mt][3]=Ac[(r0+8)*BPADW+kb+lc+4];
            }
#pragma unroll
            for(int nt=0;nt<8;nt++){
                int cb=wn*64+nt*8+lr;
                unsigned b0=Bc[cb*BPADW+kb+lc];
                unsigned b1=Bc[cb*BPADW+kb+lc+4];
#pragma unroll
                for(int mt=0;mt<2;mt++){
                    asm volatile(
                      "mma.sync.aligned.m16n8k16.row.col.f32.bf16.bf16.f32 "
                      "{%0,%1,%2,%3}, {%4,%5,%6,%7}, {%8,%9}, {%0,%1,%2,%3};\n"
                      : "+f"(acc[mt][nt][0]),"+f"(acc[mt][nt][1]),
                        "+f"(acc[mt][nt][2]),"+f"(acc[mt][nt][3])
                      : "r"(af[mt][0]),"r"(af[mt][1]),"r"(af[mt][2]),"r"(af[mt][3]),
                        "r"(b0),"r"(b1));
                }
            }
        }
        if(t+1<T) storeS(nxt);
        __syncthreads();
    }
#pragma unroll
    for(int mt=0;mt<2;mt++){
#pragma unroll
        for(int nt=0;nt<8;nt++){
            int r0=bm+wm*32+mt*16+lr;
            int c0=bn+wn*64+nt*8+lc*2;
            float b0=bias[c0], b1=bias[c0+1];
            float v0=acc[mt][nt][0]+b0, v1=acc[mt][nt][1]+b1;
            float v2=acc[mt][nt][2]+b0, v3=acc[mt][nt][3]+b1;
            if(RELU){ v0=fmaxf(v0,0.f); v1=fmaxf(v1,0.f); v2=fmaxf(v2,0.f); v3=fmaxf(v3,0.f); }
            if(r0<M){ C[(size_t)r0*N+c0]=v0; C[(size_t)r0*N+c0+1]=v1; }
            if(r0+8<M){ C[(size_t)(r0+8)*N+c0]=v2; C[(size_t)(r0+8)*N+c0+1]=v3; }
        }
    }
}

// ---------------- fp32 SGEMM (small heads), double-buffered ---------------
template<int MODE,bool VECB,bool RELU>
__global__ void gemm128(const float* __restrict__ A,const float* __restrict__ Bw,
                        const float* __restrict__ bias,float* __restrict__ C,
                        int M,int N,int K,int H,int W){
    __shared__ float As[2][8][128];
    __shared__ float Bs[2][8][132];
    int tid=threadIdx.x;
    int bm=blockIdx.y*128, bn=blockIdx.x*128;
    int tx=tid&15, ty=tid>>4;
    float acc[8][8];
#pragma unroll
    for(int i=0;i<8;i++)
#pragma unroll
        for(int j=0;j<8;j++) acc[i][j]=0.f;
    int ar=tid>>1, aco=(tid&1)*4;
    int brow=tid>>5, bcol=(tid&31)*4;
    int m=bm+ar;
    auto loadA=[&](int k0)->float4{
        float4 r=make_float4(0.f,0.f,0.f,0.f);
        if(m<M) r=*(const float4*)(A+(size_t)m*K+k0+aco);
        return r;
    };
    auto loadB=[&](int k0)->float4{
        int kk=k0+brow; int n=bn+bcol;
        float4 r=make_float4(0.f,0.f,0.f,0.f);
        if(VECB&&(n+3)<N){
            r=*(const float4*)(Bw+(size_t)kk*N+n);
        }else{
            if(n+0<N) r.x=Bw[(size_t)kk*N+n+0];
            if(n+1<N) r.y=Bw[(size_t)kk*N+n+1];
            if(n+2<N) r.z=Bw[(size_t)kk*N+n+2];
            if(n+3<N) r.w=Bw[(size_t)kk*N+n+3];
        }
        return r;
    };
    int T=K>>3;
    float4 av=loadA(0), bv=loadB(0);
    As[0][aco+0][ar]=av.x; As[0][aco+1][ar]=av.y; As[0][aco+2][ar]=av.z; As[0][aco+3][ar]=av.w;
    *(float4*)&Bs[0][brow][bcol]=bv;
    __syncthreads();
    for(int t=0;t<T;t++){
        int cur=t&1, nxt=cur^1;
        if(t+1<T){ av=loadA((t+1)*8); bv=loadB((t+1)*8); }
#pragma unroll
        for(int kk=0;kk<8;kk++){
            float af[8],bf[8];
            *(float4*)&af[0]=*(const float4*)&As[cur][kk][ty*8];
            *(float4*)&af[4]=*(const float4*)&As[cur][kk][ty*8+4];
            *(float4*)&bf[0]=*(const float4*)&Bs[cur][kk][tx*8];
            *(float4*)&bf[4]=*(const float4*)&Bs[cur][kk][tx*8+4];
#pragma unroll
            for(int i=0;i<8;i++)
#pragma unroll
                for(int j=0;j<8;j++) acc[i][j]+=af[i]*bf[j];
        }
        if(t+1<T){
            As[nxt][aco+0][ar]=av.x; As[nxt][aco+1][ar]=av.y;
            As[nxt][aco+2][ar]=av.z; As[nxt][aco+3][ar]=av.w;
            *(float4*)&Bs[nxt][brow][bcol]=bv;
        }
        __syncthreads();
    }
#pragma unroll
    for(int i=0;i<8;i++){
        int mm=bm+ty*8+i;
        if(mm>=M) continue;
#pragma unroll
        for(int j=0;j<8;j++){
            int nn=bn+tx*8+j;
            if(nn>=N) continue;
            float v=acc[i][j]+bias[nn];
            if(RELU) v=fmaxf(v,0.f);
            C[(size_t)mm*N+nn]=v;
        }
    }
}

__global__ void init_kernel(){
    int i=threadIdx.x;
    if(i<10){ g.tiecntL[i]=0; g.selcntL[i]=0; }
}

// ---------------- fused RPN head over all levels --------------------------
__global__ void rpn_head_all(const float* __restrict__ sw,const float* __restrict__ sb,
    const float* __restrict__ bw,const float* __restrict__ bb){
    __shared__ float wsm[256][16];
    __shared__ float bsm[16];
    int tid=threadIdx.x;
    int lvl=blockIdx.y;
    int H=cH[lvl],W=cW[lvl];
    int HW=H*W, Btot=2*HW;
    for(int i=tid;i<256*16;i+=blockDim.x){
        int c=i>>4, j=i&15;
        float v=0.f;
        if(j<3) v=sw[c*3+j];
        else if(j<15) v=bw[c*12+(j-3)];
        wsm[c][j]=v;
    }
    if(tid<16) bsm[tid]=(tid<3)?sb[tid]:((tid<15)?bb[tid-3]:0.f);
    __syncthreads();
    int m=blockIdx.x*blockDim.x+tid;
    if(m>=Btot) return;
    int b=m/HW, pix=m-b*HW;
    const float* hr=g.h+((size_t)cHOff[lvl]+m)*256;
    int soff=cSOff[lvl];
    float acc[15];
#pragma unroll
    for(int j=0;j<15;j++) acc[j]=0.f;
    for(int c=0;c<256;c+=4){
        float4 v=*(const float4*)(hr+c);
#pragma unroll
        for(int j=0;j<15;j++)
            acc[j]+=v.x*wsm[c][j]+v.y*wsm[c+1][j]+v.z*wsm[c+2][j]+v.w*wsm[c+3][j];
    }
    for(int a=0;a<3;a++){
        float lg=acc[a]+bsm[a];
        g.scores[b][soff+pix*3+a]=1.f/(1.f+expf(-lg));
        for(int d=0;d<4;d++)
            g.deltas[b][(size_t)(soff+pix*3+a)*4+d]=acc[3+a*4+d]+bsm[3+a*4+d];
    }
}

// ------------- fused exact stable top-k: grid = 10 instances --------------
__global__ void select_topk_all(){
    int inst=blockIdx.x;
    int lvl=inst>>1, b=inst&1;
    int Nl=cNl5[lvl], k=cK5[lvl];
    const float* s=&g.scores[b][cSOff[lvl]];
    unsigned* hist=g.histL[inst];
    int* tiebuf=g.tiebufL[inst];
    unsigned long long* sbuf=g.sbufL[inst];
    int tid=threadIdx.x;
    __shared__ unsigned csum[1024];
    __shared__ int s_t,s_above,s_u,s_above2;
    if(tid==0){ g.selcntL[inst]=0; g.tiecntL[inst]=0; }
    for(int i=tid;i<65536;i+=1024) __stcg(&hist[i],0u);
    __syncthreads();
    for(int i=tid;i<Nl;i+=1024) atomicAdd(&hist[skey(s[i])>>16],1u);
    __syncthreads();
    {
        unsigned own=0; int base=65535-tid*64;
        for(int q=0;q<64;q++) own+=__ldcg(&hist[base-q]);
        csum[tid]=own; __syncthreads();
        for(int off=1;off<1024;off<<=1){
            unsigned v=csum[tid]; unsigned add=(tid>=off)?csum[tid-off]:0u; __syncthreads();
            csum[tid]=v+add; __syncthreads();
        }
        unsigned excl=csum[tid]-own;
        if(excl<(unsigned)k&&csum[tid]>=(unsigned)k){
            unsigned cum=excl;
            for(int q=0;q<64;q++){
                unsigned c=__ldcg(&hist[base-q]);
                if(cum+c>=(unsigned)k){ s_t=base-q; s_above=(int)cum; break; }
                cum+=c;
            }
        }
        __syncthreads();
    }
    int t=s_t, above=s_above;
    for(int i=tid;i<65536;i+=1024) __stcg(&hist[i],0u);
    __syncthreads();
    for(int i=tid;i<Nl;i+=1024){
        unsigned key=skey(s[i]);
        if((int)(key>>16)==t) atomicAdd(&hist[key&0xFFFFu],1u);
    }
    __syncthreads();
    int need=k-above;
    {
        unsigned own=0; int base=65535-tid*64;
        for(int q=0;q<64;q++) own+=__ldcg(&hist[base-q]);
        csum[tid]=own; __syncthreads();
        for(int off=1;off<1024;off<<=1){
            unsigned v=csum[tid]; unsigned add=(tid>=off)?csum[tid-off]:0u; __syncthreads();
            csum[tid]=v+add; __syncthreads();
        }
        unsigned excl=csum[tid]-own;
        if(excl<(unsigned)need&&csum[tid]>=(unsigned)need){
            unsigned cum=excl;
            for(int q=0;q<64;q++){
                unsigned c=__ldcg(&hist[base-q]);
                if(cum+c>=(unsigned)need){ s_u=base-q; s_above2=(int)cum; break; }
                cum+=c;
            }
        }
        __syncthreads();
    }
    int u=s_u, above2=s_above2;
    unsigned T=(((unsigned)t)<<16)|(unsigned)u;
    for(int i=tid;i<Nl;i+=1024){
        unsigned key=skey(s[i]);
        if(key>T){
            int pos=atomicAdd(&g.selcntL[inst],1);
            sbuf[pos]=(((unsigned long long)key)<<32)|(unsigned)(~(unsigned)i);
        }else if(key==T){
            int p=atomicAdd(&g.tiecntL[inst],1);
            if(p<4096) tiebuf[p]=i;
        }
    }
    __syncthreads();
    int ct=g.tiecntL[inst]; if(ct>4096) ct=4096;
    int mtake=need-above2;
    int pos0=above+above2;
    for(int ti=tid;ti<ct;ti+=1024){
        int myi=tiebuf[ti];
        int rank=0;
        for(int q=0;q<ct;q++) rank+=(tiebuf[q]<myi);
        if(rank<mtake)
            sbuf[pos0+rank]=(((unsigned long long)T)<<32)|(unsigned)(~(unsigned)myi);
    }
    __syncthreads();
    if(tid>=k&&tid<1024) sbuf[tid]=0ull;
}

__global__ void bitonic_lvl(){
    unsigned long long* a=g.sbufL[blockIdx.x];
    const int n=1024;
    for(int k=2;k<=n;k<<=1){
        for(int j=k>>1;j>0;j>>=1){
            for(int i=threadIdx.x;i<n;i+=blockDim.x){
                int l=i^j;
                if(l>i){
                    unsigned long long x=a[i],y=a[l];
                    bool sw=((i&k)==0)?(x<y):(x>y);
                    if(sw){ a[i]=y; a[l]=x; }
                }
            }
            __syncthreads();
        }
    }
}

__global__ void bitonic_desc(int n){
    unsigned long long* a=g.sbuf[blockIdx.x];
    for(int k=2;k<=n;k<<=1){
        for(int j=k>>1;j>0;j>>=1){
            for(int i=threadIdx.x;i<n;i+=blockDim.x){
                int l=i^j;
                if(l>i){
                    unsigned long long x=a[i],y=a[l];
                    bool sw=((i&k)==0)?(x<y):(x>y);
                    if(sw){ a[i]=y; a[l]=x; }
                }
            }
            __syncthreads();
        }
    }
}

__global__ void rpn_decode_all(const float* __restrict__ iminfo){
    int inst=blockIdx.x;
    int lvl=inst>>1, b=inst&1;
    int k=cK5[lvl], W=cW[lvl];
    int r=threadIdx.x;
    if(r>=k) return;
    unsigned long long key=g.sbufL[inst][r];
    int i=(int)(~(unsigned)key);
    int a=i%3; int pix=i/3; int x=pix%W; int y=pix/W;
    double stride=(double)(1<<(lvl+2));
    double size=8.0*stride;
    double rr=(a==0)?1.0:((a==1)?0.5:2.0);
    double sr=sqrt(rr);
    double hh=size/sr, ww=size*sr;
    double ycd=((double)y+0.5)*stride, xcd=((double)x+0.5)*stride;
    float ya1=(float)(ycd-hh*0.5), xa1=(float)(xcd-ww*0.5);
    float ya2=(float)(ycd+hh*0.5), xa2=(float)(xcd+ww*0.5);
    const float* d=&g.deltas[b][(size_t)(cSOff[lvl]+i)*4];
    float ha=ya2-ya1, wa=xa2-xa1;
    float yc=ya1+0.5f*ha, xc=xa1+0.5f*wa;
    float dy=d[0], dx=d[1];
    float dh=fminf(d[2],CLIPV), dw=fminf(d[3],CLIPV);
    float pcy=dy*ha+yc, pcx=dx*wa+xc;
    float ph=expf(dh)*ha, pw=expf(dw)*wa;
    float hI=iminfo[b*5+0], wI=iminfo[b*5+1];
    g.pbL[inst][r*4+0]=fminf(fmaxf(pcy-0.5f*ph,0.f),hI);
    g.pbL[inst][r*4+1]=fminf(fmaxf(pcx-0.5f*pw,0.f),wI);
    g.pbL[inst][r*4+2]=fminf(fmaxf(pcy+0.5f*ph,0.f),hI);
    g.pbL[inst][r*4+3]=fminf(fmaxf(pcx+0.5f*pw,0.f),wI);
    g.psL[inst][r]=g.scores[b][cSOff[lvl]+i];
}

__global__ void nms_level_all(){
    __shared__ float y1[1000],x1[1000],y2[1000],x2[1000],s[1000];
    __shared__ int sp,sj;
    int inst=blockIdx.x;
    int lvl=inst>>1, b=inst&1;
    int k=cK5[lvl], off=cOffCat[lvl];
    int tid=threadIdx.x;
    float* ob=&g.catb[b][off*4];
    float* os=&g.cats[b][off];
    for(int i=tid;i<k;i+=256){
        y1[i]=g.pbL[inst][i*4+0]; x1[i]=g.pbL[inst][i*4+1];
        y2[i]=g.pbL[inst][i*4+2]; x2[i]=g.pbL[inst][i*4+3];
        s[i]=g.psL[inst][i];
    }
    if(tid==0) sp=0;
    __syncthreads();
    for(int it=0;it<k;it++){
        if(tid==0){
            int p=sp;
            while(p<k && s[p]<=NEGF*0.5f) p++;
            sj=(p<k)?p:-1; sp=p;
        }
        __syncthreads();
        int j=sj;
        if(j<0){
            for(int r=it+tid;r<k;r+=256){
                os[r]=NEGF;
                ob[r*4+0]=0.f; ob[r*4+1]=0.f; ob[r*4+2]=0.f; ob[r*4+3]=0.f;
            }
            return;
        }
        float a1=y1[j],a2=x1[j],a3=y2[j],a4=x2[j];
        float js=s[j];
        __syncthreads();
        float aA=(a3-a1)*(a4-a2);
        for(int i=tid;i<k;i+=256){
            float yy1=fmaxf(a1,y1[i]), xx1=fmaxf(a2,x1[i]);
            float yy2=fminf(a3,y2[i]), xx2=fminf(a4,x2[i]);
            float inter=fmaxf(yy2-yy1,0.f)*fmaxf(xx2-xx1,0.f);
            float bA=(y2[i]-y1[i])*(x2[i]-x1[i]);
            float iou=inter/(aA+bA-inter+1e-8f);
            if(iou>=0.7f) s[i]=NEGF;
        }
        __syncthreads();
        if(tid==0){
            s[j]=NEGF;
            os[it]=js;
            ob[it*4+0]=a1; ob[it*4+1]=a2; ob[it*4+2]=a3; ob[it*4+3]=a4;
        }
        __syncthreads();
    }
}

__device__ void nms_run(float* y1,float* x1,float* y2,float* x2,float* s,
                        int n,int iters,float th,float* ob,float* os){
    __shared__ float rv[256];
    __shared__ int ri[256];
    __shared__ float cb[4];
    int tid=threadIdx.x;
    for(int it=0;it<iters;it++){
        float bv=-3.0e38f; int bi=1<<30;
        for(int i=tid;i<n;i+=256){
            float v=s[i];
            if(v>bv||(v==bv&&i<bi)){ bv=v; bi=i; }
        }
        rv[tid]=bv; ri[tid]=bi; __syncthreads();
        for(int o=128;o>0;o>>=1){
            if(tid<o){
                float v=rv[tid+o]; int j=ri[tid+o];
                if(v>rv[tid]||(v==rv[tid]&&j<ri[tid])){ rv[tid]=v; ri[tid]=j; }
            }
            __syncthreads();
        }
        int j=ri[0]; float js=rv[0];
        if(js<=NEGF*0.5f){
            for(int r=it+tid;r<iters;r+=256){
                os[r]=NEGF;
                ob[r*4+0]=0.f; ob[r*4+1]=0.f; ob[r*4+2]=0.f; ob[r*4+3]=0.f;
            }
            __syncthreads();
            return;
        }
        if(tid==0){ cb[0]=y1[j]; cb[1]=x1[j]; cb[2]=y2[j]; cb[3]=x2[j]; }
        __syncthreads();
        float a1=cb[0],a2=cb[1],a3=cb[2],a4=cb[3];
        float aA=(a3-a1)*(a4-a2);
        for(int i=tid;i<n;i+=256){
            float yy1=fmaxf(a1,y1[i]), xx1=fmaxf(a2,x1[i]);
            float yy2=fminf(a3,y2[i]), xx2=fminf(a4,x2[i]);
            float inter=fmaxf(yy2-yy1,0.f)*fmaxf(xx2-xx1,0.f);
            float bA=(y2[i]-y1[i])*(x2[i]-x1[i]);
            float iou=inter/(aA+bA-inter+1e-8f);
            if(iou>=th) s[i]=NEGF;
        }
        __syncthreads();
        if(tid==0){
            s[j]=NEGF;
            os[it]=js;
            ob[it*4+0]=a1; ob[it*4+1]=a2; ob[it*4+2]=a3; ob[it*4+3]=a4;
        }
        __syncthreads();
    }
}

__global__ void build_cat_keys(){
    int b=blockIdx.x;
    for(int i=threadIdx.x;i<8192;i+=blockDim.x){
        unsigned long long key=0ull;
        if(i<4819) key=(((unsigned long long)skey(g.cats[b][i]))<<32)|(unsigned)(~(unsigned)i);
        g.sbuf[b][i]=key;
    }
}

__global__ void gather_rois(){
    int b=blockIdx.x;
    for(int r=threadIdx.x;r<1000;r+=blockDim.x){
        int i=(int)(~(unsigned)g.sbuf[b][r]);
        for(int d=0;d<4;d++) g.rois[b][r*4+d]=g.catb[b][i*4+d];
    }
}

__global__ void roialign(const float* f0,const float* f1,const float* f2,
                         const float* f3,const float* f4){
    int br=blockIdx.x; int b=br/1000;
    int c=threadIdx.x;
    const float* ro=&g.rois[b][(br%1000)*4];
    float y1=ro[0],x1=ro[1],y2=ro[2],x2=ro[3];
    float area=fmaxf((y2-y1)*(x2-x1),1e-6f);
    float lv=floorf(4.f+log2f(sqrtf(area)/224.f));
    lv=fminf(fmaxf(lv,2.f),6.f);
    int li=(int)lv-2;
    const float* fp=(li==0)?f0:(li==1)?f1:(li==2)?f2:(li==3)?f3:f4;
    int H=cH[li],W=cW[li];
    float Hf=(float)H,Wf=(float)W;
    float stride=cStrideF[li];
    const float* base=fp+(size_t)b*H*W*256;
    float* outp=&g.roifeat[(size_t)br*12544];
    for(int p=0;p<49;p++){
        int py=p/7,px=p%7;
        float uy=((float)py+0.5f)/7.f, ux=((float)px+0.5f)/7.f;
        float ys=(y1+(y2-y1)*uy)/stride-0.5f;
        float xs=(x1+(x2-x1)*ux)/stride-0.5f;
        ys=fminf(fmaxf(ys,0.f),Hf-1.f);
        xs=fminf(fmaxf(xs,0.f),Wf-1.f);
        float y0=floorf(ys),x0=floorf(xs);
        float wy=ys-y0,wx=xs-x0;
        int y0i=(int)y0,x0i=(int)x0;
        int y1i=min(y0i+1,H-1),x1i=min(x0i+1,W-1);
        const float* p00=base+((size_t)y0i*W+x0i)*256;
        const float* p01=base+((size_t)y0i*W+x1i)*256;
        const float* p10=base+((size_t)y1i*W+x0i)*256;
        const float* p11=base+((size_t)y1i*W+x1i)*256;
        float w00=(1.f-wy)*(1.f-wx), w01=(1.f-wy)*wx;
        float w10=wy*(1.f-wx), w11=wy*wx;
        outp[p*256+c]=p00[c]*w00+p01[c]*w01+p10[c]*w10+p11[c]*w11;
    }
}

__global__ void softmax91(){
    int i=blockIdx.x*blockDim.x+threadIdx.x;
    if(i>=2000) return;
    float* p=&g.clsl[(size_t)i*91];
    float mx=p[0];
    for(int c=1;c<91;c++) mx=fmaxf(mx,p[c]);
    float sm=0.f;
    float e[91];
    for(int c=0;c<91;c++){ e[c]=expf(p[c]-mx); sm+=e[c]; }
    for(int c=0;c<91;c++) p[c]=e[c]/sm;
}

__global__ void nms_det(const float* __restrict__ iminfo){
    __shared__ float y1[1000],x1[1000],y2[1000],x2[1000],s[1000];
    int blk=blockIdx.x; int b=blk/90; int c=blk%90+1;
    int tid=threadIdx.x;
    float hI=iminfo[b*5+0], wI=iminfo[b*5+1];
    for(int i=tid;i<1000;i+=256){
        const float* ro=&g.rois[b][i*4];
        float ya1=ro[0],xa1=ro[1],ya2=ro[2],xa2=ro[3];
        float ha=ya2-ya1, wa=xa2-xa1;
        float yc=ya1+0.5f*ha, xc=xa1+0.5f*wa;
        const float* d=&g.boxl[((size_t)(b*1000+i)*91+c)*4];
        float dy=d[0]/10.f, dx=d[1]/10.f;
        float dh=fminf(d[2]/5.f,CLIPV), dw=fminf(d[3]/5.f,CLIPV);
        float pcy=dy*ha+yc, pcx=dx*wa+xc;
        float ph=expf(dh)*ha, pw=expf(dw)*wa;
        y1[i]=fminf(fmaxf(pcy-0.5f*ph,0.f),hI);
        x1[i]=fminf(fmaxf(pcx-0.5f*pw,0.f),wI);
        y2[i]=fminf(fmaxf(pcy+0.5f*ph,0.f),hI);
        x2[i]=fminf(fmaxf(pcx+0.5f*pw,0.f),wI);
        float p=g.clsl[(size_t)(b*1000+i)*91+c];
        s[i]=(p>=0.05f)?p:NEGF;
    }
    __syncthreads();
    nms_run(y1,x1,y2,x2,s,1000,100,0.5f,&g.dnb[b][(c-1)*400],&g.dns[b][(c-1)*100]);
}

__global__ void build_det_keys(){
    int b=blockIdx.x;
    for(int i=threadIdx.x;i<16384;i+=blockDim.x){
        unsigned long long key=0ull;
        if(i<9000) key=(((unsigned long long)skey(g.dns[b][i]))<<32)|(unsigned)(~(unsigned)i);
        g.sbuf[b][i]=key;
    }
}

__global__ void write_out(float* out,int out_size){
    int tid=threadIdx.x;
    for(int i=tid;i<out_size;i+=256) out[i]=0.f;
    __syncthreads();
    __shared__ int cnt;
    for(int b=0;b<2;b++){
        if(tid==0) cnt=0;
        __syncthreads();
        if(tid<100){
            int r=tid;
            int idx=(int)(~(unsigned)g.sbuf[b][r]);
            float sc=g.dns[b][idx];
            bool valid=sc>0.f;
            if(valid) atomicAdd(&cnt,1);
            float cls=valid?(float)(idx/100+1):0.f;
            int ob=2+b*400+r*4;
            for(int d=0;d<4;d++){
                int o=ob+d;
                if(o<out_size) out[o]=valid?g.dnb[b][idx*4+d]:0.f;
            }
            int oc=2+800+b*100+r;
            if(oc<out_size) out[oc]=cls;
            int os=2+1000+b*100+r;
            if(os<out_size) out[os]=valid?sc:0.f;
        }
        __syncthreads();
        if(tid==0&&b<out_size) out[b]=(float)cnt;
        __syncthreads();
    }
}

extern "C" void kernel_launch(void* const* d_in,const int* in_sizes,int n_in,
                              void* d_out,int out_size){
    const float* feats[5];
    for(int i=0;i<5;i++) feats[i]=(const float*)d_in[i];
    const float* iminfo=(const float*)d_in[5];
    const float* cw =(const float*)d_in[6];
    const float* cbv=(const float*)d_in[7];
    const float* sw =(const float*)d_in[8];
    const float* sb =(const float*)d_in[9];
    const float* bw =(const float*)d_in[10];
    const float* bbv=(const float*)d_in[11];
    const float* fc1w=(const float*)d_in[12];
    const float* fc1b=(const float*)d_in[13];
    const float* fc2w=(const float*)d_in[14];
    const float* fc2b=(const float*)d_in[15];
    const float* clsw=(const float*)d_in[16];
    const float* clsb=(const float*)d_in[17];
    const float* boxw=(const float*)d_in[18];
    const float* boxb=(const float*)d_in[19];

    Scratch* gp=nullptr;
    cudaGetSymbolAddress((void**)&gp,g);

    int Hs[5]={208,104,52,26,13}, Ws[5]={336,168,84,42,21};
    int hOff[5]={0,139776,174720,183456,185640};

    init_kernel<<<1,32>>>();                               // idx 0
    for(int i=4;i>=0;i--){                                  // idx 1..5 (l2 = idx 5)
        int H=Hs[i],W=Ws[i],M=2*H*W;
        dim3 gr(2,(M+127)/128);
        gemm_bf16<1,true><<<gr,256>>>(feats[i],cw,cbv,gp->h+(size_t)hOff[i]*256,M,256,2304,H,W);
    }
    rpn_head_all<<<dim3(546,5),256>>>(sw,sb,bw,bbv);
    select_topk_all<<<10,1024>>>();
    bitonic_lvl<<<10,1024>>>();
    rpn_decode_all<<<10,1024>>>(iminfo);
    nms_level_all<<<10,256>>>();

    build_cat_keys<<<2,256>>>();
    bitonic_desc<<<2,1024>>>(8192);
    gather_rois<<<2,256>>>();

    roialign<<<2000,256>>>(feats[0],feats[1],feats[2],feats[3],feats[4]);

    gemm_bf16<0,true><<<dim3(8,16),256>>>(gp->roifeat,fc1w,fc1b,gp->h1,2000,1024,12544,0,0);
    gemm_bf16<0,true><<<dim3(8,16),256>>>(gp->h1,fc2w,fc2b,gp->h2,2000,1024,1024,0,0);
    gemm128<0,false,false><<<dim3(1,16),256>>>(gp->h2,clsw,clsb,gp->clsl,2000,91,1024,0,0);
    gemm128<0,true,false><<<dim3(3,16),256>>>(gp->h2,boxw,boxb,gp->boxl,2000,364,1024,0,0);

    softmax91<<<8,256>>>();
    nms_det<<<180,256>>>(iminfo);
    build_det_keys<<<2,256>>>();
    bitonic_desc<<<2,1024>>>(16384);
    write_out<<<1,256>>>((float*)d_out,out_size);
}

// round 11
// speedup vs baseline: 5.6164x; 1.1495x over previous
#include <cuda_runtime.h>
#include <cuda_bf16.h>
#include <math.h>
#include <stddef.h>

#define NEGF (-1.0e9f)
#define CLIPV 4.135166556742356f

__device__ __forceinline__ unsigned skey(float s){
    unsigned u = __float_as_uint(s);
    return (u & 0x80000000u) ? ~u : (u | 0x80000000u);
}

struct __align__(256) Scratch {
    float h[47663616];
    float scores[2][279280];
    float deltas[2][1117120];
    unsigned histL[10][65536];
    int tiebufL[10][4096];
    int tiecntL[10];
    int selcntL[10];
    unsigned long long sbufL[10][1024];
    unsigned long long sbuf[2][16384];
    float pbL[10][4000];
    float psL[10][1000];
    float catb[2][19280];
    float cats[2][4820];
    float rois[2][4000];
    float clsl[182000];
    float boxl[728000];
    float dns[2][9000];
    float dnb[2][36000];
    float clsbPad[128];
    float boxbPad[384];
    __nv_bfloat16 featsbf[47663616];
    __nv_bfloat16 cwT[256*2304];
    __nv_bfloat16 fc1wT[1024*12544];
    __nv_bfloat16 fc2wT[1024*1024];
    __nv_bfloat16 clswT[128*1024];
    __nv_bfloat16 boxwT[384*1024];
    __nv_bfloat16 roifeatb[25088000];
    __nv_bfloat16 h1b[2048000];
    __nv_bfloat16 h2b[2048000];
};
__device__ Scratch g;

__constant__ int cH[5]={208,104,52,26,13};
__constant__ int cW[5]={336,168,84,42,21};
__constant__ float cStrideF[5]={4.f,8.f,16.f,32.f,64.f};
__constant__ int cNl5[5]={209664,52416,13104,3276,819};
__constant__ int cK5[5]={1000,1000,1000,1000,819};
__constant__ int cSOff[5]={0,209664,262080,275184,278460};
__constant__ int cHOff[5]={0,139776,174720,183456,185640};
__constant__ int cOffCat[5]={0,1000,2000,3000,4000};

// ---- convert feats fp32 NHWC -> bf16 (per level) --------------------------
__global__ void cvt_feats(const float* f0,const float* f1,const float* f2,
                          const float* f3,const float* f4){
    int lvl=blockIdx.y;
    const float* src=(lvl==0)?f0:(lvl==1)?f1:(lvl==2)?f2:(lvl==3)?f3:f4;
    int Etot=2*cH[lvl]*cW[lvl]*256;
    int base=(blockIdx.x*256+threadIdx.x)*8;
    if(base>=Etot) return;
    float4 a=*(const float4*)(src+base);
    float4 b=*(const float4*)(src+base+4);
    __nv_bfloat162 r0=__floats2bfloat162_rn(a.x,a.y);
    __nv_bfloat162 r1=__floats2bfloat162_rn(a.z,a.w);
    __nv_bfloat162 r2=__floats2bfloat162_rn(b.x,b.y);
    __nv_bfloat162 r3=__floats2bfloat162_rn(b.z,b.w);
    uint4 o=make_uint4(*(unsigned*)&r0,*(unsigned*)&r1,*(unsigned*)&r2,*(unsigned*)&r3);
    *(uint4*)(g.featsbf+(size_t)cHOff[lvl]*256+base)=o;
}

// ---- transpose + convert weights: src[K][N] fp32 -> dst[Npad][K] bf16 -----
__global__ void twcvt(const float* __restrict__ src,__nv_bfloat16* __restrict__ dst,
                      int K,int N,int Npad){
    __shared__ float t[32][33];
    int kb=blockIdx.x*32, nb=blockIdx.y*32;
    int tx=threadIdx.x, ty=threadIdx.y;   // 32 x 8
#pragma unroll
    for(int d=0;d<4;d++){
        int k=kb+ty+d*8, n=nb+tx;
        t[ty+d*8][tx]=(k<K&&n<N)?src[(size_t)k*N+n]:0.f;
    }
    __syncthreads();
#pragma unroll
    for(int d=0;d<4;d++){
        int n=nb+ty+d*8, k=kb+tx;
        if(n<Npad&&k<K) dst[(size_t)n*K+k]=__float2bfloat16_rn(t[tx][ty+d*8]);
    }
}

__global__ void padbias(const float* clsb,const float* boxb){
    int i=threadIdx.x;
    if(i<128) g.clsbPad[i]=(i<91)?clsb[i]:0.f;
    if(i<384) g.boxbPad[i]=(i<364)?boxb[i]:0.f;
}

// ============ BF16 GEMM 128x128x32 (m16n8k16, fp32 acc), bf16 inputs ======
// MODE 0: dense A[M][K] bf16. MODE 1: implicit 3x3 conv, A = featsbf NHWC.
// B: bf16 [Npad][K] (pre-transposed). OUTBF: store bf16 else fp32. K%32==0.
#define BPADW 20
template<int MODE,bool OUTBF,bool RELU>
__global__ void __launch_bounds__(256,2)
gemm_bf16(const __nv_bfloat16* __restrict__ A,const __nv_bfloat16* __restrict__ Bw,
          const float* __restrict__ bias,void* __restrict__ Cout,
          int M,int N,int K,int H,int W){
    __shared__ unsigned Ah[2][128*BPADW];
    __shared__ unsigned Bh[2][128*BPADW];
    int tid=threadIdx.x;
    int bm=blockIdx.y*128, bn=blockIdx.x*128;
    int wid=tid>>5, lane=tid&31;
    int wm=wid&3, wn=wid>>2;
    int lr=lane>>2, lc=lane&3;

    float acc[2][8][4];
#pragma unroll
    for(int i=0;i<2;i++)
#pragma unroll
        for(int j=0;j<8;j++)
#pragma unroll
            for(int q=0;q<4;q++) acc[i][j][q]=0.f;

    int arow=tid>>1, ahalf=tid&1;
    int m=bm+arow;
    int ab=0,ay=0,ax=0;
    if(MODE==1){
        int HW=H*W; int mm=(m<M)?m:0;
        ab=mm/HW; int rem=mm-ab*HW; ay=rem/W; ax=rem-ay*W;
    }
    int bcol=tid>>1, bhalf=tid&1;

    uint4 aV0,aV1,bV0,bV1;
    auto loadG=[&](int k0){
        aV0=make_uint4(0,0,0,0); aV1=aV0;
        if(m<M){
            if(MODE==0){
                const __nv_bfloat16* p=A+(size_t)m*K+k0+ahalf*16;
                aV0=*(const uint4*)p; aV1=*(const uint4*)(p+8);
            }else{
                int r=k0>>8;
                int ky=r/3, kx=r-ky*3;
                int yy=ay+ky-1, xx=ax+kx-1;
                if(yy>=0&&yy<H&&xx>=0&&xx<W){
                    const __nv_bfloat16* p=A+(((size_t)ab*H+yy)*W+xx)*256+(k0&255)+ahalf*16;
                    aV0=*(const uint4*)p; aV1=*(const uint4*)(p+8);
                }
            }
        }
        const __nv_bfloat16* q=Bw+(size_t)(bn+bcol)*K+k0+bhalf*16;
        bV0=*(const uint4*)q; bV1=*(const uint4*)(q+8);
    };
    auto storeS=[&](int stg){
        unsigned* Ad=&Ah[stg][arow*BPADW+ahalf*8];
        *(uint4*)Ad=aV0; *(uint4*)(Ad+4)=aV1;
        unsigned* Bd=&Bh[stg][bcol*BPADW+bhalf*8];
        *(uint4*)Bd=bV0; *(uint4*)(Bd+4)=bV1;
    };

    int T=K>>5;
    loadG(0); storeS(0);
    __syncthreads();
    for(int t=0;t<T;t++){
        int cur=t&1, nxt=cur^1;
        if(t+1<T) loadG((t+1)*32);
        const unsigned* Ac=Ah[cur];
        const unsigned* Bc=Bh[cur];
#pragma unroll
        for(int ks=0;ks<2;ks++){
            int kb=ks*8;
            unsigned af[2][4];
#pragma unroll
            for(int mt=0;mt<2;mt++){
                int r0=wm*32+mt*16+lr;
                af[mt][0]=Ac[r0*BPADW+kb+lc];
                af[mt][1]=Ac[(r0+8)*BPADW+kb+lc];
                af[mt][2]=Ac[r0*BPADW+kb+lc+4];
                af[mt][3]=Ac[(r0+8)*BPADW+kb+lc+4];
            }
#pragma unroll
            for(int nt=0;nt<8;nt++){
                int cb=wn*64+nt*8+lr;
                unsigned b0=Bc[cb*BPADW+kb+lc];
                unsigned b1=Bc[cb*BPADW+kb+lc+4];
#pragma unroll
                for(int mt=0;mt<2;mt++){
                    asm volatile(
                      "mma.sync.aligned.m16n8k16.row.col.f32.bf16.bf16.f32 "
                      "{%0,%1,%2,%3}, {%4,%5,%6,%7}, {%8,%9}, {%0,%1,%2,%3};\n"
                      : "+f"(acc[mt][nt][0]),"+f"(acc[mt][nt][1]),
                        "+f"(acc[mt][nt][2]),"+f"(acc[mt][nt][3])
                      : "r"(af[mt][0]),"r"(af[mt][1]),"r"(af[mt][2]),"r"(af[mt][3]),
                        "r"(b0),"r"(b1));
                }
            }
        }
        if(t+1<T) storeS(nxt);
        __syncthreads();
    }
#pragma unroll
    for(int mt=0;mt<2;mt++){
#pragma unroll
        for(int nt=0;nt<8;nt++){
            int r0=bm+wm*32+mt*16+lr;
            int c0=bn+wn*64+nt*8+lc*2;
            float b0=bias[c0], b1=bias[c0+1];
            float v0=acc[mt][nt][0]+b0, v1=acc[mt][nt][1]+b1;
            float v2=acc[mt][nt][2]+b0, v3=acc[mt][nt][3]+b1;
            if(RELU){ v0=fmaxf(v0,0.f); v1=fmaxf(v1,0.f); v2=fmaxf(v2,0.f); v3=fmaxf(v3,0.f); }
            if(OUTBF){
                __nv_bfloat16* C=(__nv_bfloat16*)Cout;
                if(r0<M){
                    if(c0<N)   C[(size_t)r0*N+c0]  =__float2bfloat16_rn(v0);
                    if(c0+1<N) C[(size_t)r0*N+c0+1]=__float2bfloat16_rn(v1);
                }
                if(r0+8<M){
                    if(c0<N)   C[(size_t)(r0+8)*N+c0]  =__float2bfloat16_rn(v2);
                    if(c0+1<N) C[(size_t)(r0+8)*N+c0+1]=__float2bfloat16_rn(v3);
                }
            }else{
                float* C=(float*)Cout;
                if(r0<M){
                    if(c0<N)   C[(size_t)r0*N+c0]=v0;
                    if(c0+1<N) C[(size_t)r0*N+c0+1]=v1;
                }
                if(r0+8<M){
                    if(c0<N)   C[(size_t)(r0+8)*N+c0]=v2;
                    if(c0+1<N) C[(size_t)(r0+8)*N+c0+1]=v3;
                }
            }
        }
    }
}

__global__ void init_kernel(){
    int i=threadIdx.x;
    if(i<10){ g.tiecntL[i]=0; g.selcntL[i]=0; }
}

// ---------------- fused RPN head over all levels --------------------------
__global__ void rpn_head_all(const float* __restrict__ sw,const float* __restrict__ sb,
    const float* __restrict__ bw,const float* __restrict__ bb){
    __shared__ float wsm[256][16];
    __shared__ float bsm[16];
    int tid=threadIdx.x;
    int lvl=blockIdx.y;
    int H=cH[lvl],W=cW[lvl];
    int HW=H*W, Btot=2*HW;
    for(int i=tid;i<256*16;i+=blockDim.x){
        int c=i>>4, j=i&15;
        float v=0.f;
        if(j<3) v=sw[c*3+j];
        else if(j<15) v=bw[c*12+(j-3)];
        wsm[c][j]=v;
    }
    if(tid<16) bsm[tid]=(tid<3)?sb[tid]:((tid<15)?bb[tid-3]:0.f);
    __syncthreads();
    int m=blockIdx.x*blockDim.x+tid;
    if(m>=Btot) return;
    int b=m/HW, pix=m-b*HW;
    const float* hr=g.h+((size_t)cHOff[lvl]+m)*256;
    int soff=cSOff[lvl];
    float acc[15];
#pragma unroll
    for(int j=0;j<15;j++) acc[j]=0.f;
    for(int c=0;c<256;c+=4){
        float4 v=*(const float4*)(hr+c);
#pragma unroll
        for(int j=0;j<15;j++)
            acc[j]+=v.x*wsm[c][j]+v.y*wsm[c+1][j]+v.z*wsm[c+2][j]+v.w*wsm[c+3][j];
    }
    for(int a=0;a<3;a++){
        float lg=acc[a]+bsm[a];
        g.scores[b][soff+pix*3+a]=1.f/(1.f+expf(-lg));
        for(int d=0;d<4;d++)
            g.deltas[b][(size_t)(soff+pix*3+a)*4+d]=acc[3+a*4+d]+bsm[3+a*4+d];
    }
}

// ------------- fused exact stable top-k: grid = 10 instances --------------
__global__ void select_topk_all(){
    int inst=blockIdx.x;
    int lvl=inst>>1, b=inst&1;
    int Nl=cNl5[lvl], k=cK5[lvl];
    const float* s=&g.scores[b][cSOff[lvl]];
    unsigned* hist=g.histL[inst];
    int* tiebuf=g.tiebufL[inst];
    unsigned long long* sbuf=g.sbufL[inst];
    int tid=threadIdx.x;
    __shared__ unsigned csum[1024];
    __shared__ int s_t,s_above,s_u,s_above2;
    if(tid==0){ g.selcntL[inst]=0; g.tiecntL[inst]=0; }
    for(int i=tid;i<65536;i+=1024) __stcg(&hist[i],0u);
    __syncthreads();
    for(int i=tid;i<Nl;i+=1024) atomicAdd(&hist[skey(s[i])>>16],1u);
    __syncthreads();
    {
        unsigned own=0; int base=65535-tid*64;
        for(int q=0;q<64;q++) own+=__ldcg(&hist[base-q]);
        csum[tid]=own; __syncthreads();
        for(int off=1;off<1024;off<<=1){
            unsigned v=csum[tid]; unsigned add=(tid>=off)?csum[tid-off]:0u; __syncthreads();
            csum[tid]=v+add; __syncthreads();
        }
        unsigned excl=csum[tid]-own;
        if(excl<(unsigned)k&&csum[tid]>=(unsigned)k){
            unsigned cum=excl;
            for(int q=0;q<64;q++){
                unsigned c=__ldcg(&hist[base-q]);
                if(cum+c>=(unsigned)k){ s_t=base-q; s_above=(int)cum; break; }
                cum+=c;
            }
        }
        __syncthreads();
    }
    int t=s_t, above=s_above;
    for(int i=tid;i<65536;i+=1024) __stcg(&hist[i],0u);
    __syncthreads();
    for(int i=tid;i<Nl;i+=1024){
        unsigned key=skey(s[i]);
        if((int)(key>>16)==t) atomicAdd(&hist[key&0xFFFFu],1u);
    }
    __syncthreads();
    int need=k-above;
    {
        unsigned own=0; int base=65535-tid*64;
        for(int q=0;q<64;q++) own+=__ldcg(&hist[base-q]);
        csum[tid]=own; __syncthreads();
        for(int off=1;off<1024;off<<=1){
            unsigned v=csum[tid]; unsigned add=(tid>=off)?csum[tid-off]:0u; __syncthreads();
            csum[tid]=v+add; __syncthreads();
        }
        unsigned excl=csum[tid]-own;
        if(excl<(unsigned)need&&csum[tid]>=(unsigned)need){
            unsigned cum=excl;
            for(int q=0;q<64;q++){
                unsigned c=__ldcg(&hist[base-q]);
                if(cum+c>=(unsigned)need){ s_u=base-q; s_above2=(int)cum; break; }
                cum+=c;
            }
        }
        __syncthreads();
    }
    int u=s_u, above2=s_above2;
    unsigned T=(((unsigned)t)<<16)|(unsigned)u;
    for(int i=tid;i<Nl;i+=1024){
        unsigned key=skey(s[i]);
        if(key>T){
            int pos=atomicAdd(&g.selcntL[inst],1);
            sbuf[pos]=(((unsigned long long)key)<<32)|(unsigned)(~(unsigned)i);
        }else if(key==T){
            int p=atomicAdd(&g.tiecntL[inst],1);
            if(p<4096) tiebuf[p]=i;
        }
    }
    __syncthreads();
    int ct=g.tiecntL[inst]; if(ct>4096) ct=4096;
    int mtake=need-above2;
    int pos0=above+above2;
    for(int ti=tid;ti<ct;ti+=1024){
        int myi=tiebuf[ti];
        int rank=0;
        for(int q=0;q<ct;q++) rank+=(tiebuf[q]<myi);
        if(rank<mtake)
            sbuf[pos0+rank]=(((unsigned long long)T)<<32)|(unsigned)(~(unsigned)myi);
    }
    __syncthreads();
    if(tid>=k&&tid<1024) sbuf[tid]=0ull;
}

__global__ void bitonic_lvl(){
    unsigned long long* a=g.sbufL[blockIdx.x];
    const int n=1024;
    for(int k=2;k<=n;k<<=1){
        for(int j=k>>1;j>0;j>>=1){
            for(int i=threadIdx.x;i<n;i+=blockDim.x){
                int l=i^j;
                if(l>i){
                    unsigned long long x=a[i],y=a[l];
                    bool sw=((i&k)==0)?(x<y):(x>y);
                    if(sw){ a[i]=y; a[l]=x; }
                }
            }
            __syncthreads();
        }
    }
}

__global__ void bitonic_desc(int n){
    unsigned long long* a=g.sbuf[blockIdx.x];
    for(int k=2;k<=n;k<<=1){
        for(int j=k>>1;j>0;j>>=1){
            for(int i=threadIdx.x;i<n;i+=blockDim.x){
                int l=i^j;
                if(l>i){
                    unsigned long long x=a[i],y=a[l];
                    bool sw=((i&k)==0)?(x<y):(x>y);
                    if(sw){ a[i]=y; a[l]=x; }
                }
            }
            __syncthreads();
        }
    }
}

__global__ void rpn_decode_all(const float* __restrict__ iminfo){
    int inst=blockIdx.x;
    int lvl=inst>>1, b=inst&1;
    int k=cK5[lvl], W=cW[lvl];
    int r=threadIdx.x;
    if(r>=k) return;
    unsigned long long key=g.sbufL[inst][r];
    int i=(int)(~(unsigned)key);
    int a=i%3; int pix=i/3; int x=pix%W; int y=pix/W;
    double stride=(double)(1<<(lvl+2));
    double size=8.0*stride;
    double rr=(a==0)?1.0:((a==1)?0.5:2.0);
    double sr=sqrt(rr);
    double hh=size/sr, ww=size*sr;
    double ycd=((double)y+0.5)*stride, xcd=((double)x+0.5)*stride;
    float ya1=(float)(ycd-hh*0.5), xa1=(float)(xcd-ww*0.5);
    float ya2=(float)(ycd+hh*0.5), xa2=(float)(xcd+ww*0.5);
    const float* d=&g.deltas[b][(size_t)(cSOff[lvl]+i)*4];
    float ha=ya2-ya1, wa=xa2-xa1;
    float yc=ya1+0.5f*ha, xc=xa1+0.5f*wa;
    float dy=d[0], dx=d[1];
    float dh=fminf(d[2],CLIPV), dw=fminf(d[3],CLIPV);
    float pcy=dy*ha+yc, pcx=dx*wa+xc;
    float ph=expf(dh)*ha, pw=expf(dw)*wa;
    float hI=iminfo[b*5+0], wI=iminfo[b*5+1];
    g.pbL[inst][r*4+0]=fminf(fmaxf(pcy-0.5f*ph,0.f),hI);
    g.pbL[inst][r*4+1]=fminf(fmaxf(pcx-0.5f*pw,0.f),wI);
    g.pbL[inst][r*4+2]=fminf(fmaxf(pcy+0.5f*ph,0.f),hI);
    g.pbL[inst][r*4+3]=fminf(fmaxf(pcx+0.5f*pw,0.f),wI);
    g.psL[inst][r]=g.scores[b][cSOff[lvl]+i];
}

__global__ void nms_level_all(){
    __shared__ float y1[1000],x1[1000],y2[1000],x2[1000],s[1000];
    __shared__ int sp,sj;
    int inst=blockIdx.x;
    int lvl=inst>>1, b=inst&1;
    int k=cK5[lvl], off=cOffCat[lvl];
    int tid=threadIdx.x;
    float* ob=&g.catb[b][off*4];
    float* os=&g.cats[b][off];
    for(int i=tid;i<k;i+=256){
        y1[i]=g.pbL[inst][i*4+0]; x1[i]=g.pbL[inst][i*4+1];
        y2[i]=g.pbL[inst][i*4+2]; x2[i]=g.pbL[inst][i*4+3];
        s[i]=g.psL[inst][i];
    }
    if(tid==0) sp=0;
    __syncthreads();
    for(int it=0;it<k;it++){
        if(tid==0){
            int p=sp;
            while(p<k && s[p]<=NEGF*0.5f) p++;
            sj=(p<k)?p:-1; sp=p;
        }
        __syncthreads();
        int j=sj;
        if(j<0){
            for(int r=it+tid;r<k;r+=256){
                os[r]=NEGF;
                ob[r*4+0]=0.f; ob[r*4+1]=0.f; ob[r*4+2]=0.f; ob[r*4+3]=0.f;
            }
            return;
        }
        float a1=y1[j],a2=x1[j],a3=y2[j],a4=x2[j];
        float js=s[j];
        __syncthreads();
        float aA=(a3-a1)*(a4-a2);
        for(int i=tid;i<k;i+=256){
            float yy1=fmaxf(a1,y1[i]), xx1=fmaxf(a2,x1[i]);
            float yy2=fminf(a3,y2[i]), xx2=fminf(a4,x2[i]);
            float inter=fmaxf(yy2-yy1,0.f)*fmaxf(xx2-xx1,0.f);
            float bA=(y2[i]-y1[i])*(x2[i]-x1[i]);
            float iou=inter/(aA+bA-inter+1e-8f);
            if(iou>=0.7f) s[i]=NEGF;
        }
        __syncthreads();
        if(tid==0){
            s[j]=NEGF;
            os[it]=js;
            ob[it*4+0]=a1; ob[it*4+1]=a2; ob[it*4+2]=a3; ob[it*4+3]=a4;
        }
        __syncthreads();
    }
}

__device__ void nms_run(float* y1,float* x1,float* y2,float* x2,float* s,
                        int n,int iters,float th,float* ob,float* os){
    __shared__ float rv[256];
    __shared__ int ri[256];
    __shared__ float cb[4];
    int tid=threadIdx.x;
    for(int it=0;it<iters;it++){
        float bv=-3.0e38f; int bi=1<<30;
        for(int i=tid;i<n;i+=256){
            float v=s[i];
            if(v>bv||(v==bv&&i<bi)){ bv=v; bi=i; }
        }
        rv[tid]=bv; ri[tid]=bi; __syncthreads();
        for(int o=128;o>0;o>>=1){
            if(tid<o){
                float v=rv[tid+o]; int j=ri[tid+o];
                if(v>rv[tid]||(v==rv[tid]&&j<ri[tid])){ rv[tid]=v; ri[tid]=j; }
            }
            __syncthreads();
        }
        int j=ri[0]; float js=rv[0];
        if(js<=NEGF*0.5f){
            for(int r=it+tid;r<iters;r+=256){
                os[r]=NEGF;
                ob[r*4+0]=0.f; ob[r*4+1]=0.f; ob[r*4+2]=0.f; ob[r*4+3]=0.f;
            }
            __syncthreads();
            return;
        }
        if(tid==0){ cb[0]=y1[j]; cb[1]=x1[j]; cb[2]=y2[j]; cb[3]=x2[j]; }
        __syncthreads();
        float a1=cb[0],a2=cb[1],a3=cb[2],a4=cb[3];
        float aA=(a3-a1)*(a4-a2);
        for(int i=tid;i<n;i+=256){
            float yy1=fmaxf(a1,y1[i]), xx1=fmaxf(a2,x1[i]);
            float yy2=fminf(a3,y2[i]), xx2=fminf(a4,x2[i]);
            float inter=fmaxf(yy2-yy1,0.f)*fmaxf(xx2-xx1,0.f);
            float bA=(y2[i]-y1[i])*(x2[i]-x1[i]);
            float iou=inter/(aA+bA-inter+1e-8f);
            if(iou>=th) s[i]=NEGF;
        }
        __syncthreads();
        if(tid==0){
            s[j]=NEGF;
            os[it]=js;
            ob[it*4+0]=a1; ob[it*4+1]=a2; ob[it*4+2]=a3; ob[it*4+3]=a4;
        }
        __syncthreads();
    }
}

__global__ void build_cat_keys(){
    int b=blockIdx.x;
    for(int i=threadIdx.x;i<8192;i+=blockDim.x){
        unsigned long long key=0ull;
        if(i<4819) key=(((unsigned long long)skey(g.cats[b][i]))<<32)|(unsigned)(~(unsigned)i);
        g.sbuf[b][i]=key;
    }
}

__global__ void gather_rois(){
    int b=blockIdx.x;
    for(int r=threadIdx.x;r<1000;r+=blockDim.x){
        int i=(int)(~(unsigned)g.sbuf[b][r]);
        for(int d=0;d<4;d++) g.rois[b][r*4+d]=g.catb[b][i*4+d];
    }
}

// ---------------- multilevel ROI align -> bf16 roifeat --------------------
__global__ void roialign(const float* f0,const float* f1,const float* f2,
                         const float* f3,const float* f4){
    int br=blockIdx.x; int b=br/1000;
    int c=threadIdx.x;
    const float* ro=&g.rois[b][(br%1000)*4];
    float y1=ro[0],x1=ro[1],y2=ro[2],x2=ro[3];
    float area=fmaxf((y2-y1)*(x2-x1),1e-6f);
    float lv=floorf(4.f+log2f(sqrtf(area)/224.f));
    lv=fminf(fmaxf(lv,2.f),6.f);
    int li=(int)lv-2;
    const float* fp=(li==0)?f0:(li==1)?f1:(li==2)?f2:(li==3)?f3:f4;
    int H=cH[li],W=cW[li];
    float Hf=(float)H,Wf=(float)W;
    float stride=cStrideF[li];
    const float* base=fp+(size_t)b*H*W*256;
    __nv_bfloat16* outp=&g.roifeatb[(size_t)br*12544];
    for(int p=0;p<49;p++){
        int py=p/7,px=p%7;
        float uy=((float)py+0.5f)/7.f, ux=((float)px+0.5f)/7.f;
        float ys=(y1+(y2-y1)*uy)/stride-0.5f;
        float xs=(x1+(x2-x1)*ux)/stride-0.5f;
        ys=fminf(fmaxf(ys,0.f),Hf-1.f);
        xs=fminf(fmaxf(xs,0.f),Wf-1.f);
        float y0=floorf(ys),x0=floorf(xs);
        float wy=ys-y0,wx=xs-x0;
        int y0i=(int)y0,x0i=(int)x0;
        int y1i=min(y0i+1,H-1),x1i=min(x0i+1,W-1);
        const float* p00=base+((size_t)y0i*W+x0i)*256;
        const float* p01=base+((size_t)y0i*W+x1i)*256;
        const float* p10=base+((size_t)y1i*W+x0i)*256;
        const float* p11=base+((size_t)y1i*W+x1i)*256;
        float w00=(1.f-wy)*(1.f-wx), w01=(1.f-wy)*wx;
        float w10=wy*(1.f-wx), w11=wy*wx;
        float v=p00[c]*w00+p01[c]*w01+p10[c]*w10+p11[c]*w11;
        outp[p*256+c]=__float2bfloat16_rn(v);
    }
}

__global__ void softmax91(){
    int i=blockIdx.x*blockDim.x+threadIdx.x;
    if(i>=2000) return;
    float* p=&g.clsl[(size_t)i*91];
    float mx=p[0];
    for(int c=1;c<91;c++) mx=fmaxf(mx,p[c]);
    float sm=0.f;
    float e[91];
    for(int c=0;c<91;c++){ e[c]=expf(p[c]-mx); sm+=e[c]; }
    for(int c=0;c<91;c++) p[c]=e[c]/sm;
}

__global__ void nms_det(const float* __restrict__ iminfo){
    __shared__ float y1[1000],x1[1000],y2[1000],x2[1000],s[1000];
    int blk=blockIdx.x; int b=blk/90; int c=blk%90+1;
    int tid=threadIdx.x;
    float hI=iminfo[b*5+0], wI=iminfo[b*5+1];
    for(int i=tid;i<1000;i+=256){
        const float* ro=&g.rois[b][i*4];
        float ya1=ro[0],xa1=ro[1],ya2=ro[2],xa2=ro[3];
        float ha=ya2-ya1, wa=xa2-xa1;
        float yc=ya1+0.5f*ha, xc=xa1+0.5f*wa;
        const float* d=&g.boxl[((size_t)(b*1000+i)*91+c)*4];
        float dy=d[0]/10.f, dx=d[1]/10.f;
        float dh=fminf(d[2]/5.f,CLIPV), dw=fminf(d[3]/5.f,CLIPV);
        float pcy=dy*ha+yc, pcx=dx*wa+xc;
        float ph=expf(dh)*ha, pw=expf(dw)*wa;
        y1[i]=fminf(fmaxf(pcy-0.5f*ph,0.f),hI);
        x1[i]=fminf(fmaxf(pcx-0.5f*pw,0.f),wI);
        y2[i]=fminf(fmaxf(pcy+0.5f*ph,0.f),hI);
        x2[i]=fminf(fmaxf(pcx+0.5f*pw,0.f),wI);
        float p=g.clsl[(size_t)(b*1000+i)*91+c];
        s[i]=(p>=0.05f)?p:NEGF;
    }
    __syncthreads();
    nms_run(y1,x1,y2,x2,s,1000,100,0.5f,&g.dnb[b][(c-1)*400],&g.dns[b][(c-1)*100]);
}

__global__ void build_det_keys(){
    int b=blockIdx.x;
    for(int i=threadIdx.x;i<16384;i+=blockDim.x){
        unsigned long long key=0ull;
        if(i<9000) key=(((unsigned long long)skey(g.dns[b][i]))<<32)|(unsigned)(~(unsigned)i);
        g.sbuf[b][i]=key;
    }
}

__global__ void write_out(float* out,int out_size){
    int tid=threadIdx.x;
    for(int i=tid;i<out_size;i+=256) out[i]=0.f;
    __syncthreads();
    __shared__ int cnt;
    for(int b=0;b<2;b++){
        if(tid==0) cnt=0;
        __syncthreads();
        if(tid<100){
            int r=tid;
            int idx=(int)(~(unsigned)g.sbuf[b][r]);
            float sc=g.dns[b][idx];
            bool valid=sc>0.f;
            if(valid) atomicAdd(&cnt,1);
            float cls=valid?(float)(idx/100+1):0.f;
            int ob=2+b*400+r*4;
            for(int d=0;d<4;d++){
                int o=ob+d;
                if(o<out_size) out[o]=valid?g.dnb[b][idx*4+d]:0.f;
            }
            int oc=2+800+b*100+r;
            if(oc<out_size) out[oc]=cls;
            int os=2+1000+b*100+r;
            if(os<out_size) out[os]=valid?sc:0.f;
        }
        __syncthreads();
        if(tid==0&&b<out_size) out[b]=(float)cnt;
        __syncthreads();
    }
}

extern "C" void kernel_launch(void* const* d_in,const int* in_sizes,int n_in,
                              void* d_out,int out_size){
    const float* feats[5];
    for(int i=0;i<5;i++) feats[i]=(const float*)d_in[i];
    const float* iminfo=(const float*)d_in[5];
    const float* cw =(const float*)d_in[6];
    const float* cbv=(const float*)d_in[7];
    const float* sw =(const float*)d_in[8];
    const float* sb =(const float*)d_in[9];
    const float* bw =(const float*)d_in[10];
    const float* bbv=(const float*)d_in[11];
    const float* fc1w=(const float*)d_in[12];
    const float* fc1b=(const float*)d_in[13];
    const float* fc2w=(const float*)d_in[14];
    const float* fc2b=(const float*)d_in[15];
    const float* clsw=(const float*)d_in[16];
    const float* clsb=(const float*)d_in[17];
    const float* boxw=(const float*)d_in[18];
    const float* boxb=(const float*)d_in[19];

    Scratch* gp=nullptr;
    cudaGetSymbolAddress((void**)&gp,g);

    int Hs[5]={208,104,52,26,13}, Ws[5]={336,168,84,42,21};
    int hOff[5]={0,139776,174720,183456,185640};

    init_kernel<<<1,32>>>();                                              // 0
    cvt_feats<<<dim3(17472,5),256>>>(feats[0],feats[1],feats[2],feats[3],feats[4]); // 1
    twcvt<<<dim3(72,8),dim3(32,8)>>>(cw,gp->cwT,2304,256,256);            // 2
    {   // convs: l6(3), l5(4), l2(5 = ncu slot), l4(6), l3(7)
        int order[5]={4,3,0,2,1};
        for(int oi=0;oi<5;oi++){
            int i=order[oi];
            int H=Hs[i],W=Ws[i],M=2*H*W;
            dim3 gr(2,(M+127)/128);
            gemm_bf16<1,false,true><<<gr,256>>>(
                gp->featsbf+(size_t)hOff[i]*256,gp->cwT,cbv,
                gp->h+(size_t)hOff[i]*256,M,256,2304,H,W);
        }
    }
    twcvt<<<dim3(392,32),dim3(32,8)>>>(fc1w,gp->fc1wT,12544,1024,1024);
    twcvt<<<dim3(32,32),dim3(32,8)>>>(fc2w,gp->fc2wT,1024,1024,1024);
    twcvt<<<dim3(32,4),dim3(32,8)>>>(clsw,gp->clswT,1024,91,128);
    twcvt<<<dim3(32,12),dim3(32,8)>>>(boxw,gp->boxwT,1024,364,384);
    padbias<<<1,512>>>(clsb,boxb);

    rpn_head_all<<<dim3(546,5),256>>>(sw,sb,bw,bbv);
    select_topk_all<<<10,1024>>>();
    bitonic_lvl<<<10,1024>>>();
    rpn_decode_all<<<10,1024>>>(iminfo);
    nms_level_all<<<10,256>>>();

    build_cat_keys<<<2,256>>>();
    bitonic_desc<<<2,1024>>>(8192);
    gather_rois<<<2,256>>>();

    roialign<<<2000,256>>>(feats[0],feats[1],feats[2],feats[3],feats[4]);

    gemm_bf16<0,true ,true ><<<dim3(8,16),256>>>(gp->roifeatb,gp->fc1wT,fc1b,gp->h1b,2000,1024,12544,0,0);
    gemm_bf16<0,true ,true ><<<dim3(8,16),256>>>(gp->h1b,gp->fc2wT,fc2b,gp->h2b,2000,1024,1024,0,0);
    gemm_bf16<0,false,false><<<dim3(1,16),256>>>(gp->h2b,gp->clswT,gp->clsbPad,gp->clsl,2000,91,1024,0,0);
    gemm_bf16<0,false,false><<<dim3(3,16),256>>>(gp->h2b,gp->boxwT,gp->boxbPad,gp->boxl,2000,364,1024,0,0);

    softmax91<<<8,256>>>();
    nms_det<<<180,256>>>(iminfo);
    build_det_keys<<<2,256>>>();
    bitonic_desc<<<2,1024>>>(16384);
    write_out<<<1,256>>>((float*)d_out,out_size);
}

// round 12
// speedup vs baseline: 7.1018x; 1.2645x over previous
#include <cuda_runtime.h>
#include <cuda_bf16.h>
#include <math.h>
#include <stddef.h>

#define NEGF (-1.0e9f)
#define CLIPV 4.135166556742356f

__device__ __forceinline__ unsigned skey(float s){
    unsigned u = __float_as_uint(s);
    return (u & 0x80000000u) ? ~u : (u | 0x80000000u);
}

struct __align__(256) Scratch {
    float h[47663616];
    float scores[2][279280];
    float deltas[2][1117120];
    unsigned histL[10][65536];
    int tiebufL[10][4096];
    int tiecntL[10];
    int selcntL[10];
    unsigned long long sbufL[10][1024];
    float pbL[10][4000];
    float psL[10][1000];
    float catb[2][19280];
    float cats[2][4820];
    float rois[2][4000];
    float clsl[182000];
    float boxl[728000];
    float dns[2][9000];
    float dnb[2][36000];
    float clsbPad[128];
    float boxbPad[384];
    __nv_bfloat16 featsbf[47663616];
    __nv_bfloat16 cwT[256*2304];
    __nv_bfloat16 fc1wT[1024*12544];
    __nv_bfloat16 fc2wT[1024*1024];
    __nv_bfloat16 clswT[128*1024];
    __nv_bfloat16 boxwT[384*1024];
    __nv_bfloat16 roifeatb[25088000];
    __nv_bfloat16 h1b[2048000];
    __nv_bfloat16 h2b[2048000];
};
__device__ Scratch g;

__constant__ int cH[5]={208,104,52,26,13};
__constant__ int cW[5]={336,168,84,42,21};
__constant__ float cStrideF[5]={4.f,8.f,16.f,32.f,64.f};
__constant__ int cNl5[5]={209664,52416,13104,3276,819};
__constant__ int cK5[5]={1000,1000,1000,1000,819};
__constant__ int cSOff[5]={0,209664,262080,275184,278460};
__constant__ int cHOff[5]={0,139776,174720,183456,185640};
__constant__ int cOffCat[5]={0,1000,2000,3000,4000};

// ---- convert feats fp32 NHWC -> bf16 (per level) --------------------------
__global__ void cvt_feats(const float* f0,const float* f1,const float* f2,
                          const float* f3,const float* f4){
    int lvl=blockIdx.y;
    const float* src=(lvl==0)?f0:(lvl==1)?f1:(lvl==2)?f2:(lvl==3)?f3:f4;
    int Etot=2*cH[lvl]*cW[lvl]*256;
    int base=(blockIdx.x*256+threadIdx.x)*8;
    if(base>=Etot) return;
    float4 a=*(const float4*)(src+base);
    float4 b=*(const float4*)(src+base+4);
    __nv_bfloat162 r0=__floats2bfloat162_rn(a.x,a.y);
    __nv_bfloat162 r1=__floats2bfloat162_rn(a.z,a.w);
    __nv_bfloat162 r2=__floats2bfloat162_rn(b.x,b.y);
    __nv_bfloat162 r3=__floats2bfloat162_rn(b.z,b.w);
    uint4 o=make_uint4(*(unsigned*)&r0,*(unsigned*)&r1,*(unsigned*)&r2,*(unsigned*)&r3);
    *(uint4*)(g.featsbf+(size_t)cHOff[lvl]*256+base)=o;
}

// ---- transpose + convert weights: src[K][N] fp32 -> dst[Npad][K] bf16 -----
__global__ void twcvt(const float* __restrict__ src,__nv_bfloat16* __restrict__ dst,
                      int K,int N,int Npad){
    __shared__ float t[32][33];
    int kb=blockIdx.x*32, nb=blockIdx.y*32;
    int tx=threadIdx.x, ty=threadIdx.y;
#pragma unroll
    for(int d=0;d<4;d++){
        int k=kb+ty+d*8, n=nb+tx;
        t[ty+d*8][tx]=(k<K&&n<N)?src[(size_t)k*N+n]:0.f;
    }
    __syncthreads();
#pragma unroll
    for(int d=0;d<4;d++){
        int n=nb+ty+d*8, k=kb+tx;
        if(n<Npad&&k<K) dst[(size_t)n*K+k]=__float2bfloat16_rn(t[tx][ty+d*8]);
    }
}

__global__ void padbias(const float* clsb,const float* boxb){
    int i=threadIdx.x;
    if(i<128) g.clsbPad[i]=(i<91)?clsb[i]:0.f;
    if(i<384) g.boxbPad[i]=(i<364)?boxb[i]:0.f;
}

// ============ BF16 GEMM 128x128x32 (m16n8k16, fp32 acc), bf16 inputs ======
// MODE 0: dense A[M][K] bf16. MODE 2: fused all-level 3x3 conv over concat M.
// B: bf16 [Npad][K] (pre-transposed). OUTBF: store bf16 else fp32. K%32==0.
#define BPADW 20
template<int MODE,bool OUTBF,bool RELU>
__global__ void __launch_bounds__(256,2)
gemm_bf16(const __nv_bfloat16* __restrict__ A,const __nv_bfloat16* __restrict__ Bw,
          const float* __restrict__ bias,void* __restrict__ Cout,
          int M,int N,int K){
    __shared__ unsigned Ah[2][128*BPADW];
    __shared__ unsigned Bh[2][128*BPADW];
    int tid=threadIdx.x;
    int bm=blockIdx.y*128, bn=blockIdx.x*128;
    int wid=tid>>5, lane=tid&31;
    int wm=wid&3, wn=wid>>2;
    int lr=lane>>2, lc=lane&3;

    float acc[2][8][4];
#pragma unroll
    for(int i=0;i<2;i++)
#pragma unroll
        for(int j=0;j<8;j++)
#pragma unroll
            for(int q=0;q<4;q++) acc[i][j][q]=0.f;

    int arow=tid>>1, ahalf=tid&1;
    int m=bm+arow;
    int ay=0,ax=0,Hl=0,Wl=0; size_t base0=0;
    if(MODE==2){
        int mm=(m<M)?m:0;
        int lvl=(mm>=cHOff[1])+(mm>=cHOff[2])+(mm>=cHOff[3])+(mm>=cHOff[4]);
        Hl=cH[lvl]; Wl=cW[lvl];
        int HW=Hl*Wl;
        int rel=mm-cHOff[lvl];
        int ab=rel/HW; int rem2=rel-ab*HW;
        ay=rem2/Wl; ax=rem2-ay*Wl;
        base0=(size_t)cHOff[lvl]+(size_t)ab*HW;
    }
    int bcol=tid>>1, bhalf=tid&1;

    uint4 aV0,aV1,bV0,bV1;
    auto loadG=[&](int k0){
        aV0=make_uint4(0,0,0,0); aV1=aV0;
        if(m<M){
            if(MODE==0){
                const __nv_bfloat16* p=A+(size_t)m*K+k0+ahalf*16;
                aV0=*(const uint4*)p; aV1=*(const uint4*)(p+8);
            }else{
                int r=k0>>8;
                int ky=r/3, kx=r-ky*3;
                int yy=ay+ky-1, xx=ax+kx-1;
                if(yy>=0&&yy<Hl&&xx>=0&&xx<Wl){
                    const __nv_bfloat16* p=A+(base0+(size_t)yy*Wl+xx)*256+(k0&255)+ahalf*16;
                    aV0=*(const uint4*)p; aV1=*(const uint4*)(p+8);
                }
            }
        }
        const __nv_bfloat16* q=Bw+(size_t)(bn+bcol)*K+k0+bhalf*16;
        bV0=*(const uint4*)q; bV1=*(const uint4*)(q+8);
    };
    auto storeS=[&](int stg){
        unsigned* Ad=&Ah[stg][arow*BPADW+ahalf*8];
        *(uint4*)Ad=aV0; *(uint4*)(Ad+4)=aV1;
        unsigned* Bd=&Bh[stg][bcol*BPADW+bhalf*8];
        *(uint4*)Bd=bV0; *(uint4*)(Bd+4)=bV1;
    };

    int T=K>>5;
    loadG(0); storeS(0);
    __syncthreads();
    for(int t=0;t<T;t++){
        int cur=t&1, nxt=cur^1;
        if(t+1<T) loadG((t+1)*32);
        const unsigned* Ac=Ah[cur];
        const unsigned* Bc=Bh[cur];
#pragma unroll
        for(int ks=0;ks<2;ks++){
            int kb=ks*8;
            unsigned af[2][4];
#pragma unroll
            for(int mt=0;mt<2;mt++){
                int r0=wm*32+mt*16+lr;
                af[mt][0]=Ac[r0*BPADW+kb+lc];
                af[mt][1]=Ac[(r0+8)*BPADW+kb+lc];
                af[mt][2]=Ac[r0*BPADW+kb+lc+4];
                af[mt][3]=Ac[(r0+8)*BPADW+kb+lc+4];
            }
#pragma unroll
            for(int nt=0;nt<8;nt++){
                int cb=wn*64+nt*8+lr;
                unsigned b0=Bc[cb*BPADW+kb+lc];
                unsigned b1=Bc[cb*BPADW+kb+lc+4];
#pragma unroll
                for(int mt=0;mt<2;mt++){
                    asm volatile(
                      "mma.sync.aligned.m16n8k16.row.col.f32.bf16.bf16.f32 "
                      "{%0,%1,%2,%3}, {%4,%5,%6,%7}, {%8,%9}, {%0,%1,%2,%3};\n"
                      : "+f"(acc[mt][nt][0]),"+f"(acc[mt][nt][1]),
                        "+f"(acc[mt][nt][2]),"+f"(acc[mt][nt][3])
                      : "r"(af[mt][0]),"r"(af[mt][1]),"r"(af[mt][2]),"r"(af[mt][3]),
                        "r"(b0),"r"(b1));
                }
            }
        }
        if(t+1<T) storeS(nxt);
        __syncthreads();
    }
#pragma unroll
    for(int mt=0;mt<2;mt++){
#pragma unroll
        for(int nt=0;nt<8;nt++){
            int r0=bm+wm*32+mt*16+lr;
            int c0=bn+wn*64+nt*8+lc*2;
            float b0=bias[c0], b1=bias[c0+1];
            float v0=acc[mt][nt][0]+b0, v1=acc[mt][nt][1]+b1;
            float v2=acc[mt][nt][2]+b0, v3=acc[mt][nt][3]+b1;
            if(RELU){ v0=fmaxf(v0,0.f); v1=fmaxf(v1,0.f); v2=fmaxf(v2,0.f); v3=fmaxf(v3,0.f); }
            if(OUTBF){
                __nv_bfloat16* C=(__nv_bfloat16*)Cout;
                if(r0<M){
                    if(c0<N)   C[(size_t)r0*N+c0]  =__float2bfloat16_rn(v0);
                    if(c0+1<N) C[(size_t)r0*N+c0+1]=__float2bfloat16_rn(v1);
                }
                if(r0+8<M){
                    if(c0<N)   C[(size_t)(r0+8)*N+c0]  =__float2bfloat16_rn(v2);
                    if(c0+1<N) C[(size_t)(r0+8)*N+c0+1]=__float2bfloat16_rn(v3);
                }
            }else{
                float* C=(float*)Cout;
                if(r0<M){
                    if(c0<N)   C[(size_t)r0*N+c0]=v0;
                    if(c0+1<N) C[(size_t)r0*N+c0+1]=v1;
                }
                if(r0+8<M){
                    if(c0<N)   C[(size_t)(r0+8)*N+c0]=v2;
                    if(c0+1<N) C[(size_t)(r0+8)*N+c0+1]=v3;
                }
            }
        }
    }
}

__global__ void init_kernel(){
    int i=threadIdx.x;
    if(i<10){ g.tiecntL[i]=0; g.selcntL[i]=0; }
}

// ---------------- fused RPN head over all levels --------------------------
__global__ void rpn_head_all(const float* __restrict__ sw,const float* __restrict__ sb,
    const float* __restrict__ bw,const float* __restrict__ bb){
    __shared__ float wsm[256][16];
    __shared__ float bsm[16];
    int tid=threadIdx.x;
    int lvl=blockIdx.y;
    int H=cH[lvl],W=cW[lvl];
    int HW=H*W, Btot=2*HW;
    for(int i=tid;i<256*16;i+=blockDim.x){
        int c=i>>4, j=i&15;
        float v=0.f;
        if(j<3) v=sw[c*3+j];
        else if(j<15) v=bw[c*12+(j-3)];
        wsm[c][j]=v;
    }
    if(tid<16) bsm[tid]=(tid<3)?sb[tid]:((tid<15)?bb[tid-3]:0.f);
    __syncthreads();
    int m=blockIdx.x*blockDim.x+tid;
    if(m>=Btot) return;
    int b=m/HW, pix=m-b*HW;
    const float* hr=g.h+((size_t)cHOff[lvl]+m)*256;
    int soff=cSOff[lvl];
    float acc[15];
#pragma unroll
    for(int j=0;j<15;j++) acc[j]=0.f;
    for(int c=0;c<256;c+=4){
        float4 v=*(const float4*)(hr+c);
#pragma unroll
        for(int j=0;j<15;j++)
            acc[j]+=v.x*wsm[c][j]+v.y*wsm[c+1][j]+v.z*wsm[c+2][j]+v.w*wsm[c+3][j];
    }
    for(int a=0;a<3;a++){
        float lg=acc[a]+bsm[a];
        g.scores[b][soff+pix*3+a]=1.f/(1.f+expf(-lg));
        for(int d=0;d<4;d++)
            g.deltas[b][(size_t)(soff+pix*3+a)*4+d]=acc[3+a*4+d]+bsm[3+a*4+d];
    }
}

// ------------- fused exact stable top-k: grid = 10 instances --------------
__global__ void select_topk_all(){
    int inst=blockIdx.x;
    int lvl=inst>>1, b=inst&1;
    int Nl=cNl5[lvl], k=cK5[lvl];
    const float* s=&g.scores[b][cSOff[lvl]];
    unsigned* hist=g.histL[inst];
    int* tiebuf=g.tiebufL[inst];
    unsigned long long* sbuf=g.sbufL[inst];
    int tid=threadIdx.x;
    __shared__ unsigned csum[1024];
    __shared__ int s_t,s_above,s_u,s_above2;
    if(tid==0){ g.selcntL[inst]=0; g.tiecntL[inst]=0; }
    for(int i=tid;i<65536;i+=1024) __stcg(&hist[i],0u);
    __syncthreads();
    for(int i=tid;i<Nl;i+=1024) atomicAdd(&hist[skey(s[i])>>16],1u);
    __syncthreads();
    {
        unsigned own=0; int base=65535-tid*64;
        for(int q=0;q<64;q++) own+=__ldcg(&hist[base-q]);
        csum[tid]=own; __syncthreads();
        for(int off=1;off<1024;off<<=1){
            unsigned v=csum[tid]; unsigned add=(tid>=off)?csum[tid-off]:0u; __syncthreads();
            csum[tid]=v+add; __syncthreads();
        }
        unsigned excl=csum[tid]-own;
        if(excl<(unsigned)k&&csum[tid]>=(unsigned)k){
            unsigned cum=excl;
            for(int q=0;q<64;q++){
                unsigned c=__ldcg(&hist[base-q]);
                if(cum+c>=(unsigned)k){ s_t=base-q; s_above=(int)cum; break; }
                cum+=c;
            }
        }
        __syncthreads();
    }
    int t=s_t, above=s_above;
    for(int i=tid;i<65536;i+=1024) __stcg(&hist[i],0u);
    __syncthreads();
    for(int i=tid;i<Nl;i+=1024){
        unsigned key=skey(s[i]);
        if((int)(key>>16)==t) atomicAdd(&hist[key&0xFFFFu],1u);
    }
    __syncthreads();
    int need=k-above;
    {
        unsigned own=0; int base=65535-tid*64;
        for(int q=0;q<64;q++) own+=__ldcg(&hist[base-q]);
        csum[tid]=own; __syncthreads();
        for(int off=1;off<1024;off<<=1){
            unsigned v=csum[tid]; unsigned add=(tid>=off)?csum[tid-off]:0u; __syncthreads();
            csum[tid]=v+add; __syncthreads();
        }
        unsigned excl=csum[tid]-own;
        if(excl<(unsigned)need&&csum[tid]>=(unsigned)need){
            unsigned cum=excl;
            for(int q=0;q<64;q++){
                unsigned c=__ldcg(&hist[base-q]);
                if(cum+c>=(unsigned)need){ s_u=base-q; s_above2=(int)cum; break; }
                cum+=c;
            }
        }
        __syncthreads();
    }
    int u=s_u, above2=s_above2;
    unsigned T=(((unsigned)t)<<16)|(unsigned)u;
    for(int i=tid;i<Nl;i+=1024){
        unsigned key=skey(s[i]);
        if(key>T){
            int pos=atomicAdd(&g.selcntL[inst],1);
            sbuf[pos]=(((unsigned long long)key)<<32)|(unsigned)(~(unsigned)i);
        }else if(key==T){
            int p=atomicAdd(&g.tiecntL[inst],1);
            if(p<4096) tiebuf[p]=i;
        }
    }
    __syncthreads();
    int ct=g.tiecntL[inst]; if(ct>4096) ct=4096;
    int mtake=need-above2;
    int pos0=above+above2;
    for(int ti=tid;ti<ct;ti+=1024){
        int myi=tiebuf[ti];
        int rank=0;
        for(int q=0;q<ct;q++) rank+=(tiebuf[q]<myi);
        if(rank<mtake)
            sbuf[pos0+rank]=(((unsigned long long)T)<<32)|(unsigned)(~(unsigned)myi);
    }
    __syncthreads();
    if(tid>=k&&tid<1024) sbuf[tid]=0ull;
}

// smem bitonic sort of each instance's 1024 keys (descending)
__global__ void bitonic_lvl(){
    __shared__ unsigned long long a[1024];
    int tid=threadIdx.x;
    a[tid]=g.sbufL[blockIdx.x][tid];
    __syncthreads();
    for(int k=2;k<=1024;k<<=1){
        for(int j=k>>1;j>0;j>>=1){
            int l=tid^j;
            if(l>tid){
                unsigned long long x=a[tid],y=a[l];
                bool sw=((tid&k)==0)?(x<y):(x>y);
                if(sw){ a[tid]=y; a[l]=x; }
            }
            __syncthreads();
        }
    }
    g.sbufL[blockIdx.x][tid]=a[tid];
}

__global__ void rpn_decode_all(const float* __restrict__ iminfo){
    int inst=blockIdx.x;
    int lvl=inst>>1, b=inst&1;
    int k=cK5[lvl], W=cW[lvl];
    int r=threadIdx.x;
    if(r>=k) return;
    unsigned long long key=g.sbufL[inst][r];
    int i=(int)(~(unsigned)key);
    int a=i%3; int pix=i/3; int x=pix%W; int y=pix/W;
    double stride=(double)(1<<(lvl+2));
    double size=8.0*stride;
    double rr=(a==0)?1.0:((a==1)?0.5:2.0);
    double sr=sqrt(rr);
    double hh=size/sr, ww=size*sr;
    double ycd=((double)y+0.5)*stride, xcd=((double)x+0.5)*stride;
    float ya1=(float)(ycd-hh*0.5), xa1=(float)(xcd-ww*0.5);
    float ya2=(float)(ycd+hh*0.5), xa2=(float)(xcd+ww*0.5);
    const float* d=&g.deltas[b][(size_t)(cSOff[lvl]+i)*4];
    float ha=ya2-ya1, wa=xa2-xa1;
    float yc=ya1+0.5f*ha, xc=xa1+0.5f*wa;
    float dy=d[0], dx=d[1];
    float dh=fminf(d[2],CLIPV), dw=fminf(d[3],CLIPV);
    float pcy=dy*ha+yc, pcx=dx*wa+xc;
    float ph=expf(dh)*ha, pw=expf(dw)*wa;
    float hI=iminfo[b*5+0], wI=iminfo[b*5+1];
    g.pbL[inst][r*4+0]=fminf(fmaxf(pcy-0.5f*ph,0.f),hI);
    g.pbL[inst][r*4+1]=fminf(fmaxf(pcx-0.5f*pw,0.f),wI);
    g.pbL[inst][r*4+2]=fminf(fmaxf(pcy+0.5f*ph,0.f),hI);
    g.pbL[inst][r*4+3]=fminf(fmaxf(pcx+0.5f*pw,0.f),wI);
    g.psL[inst][r]=g.scores[b][cSOff[lvl]+i];
}

// ---- RPN NMS v2: parallel IoU bitmask + single-warp sweep (exact) --------
// smem: y1,x1,y2,x2,s [1024 each] + mask[1000*32 u32] + rem[32] + outp
__global__ void __launch_bounds__(1024,1) nms_lvl_v2(){
    extern __shared__ float smf[];
    float* y1=smf; float* x1=smf+1024; float* y2=smf+2048; float* x2=smf+3072;
    float* s=smf+4096;
    unsigned* mask=(unsigned*)(smf+5120);
    unsigned* rem=mask+32000;
    int* shoutp=(int*)(rem+32);
    int inst=blockIdx.x;
    int lvl=inst>>1, b=inst&1;
    int k=cK5[lvl], off=cOffCat[lvl];
    int tid=threadIdx.x;
    float* ob=&g.catb[b][off*4];
    float* os=&g.cats[b][off];
    for(int i=tid;i<k;i+=1024){
        y1[i]=g.pbL[inst][i*4+0]; x1[i]=g.pbL[inst][i*4+1];
        y2[i]=g.pbL[inst][i*4+2]; x2[i]=g.pbL[inst][i*4+3];
        s[i]=g.psL[inst][i];
    }
    __syncthreads();
    // mask build: thread (row-group, word). 32 rows x 32 words per pass.
    int nw=(k+31)>>5;
    for(int base=0;base<k;base+=32){
        int i=base+(tid>>5);
        int w=tid&31;
        if(i<k&&w<nw){
            float a1=y1[i],a2=x1[i],a3=y2[i],a4=x2[i];
            float aA=(a3-a1)*(a4-a2);
            unsigned bits=0u;
            int j0=w*32;
            int jmax=min(32,k-j0);
            for(int q=0;q<jmax;q++){
                int j=j0+q;
                float yy1=fmaxf(a1,y1[j]), xx1=fmaxf(a2,x1[j]);
                float yy2=fminf(a3,y2[j]), xx2=fminf(a4,x2[j]);
                float inter=fmaxf(yy2-yy1,0.f)*fmaxf(xx2-xx1,0.f);
                float bA=(y2[j]-y1[j])*(x2[j]-x1[j]);
                float iou=inter/(aA+bA-inter+1e-8f);
                if(iou>=0.7f) bits|=(1u<<q);
            }
            mask[i*32+w]=bits;
        }else if(i<k&&w<32){
            mask[i*32+w]=0u;
        }
    }
    __syncthreads();
    if(tid<32){
        int lane=tid;
        rem[lane]=0u;
        __syncwarp();
        int outp=0;
        for(int i=0;i<k;i++){
            unsigned w=rem[i>>5];
            bool sel=!((w>>(i&31))&1u);
            if(sel){
                rem[lane]|=mask[i*32+lane];
                if(lane==0){
                    os[outp]=s[i];
                    ob[outp*4+0]=y1[i]; ob[outp*4+1]=x1[i];
                    ob[outp*4+2]=y2[i]; ob[outp*4+3]=x2[i];
                }
                outp++;
            }
            __syncwarp();
        }
        if(lane==0)*shoutp=outp;
    }
    __syncthreads();
    int outp=*shoutp;
    for(int r=outp+tid;r<k;r+=1024){
        os[r]=NEGF;
        ob[r*4+0]=0.f; ob[r*4+1]=0.f; ob[r*4+2]=0.f; ob[r*4+3]=0.f;
    }
}

// ---- exact rank-select over concat level results (keys unique) -----------
__global__ void cat_rank(){
    __shared__ unsigned long long keys[4819];
    int b=blockIdx.x;
    int tid=threadIdx.x;   // 1024
    for(int i=tid;i<4819;i+=1024)
        keys[i]=(((unsigned long long)skey(g.cats[b][i]))<<32)|(unsigned)(~(unsigned)i);
    __syncthreads();
    for(int i=tid;i<4819;i+=1024){
        unsigned long long me=keys[i];
        int rank=0;
        for(int j=0;j<4819;j++) rank+=(keys[j]>me);
        if(rank<1000){
            g.rois[b][rank*4+0]=g.catb[b][i*4+0];
            g.rois[b][rank*4+1]=g.catb[b][i*4+1];
            g.rois[b][rank*4+2]=g.catb[b][i*4+2];
            g.rois[b][rank*4+3]=g.catb[b][i*4+3];
        }
    }
}

// ---------------- multilevel ROI align -> bf16 roifeat --------------------
__global__ void roialign(const float* f0,const float* f1,const float* f2,
                         const float* f3,const float* f4){
    int br=blockIdx.x; int b=br/1000;
    int c=threadIdx.x;
    const float* ro=&g.rois[b][(br%1000)*4];
    float y1=ro[0],x1=ro[1],y2=ro[2],x2=ro[3];
    float area=fmaxf((y2-y1)*(x2-x1),1e-6f);
    float lv=floorf(4.f+log2f(sqrtf(area)/224.f));
    lv=fminf(fmaxf(lv,2.f),6.f);
    int li=(int)lv-2;
    const float* fp=(li==0)?f0:(li==1)?f1:(li==2)?f2:(li==3)?f3:f4;
    int H=cH[li],W=cW[li];
    float Hf=(float)H,Wf=(float)W;
    float stride=cStrideF[li];
    const float* base=fp+(size_t)b*H*W*256;
    __nv_bfloat16* outp=&g.roifeatb[(size_t)br*12544];
    for(int p=0;p<49;p++){
        int py=p/7,px=p%7;
        float uy=((float)py+0.5f)/7.f, ux=((float)px+0.5f)/7.f;
        float ys=(y1+(y2-y1)*uy)/stride-0.5f;
        float xs=(x1+(x2-x1)*ux)/stride-0.5f;
        ys=fminf(fmaxf(ys,0.f),Hf-1.f);
        xs=fminf(fmaxf(xs,0.f),Wf-1.f);
        float y0=floorf(ys),x0=floorf(xs);
        float wy=ys-y0,wx=xs-x0;
        int y0i=(int)y0,x0i=(int)x0;
        int y1i=min(y0i+1,H-1),x1i=min(x0i+1,W-1);
        const float* p00=base+((size_t)y0i*W+x0i)*256;
        const float* p01=base+((size_t)y0i*W+x1i)*256;
        const float* p10=base+((size_t)y1i*W+x0i)*256;
        const float* p11=base+((size_t)y1i*W+x1i)*256;
        float w00=(1.f-wy)*(1.f-wx), w01=(1.f-wy)*wx;
        float w10=wy*(1.f-wx), w11=wy*wx;
        float v=p00[c]*w00+p01[c]*w01+p10[c]*w10+p11[c]*w11;
        outp[p*256+c]=__float2bfloat16_rn(v);
    }
}

__global__ void softmax91(){
    int i=blockIdx.x*blockDim.x+threadIdx.x;
    if(i>=2000) return;
    float* p=&g.clsl[(size_t)i*91];
    float mx=p[0];
    for(int c=1;c<91;c++) mx=fmaxf(mx,p[c]);
    float sm=0.f;
    float e[91];
    for(int c=0;c<91;c++){ e[c]=expf(p[c]-mx); sm+=e[c]; }
    for(int c=0;c<91;c++) p[c]=e[c]/sm;
}

// -------- general sequential NMS (det path), early-exit exact -------------
__device__ void nms_run(float* y1,float* x1,float* y2,float* x2,float* s,
                        int n,int iters,float th,float* ob,float* os){
    __shared__ float rv[256];
    __shared__ int ri[256];
    __shared__ float cb[4];
    int tid=threadIdx.x;
    for(int it=0;it<iters;it++){
        float bv=-3.0e38f; int bi=1<<30;
        for(int i=tid;i<n;i+=256){
            float v=s[i];
            if(v>bv||(v==bv&&i<bi)){ bv=v; bi=i; }
        }
        rv[tid]=bv; ri[tid]=bi; __syncthreads();
        for(int o=128;o>0;o>>=1){
            if(tid<o){
                float v=rv[tid+o]; int j=ri[tid+o];
                if(v>rv[tid]||(v==rv[tid]&&j<ri[tid])){ rv[tid]=v; ri[tid]=j; }
            }
            __syncthreads();
        }
        int j=ri[0]; float js=rv[0];
        if(js<=NEGF*0.5f){
            for(int r=it+tid;r<iters;r+=256){
                os[r]=NEGF;
                ob[r*4+0]=0.f; ob[r*4+1]=0.f; ob[r*4+2]=0.f; ob[r*4+3]=0.f;
            }
            __syncthreads();
            return;
        }
        if(tid==0){ cb[0]=y1[j]; cb[1]=x1[j]; cb[2]=y2[j]; cb[3]=x2[j]; }
        __syncthreads();
        float a1=cb[0],a2=cb[1],a3=cb[2],a4=cb[3];
        float aA=(a3-a1)*(a4-a2);
        for(int i=tid;i<n;i+=256){
            float yy1=fmaxf(a1,y1[i]), xx1=fmaxf(a2,x1[i]);
            float yy2=fminf(a3,y2[i]), xx2=fminf(a4,x2[i]);
            float inter=fmaxf(yy2-yy1,0.f)*fmaxf(xx2-xx1,0.f);
            float bA=(y2[i]-y1[i])*(x2[i]-x1[i]);
            float iou=inter/(aA+bA-inter+1e-8f);
            if(iou>=th) s[i]=NEGF;
        }
        __syncthreads();
        if(tid==0){
            s[j]=NEGF;
            os[it]=js;
            ob[it*4+0]=a1; ob[it*4+1]=a2; ob[it*4+2]=a3; ob[it*4+3]=a4;
        }
        __syncthreads();
    }
}

__global__ void nms_det(const float* __restrict__ iminfo){
    __shared__ float y1[1000],x1[1000],y2[1000],x2[1000],s[1000];
    int blk=blockIdx.x; int b=blk/90; int c=blk%90+1;
    int tid=threadIdx.x;
    float hI=iminfo[b*5+0], wI=iminfo[b*5+1];
    for(int i=tid;i<1000;i+=256){
        const float* ro=&g.rois[b][i*4];
        float ya1=ro[0],xa1=ro[1],ya2=ro[2],xa2=ro[3];
        float ha=ya2-ya1, wa=xa2-xa1;
        float yc=ya1+0.5f*ha, xc=xa1+0.5f*wa;
        const float* d=&g.boxl[((size_t)(b*1000+i)*91+c)*4];
        float dy=d[0]/10.f, dx=d[1]/10.f;
        float dh=fminf(d[2]/5.f,CLIPV), dw=fminf(d[3]/5.f,CLIPV);
        float pcy=dy*ha+yc, pcx=dx*wa+xc;
        float ph=expf(dh)*ha, pw=expf(dw)*wa;
        y1[i]=fminf(fmaxf(pcy-0.5f*ph,0.f),hI);
        x1[i]=fminf(fmaxf(pcx-0.5f*pw,0.f),wI);
        y2[i]=fminf(fmaxf(pcy+0.5f*ph,0.f),hI);
        x2[i]=fminf(fmaxf(pcx+0.5f*pw,0.f),wI);
        float p=g.clsl[(size_t)(b*1000+i)*91+c];
        s[i]=(p>=0.05f)?p:NEGF;
    }
    __syncthreads();
    nms_run(y1,x1,y2,x2,s,1000,100,0.5f,&g.dnb[b][(c-1)*400],&g.dns[b][(c-1)*100]);
}

__global__ void zero_out(float* out,int out_size){
    int i=blockIdx.x*256+threadIdx.x;
    if(i<out_size) out[i]=0.f;
}

// ---- exact rank-select top-100 of 9000 det candidates, write output ------
__global__ void det_rank(float* out,int out_size){
    extern __shared__ unsigned long long dk[];
    int b=blockIdx.x;
    int chunk=blockIdx.y;
    int tid=threadIdx.x;   // 1024
    for(int i=tid;i<9000;i+=1024)
        dk[i]=(((unsigned long long)skey(g.dns[b][i]))<<32)|(unsigned)(~(unsigned)i);
    __syncthreads();
    int i0=chunk*1125, i1=i0+1125;
    for(int i=i0+tid;i<i1;i+=1024){
        unsigned long long me=dk[i];
        int rank=0;
        for(int j=0;j<9000;j++) rank+=(dk[j]>me);
        if(rank<100){
            float sc=g.dns[b][i];
            bool valid=sc>0.f;
            if(valid){
                int ob=2+b*400+rank*4;
                for(int d=0;d<4;d++){
                    int o=ob+d;
                    if(o<out_size) out[o]=g.dnb[b][i*4+d];
                }
                int oc=2+800+b*100+rank;
                if(oc<out_size) out[oc]=(float)(i/100+1);
                int os=2+1000+b*100+rank;
                if(os<out_size) out[os]=sc;
                if(b<out_size) atomicAdd(&out[b],1.f);
            }
        }
    }
}

extern "C" void kernel_launch(void* const* d_in,const int* in_sizes,int n_in,
                              void* d_out,int out_size){
    const float* feats[5];
    for(int i=0;i<5;i++) feats[i]=(const float*)d_in[i];
    const float* iminfo=(const float*)d_in[5];
    const float* cw =(const float*)d_in[6];
    const float* cbv=(const float*)d_in[7];
    const float* sw =(const float*)d_in[8];
    const float* sb =(const float*)d_in[9];
    const float* bw =(const float*)d_in[10];
    const float* bbv=(const float*)d_in[11];
    const float* fc1w=(const float*)d_in[12];
    const float* fc1b=(const float*)d_in[13];
    const float* fc2w=(const float*)d_in[14];
    const float* fc2b=(const float*)d_in[15];
    const float* clsw=(const float*)d_in[16];
    const float* clsb=(const float*)d_in[17];
    const float* boxw=(const float*)d_in[18];
    const float* boxb=(const float*)d_in[19];

    Scratch* gp=nullptr;
    cudaGetSymbolAddress((void**)&gp,g);

    static int attr_done=0;
    if(!attr_done){
        cudaFuncSetAttribute(nms_lvl_v2,cudaFuncAttributeMaxDynamicSharedMemorySize,152*1024);
        cudaFuncSetAttribute(det_rank,cudaFuncAttributeMaxDynamicSharedMemorySize,80*1024);
        attr_done=1;
    }
    const int NMS_SMEM=5120*4+32000*4+32*4+16;   // ~148.7KB
    const int DET_SMEM=9000*8;                    // 72KB

    init_kernel<<<1,32>>>();                                                         // 0
    cvt_feats<<<dim3(17472,5),256>>>(feats[0],feats[1],feats[2],feats[3],feats[4]);  // 1
    twcvt<<<dim3(72,8),dim3(32,8)>>>(cw,gp->cwT,2304,256,256);                       // 2
    gemm_bf16<2,false,true><<<dim3(2,1455),256>>>(gp->featsbf,gp->cwT,cbv,gp->h,186186,256,2304); // 3
    rpn_head_all<<<dim3(546,5),256>>>(sw,sb,bw,bbv);                                 // 4
    select_topk_all<<<10,1024>>>();                                                  // 5 (ncu slot)
    bitonic_lvl<<<10,1024>>>();
    rpn_decode_all<<<10,1024>>>(iminfo);
    nms_lvl_v2<<<10,1024,NMS_SMEM>>>();
    cat_rank<<<2,1024>>>();

    roialign<<<2000,256>>>(feats[0],feats[1],feats[2],feats[3],feats[4]);

    twcvt<<<dim3(392,32),dim3(32,8)>>>(fc1w,gp->fc1wT,12544,1024,1024);
    twcvt<<<dim3(32,32),dim3(32,8)>>>(fc2w,gp->fc2wT,1024,1024,1024);
    twcvt<<<dim3(32,4),dim3(32,8)>>>(clsw,gp->clswT,1024,91,128);
    twcvt<<<dim3(32,12),dim3(32,8)>>>(boxw,gp->boxwT,1024,364,384);
    padbias<<<1,512>>>(clsb,boxb);

    gemm_bf16<0,true ,true ><<<dim3(8,16),256>>>(gp->roifeatb,gp->fc1wT,fc1b,gp->h1b,2000,1024,12544);
    gemm_bf16<0,true ,true ><<<dim3(8,16),256>>>(gp->h1b,gp->fc2wT,fc2b,gp->h2b,2000,1024,1024);
    gemm_bf16<0,false,false><<<dim3(1,16),256>>>(gp->h2b,gp->clswT,gp->clsbPad,gp->clsl,2000,91,1024);
    gemm_bf16<0,false,false><<<dim3(3,16),256>>>(gp->h2b,gp->boxwT,gp->boxbPad,gp->boxl,2000,364,1024);

    softmax91<<<8,256>>>();
    nms_det<<<180,256>>>(iminfo);
    zero_out<<<(out_size+255)/256,256>>>((float*)d_out,out_size);
    det_rank<<<dim3(2,8),1024,DET_SMEM>>>((float*)d_out,out_size);
}